// round 1
// baseline (speedup 1.0000x reference)
#include <cuda_runtime.h>
#include <cuda_bf16.h>

// Problem constants: B=4, T=2048, C=1024, H=16, D=64
#define BB   4
#define TT   2048
#define CC   1024
#define C3   3072
#define HH   16
#define DD   64
#define BT   (BB * TT)          // 8192 rows

// Scratch (allocation-free rule: __device__ globals)
__device__ float g_qkv[(size_t)BT * C3];   // [B*T, 3C]
__device__ float g_y  [(size_t)BT * CC];   // [B*T, C] attention output (pre-proj)

// ---------------------------------------------------------------------------
// Classic 128x128x8 register-blocked SGEMM with bias epilogue.
// C[M,N] = A[M,K] @ B[K,N] + bias[N]. All row-major. M%128==N%128==K%8==0.
// ---------------------------------------------------------------------------
__global__ __launch_bounds__(256)
void sgemm_bias_kernel(const float* __restrict__ A, const float* __restrict__ B,
                       const float* __restrict__ bias, float* __restrict__ Cout,
                       int M, int N, int K)
{
    constexpr int BM = 128, BN = 128, BK = 8;
    __shared__ float As[BK][BM];   // A tile transposed: As[k][m]
    __shared__ float Bs[BK][BN];

    const int tid = threadIdx.x;           // 256 threads
    const int tx  = tid & 15;              // 16 col groups (8 cols each)
    const int ty  = tid >> 4;              // 16 row groups (8 rows each)
    const int bx  = blockIdx.x;            // N tiles
    const int by  = blockIdx.y;            // M tiles

    const float* Ab = A + (size_t)by * BM * K;
    const float* Bb = B + (size_t)bx * BN;

    const int aRow = tid >> 1;             // 0..127
    const int aCol = (tid & 1) * 4;        // 0 or 4
    const int bRow = tid >> 5;             // 0..7
    const int bCol = (tid & 31) * 4;       // 0..124

    float acc[8][8];
    #pragma unroll
    for (int i = 0; i < 8; i++)
        #pragma unroll
        for (int j = 0; j < 8; j++) acc[i][j] = 0.f;

    for (int k0 = 0; k0 < K; k0 += BK) {
        float4 a4 = *(const float4*)(Ab + (size_t)aRow * K + k0 + aCol);
        As[aCol + 0][aRow] = a4.x;
        As[aCol + 1][aRow] = a4.y;
        As[aCol + 2][aRow] = a4.z;
        As[aCol + 3][aRow] = a4.w;
        float4 b4 = *(const float4*)(Bb + (size_t)(k0 + bRow) * N + bCol);
        *(float4*)&Bs[bRow][bCol] = b4;
        __syncthreads();

        #pragma unroll
        for (int kk = 0; kk < BK; kk++) {
            float ra[8], rb[8];
            *(float4*)&ra[0] = *(const float4*)&As[kk][ty * 8];
            *(float4*)&ra[4] = *(const float4*)&As[kk][ty * 8 + 4];
            *(float4*)&rb[0] = *(const float4*)&Bs[kk][tx * 8];
            *(float4*)&rb[4] = *(const float4*)&Bs[kk][tx * 8 + 4];
            #pragma unroll
            for (int i = 0; i < 8; i++)
                #pragma unroll
                for (int j = 0; j < 8; j++)
                    acc[i][j] = fmaf(ra[i], rb[j], acc[i][j]);
        }
        __syncthreads();
    }

    const int row0 = by * BM + ty * 8;
    const int col0 = bx * BN + tx * 8;
    float bsv[8];
    *(float4*)&bsv[0] = *(const float4*)(bias + col0);
    *(float4*)&bsv[4] = *(const float4*)(bias + col0 + 4);
    #pragma unroll
    for (int i = 0; i < 8; i++) {
        float4 o0 = make_float4(acc[i][0] + bsv[0], acc[i][1] + bsv[1],
                                acc[i][2] + bsv[2], acc[i][3] + bsv[3]);
        float4 o1 = make_float4(acc[i][4] + bsv[4], acc[i][5] + bsv[5],
                                acc[i][6] + bsv[6], acc[i][7] + bsv[7]);
        *(float4*)(Cout + (size_t)(row0 + i) * N + col0)     = o0;
        *(float4*)(Cout + (size_t)(row0 + i) * N + col0 + 4) = o1;
    }
}

// ---------------------------------------------------------------------------
// Flash attention (fp32, causal). One CTA per (b, h, 64-row q tile).
// 256 threads; thread (rg, cg) owns a 4x4 sub-tile of the 64x64 S / O tiles.
// Q/K stored transposed in smem so the S inner loop is 2x LDS.128 + 16 FMA.
// ---------------------------------------------------------------------------
#define BQ   64
#define BKV  64
#define PAD  68      // 68 % 32 == 4 -> conflict-free strided row access

__global__ __launch_bounds__(256)
void attn_kernel(const float* __restrict__ qkv, float* __restrict__ y)
{
    extern __shared__ float sm[];
    float* QsT = sm;                    // [DD][PAD]  QsT[d*PAD + r]
    float* KsT = sm + DD * PAD;         // [DD][PAD]  KsT[d*PAD + c]
    float* Vs  = sm + 2 * DD * PAD;     // [BKV][PAD] Vs[c*PAD + d]
    float* PsT = sm + 3 * DD * PAD;     // [BKV][PAD] PsT[c*PAD + r]

    const int qt = blockIdx.x;          // q tile (0..31)
    const int h  = blockIdx.y;          // head
    const int b  = blockIdx.z;          // batch
    const int tid = threadIdx.x;
    const int rg = tid >> 4;            // 0..15
    const int cg = tid & 15;            // 0..15
    const int r0 = rg * 4;
    const int c0 = cg * 4;              // also the d0 for the O accumulator

    const size_t baseQ = ((size_t)(b * TT + qt * BQ)) * C3 + h * DD;

    // Load Q tile transposed, pre-scaled by 1/sqrt(D)=0.125
    for (int i = tid; i < BQ * DD; i += 256) {
        int row = i >> 6, col = i & 63;
        QsT[col * PAD + row] = qkv[baseQ + (size_t)row * C3 + col] * 0.125f;
    }

    float acc[4][4];
    float m[4], l[4];
    #pragma unroll
    for (int i = 0; i < 4; i++) {
        m[i] = -1e30f; l[i] = 0.f;
        #pragma unroll
        for (int j = 0; j < 4; j++) acc[i][j] = 0.f;
    }

    for (int kt = 0; kt <= qt; ++kt) {
        __syncthreads();   // previous iter's PV done before overwriting K/V
        const size_t baseK = ((size_t)(b * TT + kt * BKV)) * C3 + CC + h * DD;
        const size_t baseV = baseK + CC;
        for (int i = tid; i < BKV * DD; i += 256) {
            int row = i >> 6, col = i & 63;
            float kvK = qkv[baseK + (size_t)row * C3 + col];
            float kvV = qkv[baseV + (size_t)row * C3 + col];
            KsT[col * PAD + row] = kvK;
            Vs[row * PAD + col]  = kvV;
        }
        __syncthreads();

        // S = Q @ K^T  (4x4 per thread)
        float s[4][4];
        #pragma unroll
        for (int i = 0; i < 4; i++)
            #pragma unroll
            for (int j = 0; j < 4; j++) s[i][j] = 0.f;

        #pragma unroll 8
        for (int d = 0; d < DD; ++d) {
            float4 qv = *(const float4*)&QsT[d * PAD + r0];
            float4 kv = *(const float4*)&KsT[d * PAD + c0];
            float qa[4] = {qv.x, qv.y, qv.z, qv.w};
            float ka[4] = {kv.x, kv.y, kv.z, kv.w};
            #pragma unroll
            for (int i = 0; i < 4; i++)
                #pragma unroll
                for (int j = 0; j < 4; j++)
                    s[i][j] = fmaf(qa[i], ka[j], s[i][j]);
        }

        // Causal mask on the diagonal tile
        if (kt == qt) {
            #pragma unroll
            for (int i = 0; i < 4; i++)
                #pragma unroll
                for (int j = 0; j < 4; j++)
                    if (c0 + j > r0 + i) s[i][j] = -1e30f;
        }

        // Online softmax per row (stats replicated across the 16 col-group lanes)
        #pragma unroll
        for (int i = 0; i < 4; i++) {
            float mt = fmaxf(fmaxf(s[i][0], s[i][1]), fmaxf(s[i][2], s[i][3]));
            mt = fmaxf(mt, __shfl_xor_sync(0xffffffffu, mt, 1));
            mt = fmaxf(mt, __shfl_xor_sync(0xffffffffu, mt, 2));
            mt = fmaxf(mt, __shfl_xor_sync(0xffffffffu, mt, 4));
            mt = fmaxf(mt, __shfl_xor_sync(0xffffffffu, mt, 8));
            mt = fmaxf(mt, m[i]);

            float rs = 0.f;
            #pragma unroll
            for (int j = 0; j < 4; j++) {
                float p = __expf(s[i][j] - mt);
                s[i][j] = p;
                rs += p;
            }
            rs += __shfl_xor_sync(0xffffffffu, rs, 1);
            rs += __shfl_xor_sync(0xffffffffu, rs, 2);
            rs += __shfl_xor_sync(0xffffffffu, rs, 4);
            rs += __shfl_xor_sync(0xffffffffu, rs, 8);

            float alpha = __expf(m[i] - mt);
            m[i] = mt;
            l[i] = l[i] * alpha + rs;
            #pragma unroll
            for (int j = 0; j < 4; j++) acc[i][j] *= alpha;
        }

        // Stage P transposed for the PV matmul
        #pragma unroll
        for (int i = 0; i < 4; i++)
            #pragma unroll
            for (int j = 0; j < 4; j++)
                PsT[(c0 + j) * PAD + (r0 + i)] = s[i][j];
        __syncthreads();

        // O += P @ V   (thread owns rows r0..r0+3, d cols c0..c0+3)
        #pragma unroll 8
        for (int c = 0; c < BKV; ++c) {
            float4 pv = *(const float4*)&PsT[c * PAD + r0];
            float4 vv = *(const float4*)&Vs[c * PAD + c0];
            float pa[4] = {pv.x, pv.y, pv.z, pv.w};
            float va[4] = {vv.x, vv.y, vv.z, vv.w};
            #pragma unroll
            for (int i = 0; i < 4; i++)
                #pragma unroll
                for (int j = 0; j < 4; j++)
                    acc[i][j] = fmaf(pa[i], va[j], acc[i][j]);
        }
    }

    // Normalize and write y[b, t, h*64 + d]
    #pragma unroll
    for (int i = 0; i < 4; i++) {
        float inv = 1.f / l[i];
        float4 o = make_float4(acc[i][0] * inv, acc[i][1] * inv,
                               acc[i][2] * inv, acc[i][3] * inv);
        size_t row = (size_t)(b * TT + qt * BQ + r0 + i);
        *(float4*)(y + row * CC + h * DD + c0) = o;
    }
}

// ---------------------------------------------------------------------------
extern "C" void kernel_launch(void* const* d_in, const int* in_sizes, int n_in,
                              void* d_out, int out_size)
{
    const float* x      = (const float*)d_in[0];
    const float* W_attn = (const float*)d_in[1];
    const float* b_attn = (const float*)d_in[2];
    const float* W_proj = (const float*)d_in[3];
    const float* b_proj = (const float*)d_in[4];
    float* out = (float*)d_out;

    float *qkv, *y;
    cudaGetSymbolAddress((void**)&qkv, g_qkv);
    cudaGetSymbolAddress((void**)&y,   g_y);

    // 1) QKV = x @ W_attn + b_attn   [8192,1024]x[1024,3072]
    {
        dim3 grid(C3 / 128, BT / 128);
        sgemm_bias_kernel<<<grid, 256>>>(x, W_attn, b_attn, qkv, BT, C3, CC);
    }

    // 2) Flash attention (causal)
    {
        const int smem = 4 * DD * PAD * (int)sizeof(float);   // 69632 B
        cudaFuncSetAttribute(attn_kernel,
                             cudaFuncAttributeMaxDynamicSharedMemorySize, smem);
        dim3 grid(TT / BQ, HH, BB);
        attn_kernel<<<grid, 256, smem>>>(qkv, y);
    }

    // 3) out = y @ W_proj + b_proj   [8192,1024]x[1024,1024]
    {
        dim3 grid(CC / 128, BT / 128);
        sgemm_bias_kernel<<<grid, 256>>>(y, W_proj, b_proj, out, BT, CC, CC);
    }
}

// round 5
// speedup vs baseline: 1.6555x; 1.6555x over previous
#include <cuda_runtime.h>
#include <cuda_bf16.h>
#include <cstdint>

// Problem constants: B=4, T=2048, C=1024, H=16, D=64
#define BB   4
#define TT   2048
#define CC   1024
#define C3   3072
#define HH   16
#define DD   64
#define BT   (BB * TT)          // 8192 rows
#define KK   1024               // GEMM K (both GEMMs)

// ---------------------------------------------------------------------------
// Scratch (__device__ globals; no allocation allowed)
// ---------------------------------------------------------------------------
__device__ __align__(1024) float          g_qkv[(size_t)BT * C3];     // fp32 [B*T,3C]
__device__ __align__(1024) float          g_y  [(size_t)BT * CC];     // fp32 attn out
__device__ __align__(1024) __nv_bfloat16  g_xhi[(size_t)BT * CC];
__device__ __align__(1024) __nv_bfloat16  g_xlo[(size_t)BT * CC];
__device__ __align__(1024) __nv_bfloat16  g_yhi[(size_t)BT * CC];
__device__ __align__(1024) __nv_bfloat16  g_ylo[(size_t)BT * CC];
__device__ __align__(1024) __nv_bfloat16  g_Wahi[(size_t)C3 * CC];    // W_attn^T [N,K]
__device__ __align__(1024) __nv_bfloat16  g_Walo[(size_t)C3 * CC];
__device__ __align__(1024) __nv_bfloat16  g_Wphi[(size_t)CC * CC];    // W_proj^T [N,K]
__device__ __align__(1024) __nv_bfloat16  g_Wplo[(size_t)CC * CC];

// ---------------------------------------------------------------------------
// PTX helpers — baseline PTX only (compute_103 has no tcgen05/TMA-tensor!)
// ---------------------------------------------------------------------------
__device__ __forceinline__ uint32_t smem_u32(const void* p) {
    uint32_t a;
    asm("{ .reg .u64 t; cvta.to.shared.u64 t, %1; cvt.u32.u64 %0, t; }" : "=r"(a) : "l"(p));
    return a;
}
__device__ __forceinline__ void cp16(uint32_t saddr, const void* g) {
    asm volatile("cp.async.cg.shared.global [%0], [%1], 16;\n" :: "r"(saddr), "l"(g));
}
__device__ __forceinline__ void cp_commit() {
    asm volatile("cp.async.commit_group;\n" ::: "memory");
}
template<int N> __device__ __forceinline__ void cp_wait() {
    asm volatile("cp.async.wait_group %0;\n" :: "n"(N) : "memory");
}
__device__ __forceinline__ void ldsm_x4(uint32_t* r, uint32_t addr) {
    asm volatile("ldmatrix.sync.aligned.m8n8.x4.shared.b16 {%0,%1,%2,%3}, [%4];"
        : "=r"(r[0]), "=r"(r[1]), "=r"(r[2]), "=r"(r[3]) : "r"(addr));
}
__device__ __forceinline__ void mma16816(float* d, const uint32_t* a, const uint32_t* b) {
    asm volatile("mma.sync.aligned.m16n8k16.row.col.f32.bf16.bf16.f32 "
        "{%0,%1,%2,%3}, {%4,%5,%6,%7}, {%8,%9}, {%0,%1,%2,%3};"
        : "+f"(d[0]), "+f"(d[1]), "+f"(d[2]), "+f"(d[3])
        : "r"(a[0]), "r"(a[1]), "r"(a[2]), "r"(a[3]), "r"(b[0]), "r"(b[1]));
}
// swizzled address inside a [rows][128B] tile (SW128: 16B chunks permuted)
__device__ __forceinline__ uint32_t sw_addr(uint32_t base, int row, int kb) {
    uint32_t off = ((uint32_t)row << 7) + (uint32_t)kb;
    return base + (off ^ ((off >> 3) & 0x70));
}

// ---------------------------------------------------------------------------
// Split fp32 -> bf16 hi/lo
// ---------------------------------------------------------------------------
__global__ void split_kernel(const float* __restrict__ src,
                             __nv_bfloat16* __restrict__ hi,
                             __nv_bfloat16* __restrict__ lo, int n4) {
    int i = blockIdx.x * blockDim.x + threadIdx.x;
    if (i >= n4) return;
    float4 v = ((const float4*)src)[i];
    __nv_bfloat16 h0 = __float2bfloat16(v.x), h1 = __float2bfloat16(v.y);
    __nv_bfloat16 h2 = __float2bfloat16(v.z), h3 = __float2bfloat16(v.w);
    __nv_bfloat16 l0 = __float2bfloat16(v.x - __bfloat162float(h0));
    __nv_bfloat16 l1 = __float2bfloat16(v.y - __bfloat162float(h1));
    __nv_bfloat16 l2 = __float2bfloat16(v.z - __bfloat162float(h2));
    __nv_bfloat16 l3 = __float2bfloat16(v.w - __bfloat162float(h3));
    ((__nv_bfloat162*)hi)[2*i]   = __nv_bfloat162(h0, h1);
    ((__nv_bfloat162*)hi)[2*i+1] = __nv_bfloat162(h2, h3);
    ((__nv_bfloat162*)lo)[2*i]   = __nv_bfloat162(l0, l1);
    ((__nv_bfloat162*)lo)[2*i+1] = __nv_bfloat162(l2, l3);
}

// Transpose W[K,N] -> Wt[N,K] with hi/lo split
__global__ void transpose_split_kernel(const float* __restrict__ W,
                                       __nv_bfloat16* __restrict__ Th,
                                       __nv_bfloat16* __restrict__ Tl,
                                       int K, int N) {
    __shared__ float t[32][33];
    int tx = threadIdx.x, ty = threadIdx.y;
    int n0 = blockIdx.x * 32, k0 = blockIdx.y * 32;
    #pragma unroll
    for (int j = 0; j < 4; j++)
        t[ty + 8*j][tx] = W[(size_t)(k0 + ty + 8*j) * N + n0 + tx];
    __syncthreads();
    #pragma unroll
    for (int j = 0; j < 4; j++) {
        float v = t[tx][ty + 8*j];
        __nv_bfloat16 h = __float2bfloat16(v);
        __nv_bfloat16 l = __float2bfloat16(v - __bfloat162float(h));
        size_t idx = (size_t)(n0 + ty + 8*j) * K + k0 + tx;
        Th[idx] = h;
        Tl[idx] = l;
    }
}

// ---------------------------------------------------------------------------
// mma.sync split-bf16 GEMM: C[M,N] = Ahi·Bhi^T + Ahi·Blo^T + Alo·Bhi^T + bias
// A: [M,K] bf16 (hi,lo), B: [N,K] bf16 (hi,lo), C fp32 row-major.
// CTA 128x128, BK=64 (128B rows, SW128), 8 warps (2m x 4n), warp tile 64x32.
// 2-stage cp.async pipeline.
// ---------------------------------------------------------------------------
#define GT_M   128
#define GT_N   128
#define GT_K   64
#define NKCH   (KK / GT_K)                // 16
#define TILE_B (128 * 128)                // 16384 bytes per [128][64bf16] tile
#define OFF_AH 0
#define OFF_AL (TILE_B)
#define OFF_BH (2 * TILE_B)
#define OFF_BL (3 * TILE_B)
#define STAGE  (4 * TILE_B)               // 65536
#define GEMM_SMEM (2 * STAGE)             // 131072

// load a [128 rows][64 bf16] tile chunk; gmem pitch 2048 B (K=1024 bf16)
__device__ __forceinline__ void load_buf(uint32_t sdst, const char* g,
                                         int kbytes, int tid) {
    #pragma unroll
    for (int it = 0; it < 4; it++) {
        int c = tid + it * 256;           // 1024 chunks of 16B
        int r = c >> 3;
        int cb = (c & 7) << 4;
        uint32_t off = ((uint32_t)r << 7) | (uint32_t)cb;
        uint32_t sw = off ^ ((off >> 3) & 0x70);
        cp16(sdst + sw, g + (size_t)r * 2048 + kbytes + cb);
    }
}

__global__ __launch_bounds__(256)
void hmma_gemm_kernel(const __nv_bfloat16* __restrict__ Ahi,
                      const __nv_bfloat16* __restrict__ Alo,
                      const __nv_bfloat16* __restrict__ Bhi,
                      const __nv_bfloat16* __restrict__ Blo,
                      const float* __restrict__ bias,
                      float* __restrict__ C, int N) {
    extern __shared__ char smem[];
    const uint32_t sbase = smem_u32(smem);
    const int tid  = threadIdx.x;
    const int lane = tid & 31;
    const int wid  = tid >> 5;
    const int wm   = wid >> 2;            // 0..1 -> 64 rows
    const int wn   = wid & 3;             // 0..3 -> 32 cols
    const int bx   = blockIdx.x;          // N tile
    const int by   = blockIdx.y;          // M tile

    const char* gAh = (const char*)Ahi + (size_t)by * GT_M * 2048;
    const char* gAl = (const char*)Alo + (size_t)by * GT_M * 2048;
    const char* gBh = (const char*)Bhi + (size_t)bx * GT_N * 2048;
    const char* gBl = (const char*)Blo + (size_t)bx * GT_N * 2048;

    // Prologue: chunks 0,1 -> stages 0,1
    #pragma unroll
    for (int st = 0; st < 2; st++) {
        uint32_t sb = sbase + st * STAGE;
        int kb = st * 128;
        load_buf(sb + OFF_AH, gAh, kb, tid);
        load_buf(sb + OFF_AL, gAl, kb, tid);
        load_buf(sb + OFF_BH, gBh, kb, tid);
        load_buf(sb + OFF_BL, gBl, kb, tid);
        cp_commit();
    }

    float acc[4][4][4];
    #pragma unroll
    for (int mt = 0; mt < 4; mt++)
        #pragma unroll
        for (int nt = 0; nt < 4; nt++)
            #pragma unroll
            for (int r = 0; r < 4; r++) acc[mt][nt][r] = 0.f;

    // per-lane fragment coordinates
    const int arow = wm * 64 + (lane & 15);           // + mt*16
    const int akb  = (lane >> 4) << 4;                // + ks*32
    const int brow = wn * 32 + (lane & 7) + ((lane >> 4) << 3);  // + {0,16}
    const int bkb  = ((lane >> 3) & 1) << 4;          // + ks*32

    for (int i = 0; i < NKCH; i++) {
        const int s = i & 1;
        const uint32_t sb = sbase + s * STAGE;

        if (i < NKCH - 1) cp_wait<1>(); else cp_wait<0>();
        __syncthreads();

        #pragma unroll
        for (int ks = 0; ks < 4; ks++) {
            const int ksb = ks * 32;
            uint32_t ah[4][4], al[4][4], bh[2][4], bl[2][4];
            #pragma unroll
            for (int mt = 0; mt < 4; mt++) {
                ldsm_x4(ah[mt], sw_addr(sb + OFF_AH, arow + mt * 16, ksb + akb));
                ldsm_x4(al[mt], sw_addr(sb + OFF_AL, arow + mt * 16, ksb + akb));
            }
            #pragma unroll
            for (int p = 0; p < 2; p++) {
                ldsm_x4(bh[p], sw_addr(sb + OFF_BH, brow + p * 16, ksb + bkb));
                ldsm_x4(bl[p], sw_addr(sb + OFF_BL, brow + p * 16, ksb + bkb));
            }
            // term-outer so consecutive mma hit different accumulators
            #pragma unroll
            for (int mt = 0; mt < 4; mt++)
                #pragma unroll
                for (int nt = 0; nt < 4; nt++)
                    mma16816(acc[mt][nt], ah[mt], &bh[nt >> 1][(nt & 1) * 2]);
            #pragma unroll
            for (int mt = 0; mt < 4; mt++)
                #pragma unroll
                for (int nt = 0; nt < 4; nt++)
                    mma16816(acc[mt][nt], ah[mt], &bl[nt >> 1][(nt & 1) * 2]);
            #pragma unroll
            for (int mt = 0; mt < 4; mt++)
                #pragma unroll
                for (int nt = 0; nt < 4; nt++)
                    mma16816(acc[mt][nt], al[mt], &bh[nt >> 1][(nt & 1) * 2]);
        }
        __syncthreads();   // everyone done reading stage s before refill

        if (i + 2 < NKCH) {
            int kb = (i + 2) * 128;
            load_buf(sb + OFF_AH, gAh, kb, tid);
            load_buf(sb + OFF_AL, gAl, kb, tid);
            load_buf(sb + OFF_BH, gBh, kb, tid);
            load_buf(sb + OFF_BL, gBl, kb, tid);
            cp_commit();
        }
    }

    // Epilogue: bias add + fp32 store
    const int g = lane >> 2, t = lane & 3;
    const int row_base = by * GT_M + wm * 64 + g;
    const int col_base = bx * GT_N + wn * 32 + t * 2;
    #pragma unroll
    for (int mt = 0; mt < 4; mt++) {
        const int r0 = row_base + mt * 16;
        #pragma unroll
        for (int nt = 0; nt < 4; nt++) {
            const int c = col_base + nt * 8;
            float b0 = bias[c], b1 = bias[c + 1];
            float2 v0 = make_float2(acc[mt][nt][0] + b0, acc[mt][nt][1] + b1);
            float2 v1 = make_float2(acc[mt][nt][2] + b0, acc[mt][nt][3] + b1);
            *(float2*)(C + (size_t)r0 * N + c)       = v0;
            *(float2*)(C + (size_t)(r0 + 8) * N + c) = v1;
        }
    }
}

// ---------------------------------------------------------------------------
// Flash attention (fp32, causal) — unchanged
// ---------------------------------------------------------------------------
#define BQ   64
#define BKV  64
#define PAD  68

__global__ __launch_bounds__(256)
void attn_kernel(const float* __restrict__ qkv, float* __restrict__ y)
{
    extern __shared__ float sm[];
    float* QsT = sm;
    float* KsT = sm + DD * PAD;
    float* Vs  = sm + 2 * DD * PAD;
    float* PsT = sm + 3 * DD * PAD;

    const int qt = blockIdx.x;
    const int h  = blockIdx.y;
    const int b  = blockIdx.z;
    const int tid = threadIdx.x;
    const int rg = tid >> 4;
    const int cg = tid & 15;
    const int r0 = rg * 4;
    const int c0 = cg * 4;

    const size_t baseQ = ((size_t)(b * TT + qt * BQ)) * C3 + h * DD;

    for (int i = tid; i < BQ * DD; i += 256) {
        int row = i >> 6, col = i & 63;
        QsT[col * PAD + row] = qkv[baseQ + (size_t)row * C3 + col] * 0.125f;
    }

    float acc[4][4];
    float m[4], l[4];
    #pragma unroll
    for (int i = 0; i < 4; i++) {
        m[i] = -1e30f; l[i] = 0.f;
        #pragma unroll
        for (int j = 0; j < 4; j++) acc[i][j] = 0.f;
    }

    for (int kt = 0; kt <= qt; ++kt) {
        __syncthreads();
        const size_t baseK = ((size_t)(b * TT + kt * BKV)) * C3 + CC + h * DD;
        const size_t baseV = baseK + CC;
        for (int i = tid; i < BKV * DD; i += 256) {
            int row = i >> 6, col = i & 63;
            float kvK = qkv[baseK + (size_t)row * C3 + col];
            float kvV = qkv[baseV + (size_t)row * C3 + col];
            KsT[col * PAD + row] = kvK;
            Vs[row * PAD + col]  = kvV;
        }
        __syncthreads();

        float s[4][4];
        #pragma unroll
        for (int i = 0; i < 4; i++)
            #pragma unroll
            for (int j = 0; j < 4; j++) s[i][j] = 0.f;

        #pragma unroll 8
        for (int d = 0; d < DD; ++d) {
            float4 qv = *(const float4*)&QsT[d * PAD + r0];
            float4 kv = *(const float4*)&KsT[d * PAD + c0];
            float qa[4] = {qv.x, qv.y, qv.z, qv.w};
            float ka[4] = {kv.x, kv.y, kv.z, kv.w};
            #pragma unroll
            for (int i = 0; i < 4; i++)
                #pragma unroll
                for (int j = 0; j < 4; j++)
                    s[i][j] = fmaf(qa[i], ka[j], s[i][j]);
        }

        if (kt == qt) {
            #pragma unroll
            for (int i = 0; i < 4; i++)
                #pragma unroll
                for (int j = 0; j < 4; j++)
                    if (c0 + j > r0 + i) s[i][j] = -1e30f;
        }

        #pragma unroll
        for (int i = 0; i < 4; i++) {
            float mt = fmaxf(fmaxf(s[i][0], s[i][1]), fmaxf(s[i][2], s[i][3]));
            mt = fmaxf(mt, __shfl_xor_sync(0xffffffffu, mt, 1));
            mt = fmaxf(mt, __shfl_xor_sync(0xffffffffu, mt, 2));
            mt = fmaxf(mt, __shfl_xor_sync(0xffffffffu, mt, 4));
            mt = fmaxf(mt, __shfl_xor_sync(0xffffffffu, mt, 8));
            mt = fmaxf(mt, m[i]);

            float rs = 0.f;
            #pragma unroll
            for (int j = 0; j < 4; j++) {
                float p = __expf(s[i][j] - mt);
                s[i][j] = p;
                rs += p;
            }
            rs += __shfl_xor_sync(0xffffffffu, rs, 1);
            rs += __shfl_xor_sync(0xffffffffu, rs, 2);
            rs += __shfl_xor_sync(0xffffffffu, rs, 4);
            rs += __shfl_xor_sync(0xffffffffu, rs, 8);

            float alpha = __expf(m[i] - mt);
            m[i] = mt;
            l[i] = l[i] * alpha + rs;
            #pragma unroll
            for (int j = 0; j < 4; j++) acc[i][j] *= alpha;
        }

        #pragma unroll
        for (int i = 0; i < 4; i++)
            #pragma unroll
            for (int j = 0; j < 4; j++)
                PsT[(c0 + j) * PAD + (r0 + i)] = s[i][j];
        __syncthreads();

        #pragma unroll 8
        for (int c = 0; c < BKV; ++c) {
            float4 pv = *(const float4*)&PsT[c * PAD + r0];
            float4 vv = *(const float4*)&Vs[c * PAD + c0];
            float pa[4] = {pv.x, pv.y, pv.z, pv.w};
            float va[4] = {vv.x, vv.y, vv.z, vv.w};
            #pragma unroll
            for (int i = 0; i < 4; i++)
                #pragma unroll
                for (int j = 0; j < 4; j++)
                    acc[i][j] = fmaf(pa[i], va[j], acc[i][j]);
        }
    }

    #pragma unroll
    for (int i = 0; i < 4; i++) {
        float inv = 1.f / l[i];
        float4 o = make_float4(acc[i][0] * inv, acc[i][1] * inv,
                               acc[i][2] * inv, acc[i][3] * inv);
        size_t row = (size_t)(b * TT + qt * BQ + r0 + i);
        *(float4*)(y + row * CC + h * DD + c0) = o;
    }
}

// ---------------------------------------------------------------------------
extern "C" void kernel_launch(void* const* d_in, const int* in_sizes, int n_in,
                              void* d_out, int out_size)
{
    const float* x      = (const float*)d_in[0];
    const float* W_attn = (const float*)d_in[1];
    const float* b_attn = (const float*)d_in[2];
    const float* W_proj = (const float*)d_in[3];
    const float* b_proj = (const float*)d_in[4];
    float* out = (float*)d_out;

    float *qkv, *y;
    __nv_bfloat16 *xhi, *xlo, *yhi, *ylo, *wahi, *walo, *wphi, *wplo;
    cudaGetSymbolAddress((void**)&qkv,  g_qkv);
    cudaGetSymbolAddress((void**)&y,    g_y);
    cudaGetSymbolAddress((void**)&xhi,  g_xhi);
    cudaGetSymbolAddress((void**)&xlo,  g_xlo);
    cudaGetSymbolAddress((void**)&yhi,  g_yhi);
    cudaGetSymbolAddress((void**)&ylo,  g_ylo);
    cudaGetSymbolAddress((void**)&wahi, g_Wahi);
    cudaGetSymbolAddress((void**)&walo, g_Walo);
    cudaGetSymbolAddress((void**)&wphi, g_Wphi);
    cudaGetSymbolAddress((void**)&wplo, g_Wplo);

    static bool attr_done = false;
    if (!attr_done) {
        cudaFuncSetAttribute(hmma_gemm_kernel,
                             cudaFuncAttributeMaxDynamicSharedMemorySize, GEMM_SMEM);
        cudaFuncSetAttribute(attn_kernel,
                             cudaFuncAttributeMaxDynamicSharedMemorySize,
                             4 * DD * PAD * (int)sizeof(float));
        attr_done = true;
    }

    // 1) split x -> bf16 hi/lo
    {
        int n4 = BT * CC / 4;
        split_kernel<<<(n4 + 255) / 256, 256>>>(x, xhi, xlo, n4);
    }
    // 2) transpose+split weights
    transpose_split_kernel<<<dim3(C3 / 32, CC / 32), dim3(32, 8)>>>(W_attn, wahi, walo, CC, C3);
    transpose_split_kernel<<<dim3(CC / 32, CC / 32), dim3(32, 8)>>>(W_proj, wphi, wplo, CC, CC);

    // 3) QKV = x @ W_attn + b_attn  (HMMA split-bf16)
    hmma_gemm_kernel<<<dim3(C3 / GT_N, BT / GT_M), 256, GEMM_SMEM>>>(
        xhi, xlo, wahi, walo, b_attn, qkv, C3);

    // 4) flash attention
    attn_kernel<<<dim3(TT / BQ, HH, BB), 256, 4 * DD * PAD * (int)sizeof(float)>>>(qkv, y);

    // 5) split y
    {
        int n4 = BT * CC / 4;
        split_kernel<<<(n4 + 255) / 256, 256>>>(y, yhi, ylo, n4);
    }

    // 6) out = y @ W_proj + b_proj  (HMMA split-bf16)
    hmma_gemm_kernel<<<dim3(CC / GT_N, BT / GT_M), 256, GEMM_SMEM>>>(
        yhi, ylo, wphi, wplo, b_proj, out, CC);
}

// round 6
// speedup vs baseline: 3.0287x; 1.8295x over previous
#include <cuda_runtime.h>
#include <cuda_bf16.h>
#include <cstdint>

// Problem constants: B=4, T=2048, C=1024, H=16, D=64
#define BB   4
#define TT   2048
#define CC   1024
#define C3   3072
#define HH   16
#define DD   64
#define BT   (BB * TT)          // 8192 rows
#define KK   1024               // GEMM K (both GEMMs)

// ---------------------------------------------------------------------------
// Scratch (__device__ globals; no allocation allowed)
// ---------------------------------------------------------------------------
__device__ __align__(1024) __nv_bfloat16  g_qkvh[(size_t)BT * C3];   // qkv hi
__device__ __align__(1024) __nv_bfloat16  g_qkvl[(size_t)BT * C3];   // qkv lo
__device__ __align__(1024) __nv_bfloat16  g_xhi[(size_t)BT * CC];
__device__ __align__(1024) __nv_bfloat16  g_xlo[(size_t)BT * CC];
__device__ __align__(1024) __nv_bfloat16  g_yhi[(size_t)BT * CC];
__device__ __align__(1024) __nv_bfloat16  g_ylo[(size_t)BT * CC];
__device__ __align__(1024) __nv_bfloat16  g_Wahi[(size_t)C3 * CC];   // W_attn^T [N,K]
__device__ __align__(1024) __nv_bfloat16  g_Walo[(size_t)C3 * CC];
__device__ __align__(1024) __nv_bfloat16  g_Wphi[(size_t)CC * CC];   // W_proj^T [N,K]
__device__ __align__(1024) __nv_bfloat16  g_Wplo[(size_t)CC * CC];

// ---------------------------------------------------------------------------
// PTX helpers — baseline PTX only (compute_103 has no tcgen05/TMA-tensor!)
// ---------------------------------------------------------------------------
__device__ __forceinline__ uint32_t smem_u32(const void* p) {
    uint32_t a;
    asm("{ .reg .u64 t; cvta.to.shared.u64 t, %1; cvt.u32.u64 %0, t; }" : "=r"(a) : "l"(p));
    return a;
}
__device__ __forceinline__ void cp16(uint32_t saddr, const void* g) {
    asm volatile("cp.async.cg.shared.global [%0], [%1], 16;\n" :: "r"(saddr), "l"(g));
}
__device__ __forceinline__ void cp_commit() {
    asm volatile("cp.async.commit_group;\n" ::: "memory");
}
template<int N> __device__ __forceinline__ void cp_wait() {
    asm volatile("cp.async.wait_group %0;\n" :: "n"(N) : "memory");
}
__device__ __forceinline__ void ldsm_x4(uint32_t* r, uint32_t addr) {
    asm volatile("ldmatrix.sync.aligned.m8n8.x4.shared.b16 {%0,%1,%2,%3}, [%4];"
        : "=r"(r[0]), "=r"(r[1]), "=r"(r[2]), "=r"(r[3]) : "r"(addr));
}
__device__ __forceinline__ void ldsm_x4_t(uint32_t* r, uint32_t addr) {
    asm volatile("ldmatrix.sync.aligned.m8n8.x4.trans.shared.b16 {%0,%1,%2,%3}, [%4];"
        : "=r"(r[0]), "=r"(r[1]), "=r"(r[2]), "=r"(r[3]) : "r"(addr));
}
__device__ __forceinline__ void mma16816(float* d, const uint32_t* a, const uint32_t* b) {
    asm volatile("mma.sync.aligned.m16n8k16.row.col.f32.bf16.bf16.f32 "
        "{%0,%1,%2,%3}, {%4,%5,%6,%7}, {%8,%9}, {%0,%1,%2,%3};"
        : "+f"(d[0]), "+f"(d[1]), "+f"(d[2]), "+f"(d[3])
        : "r"(a[0]), "r"(a[1]), "r"(a[2]), "r"(a[3]), "r"(b[0]), "r"(b[1]));
}
// swizzled address inside a [rows][128B] tile (SW128: 16B chunks permuted)
__device__ __forceinline__ uint32_t sw_addr(uint32_t base, int row, int kb) {
    uint32_t off = ((uint32_t)row << 7) + (uint32_t)kb;
    return base + (off ^ ((off >> 3) & 0x70));
}
__device__ __forceinline__ uint32_t pack_bf16(float a, float b) {
    __nv_bfloat162 h = __floats2bfloat162_rn(a, b);
    return *(uint32_t*)&h;
}

// ---------------------------------------------------------------------------
// Split fp32 -> bf16 hi/lo (for input x)
// ---------------------------------------------------------------------------
__global__ void split_kernel(const float* __restrict__ src,
                             __nv_bfloat16* __restrict__ hi,
                             __nv_bfloat16* __restrict__ lo, int n4) {
    int i = blockIdx.x * blockDim.x + threadIdx.x;
    if (i >= n4) return;
    float4 v = ((const float4*)src)[i];
    __nv_bfloat16 h0 = __float2bfloat16(v.x), h1 = __float2bfloat16(v.y);
    __nv_bfloat16 h2 = __float2bfloat16(v.z), h3 = __float2bfloat16(v.w);
    __nv_bfloat16 l0 = __float2bfloat16(v.x - __bfloat162float(h0));
    __nv_bfloat16 l1 = __float2bfloat16(v.y - __bfloat162float(h1));
    __nv_bfloat16 l2 = __float2bfloat16(v.z - __bfloat162float(h2));
    __nv_bfloat16 l3 = __float2bfloat16(v.w - __bfloat162float(h3));
    ((__nv_bfloat162*)hi)[2*i]   = __nv_bfloat162(h0, h1);
    ((__nv_bfloat162*)hi)[2*i+1] = __nv_bfloat162(h2, h3);
    ((__nv_bfloat162*)lo)[2*i]   = __nv_bfloat162(l0, l1);
    ((__nv_bfloat162*)lo)[2*i+1] = __nv_bfloat162(l2, l3);
}

// Transpose W[K,N] -> Wt[N,K] with hi/lo split
__global__ void transpose_split_kernel(const float* __restrict__ W,
                                       __nv_bfloat16* __restrict__ Th,
                                       __nv_bfloat16* __restrict__ Tl,
                                       int K, int N) {
    __shared__ float t[32][33];
    int tx = threadIdx.x, ty = threadIdx.y;
    int n0 = blockIdx.x * 32, k0 = blockIdx.y * 32;
    #pragma unroll
    for (int j = 0; j < 4; j++)
        t[ty + 8*j][tx] = W[(size_t)(k0 + ty + 8*j) * N + n0 + tx];
    __syncthreads();
    #pragma unroll
    for (int j = 0; j < 4; j++) {
        float v = t[tx][ty + 8*j];
        __nv_bfloat16 h = __float2bfloat16(v);
        __nv_bfloat16 l = __float2bfloat16(v - __bfloat162float(h));
        size_t idx = (size_t)(n0 + ty + 8*j) * K + k0 + tx;
        Th[idx] = h;
        Tl[idx] = l;
    }
}

// ---------------------------------------------------------------------------
// mma.sync split-bf16 GEMM: C = Ahi·Bhi^T + Ahi·Blo^T + Alo·Bhi^T + bias
// SPLIT=true: write bf16 hi/lo outputs; SPLIT=false: write fp32.
// CTA 128x128, BK=64 (128B rows, SW128), 8 warps (2m x 4n), 2-stage cp.async.
// ---------------------------------------------------------------------------
#define GT_M   128
#define GT_N   128
#define GT_K   64
#define NKCH   (KK / GT_K)                // 16
#define TILE_B (128 * 128)                // 16384 bytes per [128][64bf16] tile
#define OFF_AH 0
#define OFF_AL (TILE_B)
#define OFF_BH (2 * TILE_B)
#define OFF_BL (3 * TILE_B)
#define STAGE  (4 * TILE_B)               // 65536
#define GEMM_SMEM (2 * STAGE)             // 131072

__device__ __forceinline__ void load_buf(uint32_t sdst, const char* g,
                                         int kbytes, int tid) {
    #pragma unroll
    for (int it = 0; it < 4; it++) {
        int c = tid + it * 256;           // 1024 chunks of 16B
        int r = c >> 3;
        int cb = (c & 7) << 4;
        uint32_t off = ((uint32_t)r << 7) | (uint32_t)cb;
        uint32_t sw = off ^ ((off >> 3) & 0x70);
        cp16(sdst + sw, g + (size_t)r * 2048 + kbytes + cb);
    }
}

template<bool SPLIT>
__global__ __launch_bounds__(256)
void hmma_gemm_kernel(const __nv_bfloat16* __restrict__ Ahi,
                      const __nv_bfloat16* __restrict__ Alo,
                      const __nv_bfloat16* __restrict__ Bhi,
                      const __nv_bfloat16* __restrict__ Blo,
                      const float* __restrict__ bias,
                      float* __restrict__ C,
                      __nv_bfloat16* __restrict__ Ch,
                      __nv_bfloat16* __restrict__ Cl, int N) {
    extern __shared__ char smem[];
    const uint32_t sbase = smem_u32(smem);
    const int tid  = threadIdx.x;
    const int lane = tid & 31;
    const int wid  = tid >> 5;
    const int wm   = wid >> 2;
    const int wn   = wid & 3;
    const int bx   = blockIdx.x;
    const int by   = blockIdx.y;

    const char* gAh = (const char*)Ahi + (size_t)by * GT_M * 2048;
    const char* gAl = (const char*)Alo + (size_t)by * GT_M * 2048;
    const char* gBh = (const char*)Bhi + (size_t)bx * GT_N * 2048;
    const char* gBl = (const char*)Blo + (size_t)bx * GT_N * 2048;

    #pragma unroll
    for (int st = 0; st < 2; st++) {
        uint32_t sb = sbase + st * STAGE;
        int kb = st * 128;
        load_buf(sb + OFF_AH, gAh, kb, tid);
        load_buf(sb + OFF_AL, gAl, kb, tid);
        load_buf(sb + OFF_BH, gBh, kb, tid);
        load_buf(sb + OFF_BL, gBl, kb, tid);
        cp_commit();
    }

    float acc[4][4][4];
    #pragma unroll
    for (int mt = 0; mt < 4; mt++)
        #pragma unroll
        for (int nt = 0; nt < 4; nt++)
            #pragma unroll
            for (int r = 0; r < 4; r++) acc[mt][nt][r] = 0.f;

    const int arow = wm * 64 + (lane & 15);
    const int akb  = (lane >> 4) << 4;
    const int brow = wn * 32 + (lane & 7) + ((lane >> 4) << 3);
    const int bkb  = ((lane >> 3) & 1) << 4;

    for (int i = 0; i < NKCH; i++) {
        const int s = i & 1;
        const uint32_t sb = sbase + s * STAGE;

        if (i < NKCH - 1) cp_wait<1>(); else cp_wait<0>();
        __syncthreads();

        #pragma unroll
        for (int ks = 0; ks < 4; ks++) {
            const int ksb = ks * 32;
            uint32_t ah[4][4], al[4][4], bh[2][4], bl[2][4];
            #pragma unroll
            for (int mt = 0; mt < 4; mt++) {
                ldsm_x4(ah[mt], sw_addr(sb + OFF_AH, arow + mt * 16, ksb + akb));
                ldsm_x4(al[mt], sw_addr(sb + OFF_AL, arow + mt * 16, ksb + akb));
            }
            #pragma unroll
            for (int p = 0; p < 2; p++) {
                ldsm_x4(bh[p], sw_addr(sb + OFF_BH, brow + p * 16, ksb + bkb));
                ldsm_x4(bl[p], sw_addr(sb + OFF_BL, brow + p * 16, ksb + bkb));
            }
            #pragma unroll
            for (int mt = 0; mt < 4; mt++)
                #pragma unroll
                for (int nt = 0; nt < 4; nt++)
                    mma16816(acc[mt][nt], ah[mt], &bh[nt >> 1][(nt & 1) * 2]);
            #pragma unroll
            for (int mt = 0; mt < 4; mt++)
                #pragma unroll
                for (int nt = 0; nt < 4; nt++)
                    mma16816(acc[mt][nt], ah[mt], &bl[nt >> 1][(nt & 1) * 2]);
            #pragma unroll
            for (int mt = 0; mt < 4; mt++)
                #pragma unroll
                for (int nt = 0; nt < 4; nt++)
                    mma16816(acc[mt][nt], al[mt], &bh[nt >> 1][(nt & 1) * 2]);
        }
        __syncthreads();

        if (i + 2 < NKCH) {
            int kb = (i + 2) * 128;
            load_buf(sb + OFF_AH, gAh, kb, tid);
            load_buf(sb + OFF_AL, gAl, kb, tid);
            load_buf(sb + OFF_BH, gBh, kb, tid);
            load_buf(sb + OFF_BL, gBl, kb, tid);
            cp_commit();
        }
    }

    // Epilogue
    const int g = lane >> 2, t = lane & 3;
    const int row_base = by * GT_M + wm * 64 + g;
    const int col_base = bx * GT_N + wn * 32 + t * 2;
    #pragma unroll
    for (int mt = 0; mt < 4; mt++) {
        const int r0 = row_base + mt * 16;
        #pragma unroll
        for (int nt = 0; nt < 4; nt++) {
            const int c = col_base + nt * 8;
            float b0 = bias[c], b1 = bias[c + 1];
            float v0 = acc[mt][nt][0] + b0, v1 = acc[mt][nt][1] + b1;
            float v2 = acc[mt][nt][2] + b0, v3 = acc[mt][nt][3] + b1;
            if (SPLIT) {
                __nv_bfloat16 h0 = __float2bfloat16(v0), h1 = __float2bfloat16(v1);
                __nv_bfloat16 h2 = __float2bfloat16(v2), h3 = __float2bfloat16(v3);
                *(__nv_bfloat162*)(Ch + (size_t)r0 * N + c)       = __nv_bfloat162(h0, h1);
                *(__nv_bfloat162*)(Ch + (size_t)(r0 + 8) * N + c) = __nv_bfloat162(h2, h3);
                *(__nv_bfloat162*)(Cl + (size_t)r0 * N + c)       = __nv_bfloat162(
                    __float2bfloat16(v0 - __bfloat162float(h0)),
                    __float2bfloat16(v1 - __bfloat162float(h1)));
                *(__nv_bfloat162*)(Cl + (size_t)(r0 + 8) * N + c) = __nv_bfloat162(
                    __float2bfloat16(v2 - __bfloat162float(h2)),
                    __float2bfloat16(v3 - __bfloat162float(h3)));
            } else {
                *(float2*)(C + (size_t)r0 * N + c)       = make_float2(v0, v1);
                *(float2*)(C + (size_t)(r0 + 8) * N + c) = make_float2(v2, v3);
            }
        }
    }
}

// ---------------------------------------------------------------------------
// mma.sync flash attention (causal, split-bf16 3-term everywhere).
// CTA: 128 q rows (8 warps x 16 rows), BK=64 kv chunks, 2-stage cp.async.
// Reads qkv hi/lo bf16; writes y hi/lo bf16.
// ---------------------------------------------------------------------------
#define AT_BQ 128
#define AT_BK 64
#define A_QH  0
#define A_QL  16384
#define A_KV0 32768
#define KV_KH 0
#define KV_KL 8192
#define KV_VH 16384
#define KV_VL 24576
#define KV_STAGE 32768
#define ATTN_SMEM (A_KV0 + 2 * KV_STAGE)   // 98304

// rows=64 tile load, gmem pitch 6144 B (C3 bf16)
__device__ __forceinline__ void load_rows64(uint32_t sdst, const char* g, int tid) {
    #pragma unroll
    for (int it = 0; it < 2; it++) {
        int c = tid + it * 256;
        int r = c >> 3;
        int cb = (c & 7) << 4;
        uint32_t off = ((uint32_t)r << 7) | (uint32_t)cb;
        cp16(sdst + (off ^ ((off >> 3) & 0x70)), g + (size_t)r * 6144 + cb);
    }
}
__device__ __forceinline__ void load_rows128(uint32_t sdst, const char* g, int tid) {
    #pragma unroll
    for (int it = 0; it < 4; it++) {
        int c = tid + it * 256;
        int r = c >> 3;
        int cb = (c & 7) << 4;
        uint32_t off = ((uint32_t)r << 7) | (uint32_t)cb;
        cp16(sdst + (off ^ ((off >> 3) & 0x70)), g + (size_t)r * 6144 + cb);
    }
}

__global__ __launch_bounds__(256)
void attn_mma_kernel(const __nv_bfloat16* __restrict__ qh,
                     const __nv_bfloat16* __restrict__ ql,
                     __nv_bfloat16* __restrict__ yh,
                     __nv_bfloat16* __restrict__ yl)
{
    extern __shared__ char smem[];
    const uint32_t sbase = smem_u32(smem);
    const int tid  = threadIdx.x;
    const int lane = tid & 31;
    const int w    = tid >> 5;            // warp 0..7, owns q rows w*16..+15
    const int qt = blockIdx.x, h = blockIdx.y, b = blockIdx.z;
    const int q0 = qt * AT_BQ;
    const int n  = 2 * qt + 2;            // kv chunks

    const char* gQh = (const char*)(qh + (size_t)(b * TT + q0) * C3 + h * DD);
    const char* gQl = (const char*)(ql + (size_t)(b * TT + q0) * C3 + h * DD);

    // prologue: Q then KV0, KV1
    load_rows128(sbase + A_QH, gQh, tid);
    load_rows128(sbase + A_QL, gQl, tid);
    cp_commit();
    #pragma unroll 1
    for (int c = 0; c < 2; c++) {
        if (c >= n) break;
        uint32_t sb = sbase + A_KV0 + c * KV_STAGE;
        const char* gK = (const char*)(qh + (size_t)(b * TT + c * AT_BK) * C3 + CC + h * DD);
        const char* gKl = (const char*)(ql + (size_t)(b * TT + c * AT_BK) * C3 + CC + h * DD);
        load_rows64(sb + KV_KH, gK, tid);
        load_rows64(sb + KV_KL, gKl, tid);
        load_rows64(sb + KV_VH, gK + 2048, tid);    // V = +CC bf16 = +2048 B
        load_rows64(sb + KV_VL, gKl + 2048, tid);
        cp_commit();
    }

    cp_wait<2>();
    __syncthreads();

    // Q fragments (loop-invariant): 4 ksteps x 4 regs, hi+lo
    const int arow = w * 16 + (lane & 15);
    const int akb  = (lane >> 4) << 4;
    uint32_t qfh[4][4], qfl[4][4];
    #pragma unroll
    for (int ks = 0; ks < 4; ks++) {
        ldsm_x4(qfh[ks], sw_addr(sbase + A_QH, arow, ks * 32 + akb));
        ldsm_x4(qfl[ks], sw_addr(sbase + A_QL, arow, ks * 32 + akb));
    }

    float oacc[8][4];
    #pragma unroll
    for (int nt = 0; nt < 8; nt++)
        #pragma unroll
        for (int r = 0; r < 4; r++) oacc[nt][r] = 0.f;
    float m0 = -1e30f, m1 = -1e30f, l0 = 0.f, l1 = 0.f;

    const int g_ = lane >> 2, t_ = lane & 3;
    const int brow = (lane & 7) + ((lane >> 4) << 3);
    const int bkb  = ((lane >> 3) & 1) << 4;
    const int vrow = ((lane >> 3) & 1) * 8 + (lane & 7);
    const int vcb  = (lane >> 4) << 4;

    for (int c = 0; c < n; c++) {
        if (c + 1 < n) cp_wait<1>(); else cp_wait<0>();
        __syncthreads();
        const uint32_t sb = sbase + A_KV0 + (c & 1) * KV_STAGE;
        const int kv0 = c * AT_BK;
        const bool active = (kv0 <= q0 + w * 16 + 15);
        const bool need_mask = (kv0 + 63 > q0 + w * 16);

        if (active) {
            // ---- S = Q K^T (3-term) ----
            float sacc[8][4];
            #pragma unroll
            for (int nt = 0; nt < 8; nt++)
                #pragma unroll
                for (int r = 0; r < 4; r++) sacc[nt][r] = 0.f;

            #pragma unroll
            for (int ks = 0; ks < 4; ks++) {
                const int ksb = ks * 32;
                uint32_t kh4[4][4], kl4[4][4];
                #pragma unroll
                for (int p = 0; p < 4; p++) {
                    ldsm_x4(kh4[p], sw_addr(sb + KV_KH, p * 16 + brow, ksb + bkb));
                    ldsm_x4(kl4[p], sw_addr(sb + KV_KL, p * 16 + brow, ksb + bkb));
                }
                #pragma unroll
                for (int p = 0; p < 4; p++) {
                    mma16816(sacc[2*p],   qfh[ks], &kh4[p][0]);
                    mma16816(sacc[2*p+1], qfh[ks], &kh4[p][2]);
                }
                #pragma unroll
                for (int p = 0; p < 4; p++) {
                    mma16816(sacc[2*p],   qfh[ks], &kl4[p][0]);
                    mma16816(sacc[2*p+1], qfh[ks], &kl4[p][2]);
                }
                #pragma unroll
                for (int p = 0; p < 4; p++) {
                    mma16816(sacc[2*p],   qfl[ks], &kh4[p][0]);
                    mma16816(sacc[2*p+1], qfl[ks], &kh4[p][2]);
                }
            }

            // scale + causal mask
            const int row0 = q0 + w * 16 + g_;
            #pragma unroll
            for (int nt = 0; nt < 8; nt++)
                #pragma unroll
                for (int r = 0; r < 4; r++) sacc[nt][r] *= 0.125f;
            if (need_mask) {
                #pragma unroll
                for (int nt = 0; nt < 8; nt++) {
                    int col = kv0 + nt * 8 + 2 * t_;
                    if (col     > row0)     sacc[nt][0] = -1e30f;
                    if (col + 1 > row0)     sacc[nt][1] = -1e30f;
                    if (col     > row0 + 8) sacc[nt][2] = -1e30f;
                    if (col + 1 > row0 + 8) sacc[nt][3] = -1e30f;
                }
            }

            // ---- online softmax (rows g_, g_+8) ----
            float mx0 = -1e30f, mx1 = -1e30f;
            #pragma unroll
            for (int nt = 0; nt < 8; nt++) {
                mx0 = fmaxf(mx0, fmaxf(sacc[nt][0], sacc[nt][1]));
                mx1 = fmaxf(mx1, fmaxf(sacc[nt][2], sacc[nt][3]));
            }
            mx0 = fmaxf(mx0, __shfl_xor_sync(0xffffffffu, mx0, 1));
            mx0 = fmaxf(mx0, __shfl_xor_sync(0xffffffffu, mx0, 2));
            mx1 = fmaxf(mx1, __shfl_xor_sync(0xffffffffu, mx1, 1));
            mx1 = fmaxf(mx1, __shfl_xor_sync(0xffffffffu, mx1, 2));
            mx0 = fmaxf(mx0, m0);
            mx1 = fmaxf(mx1, m1);

            float rs0 = 0.f, rs1 = 0.f;
            #pragma unroll
            for (int nt = 0; nt < 8; nt++) {
                sacc[nt][0] = __expf(sacc[nt][0] - mx0);
                sacc[nt][1] = __expf(sacc[nt][1] - mx0);
                sacc[nt][2] = __expf(sacc[nt][2] - mx1);
                sacc[nt][3] = __expf(sacc[nt][3] - mx1);
                rs0 += sacc[nt][0] + sacc[nt][1];
                rs1 += sacc[nt][2] + sacc[nt][3];
            }
            rs0 += __shfl_xor_sync(0xffffffffu, rs0, 1);
            rs0 += __shfl_xor_sync(0xffffffffu, rs0, 2);
            rs1 += __shfl_xor_sync(0xffffffffu, rs1, 1);
            rs1 += __shfl_xor_sync(0xffffffffu, rs1, 2);

            float a0 = __expf(m0 - mx0);
            float a1 = __expf(m1 - mx1);
            m0 = mx0; m1 = mx1;
            l0 = l0 * a0 + rs0;
            l1 = l1 * a1 + rs1;
            #pragma unroll
            for (int nt = 0; nt < 8; nt++) {
                oacc[nt][0] *= a0; oacc[nt][1] *= a0;
                oacc[nt][2] *= a1; oacc[nt][3] *= a1;
            }

            // ---- pack P hi/lo (accumulator -> A fragment register reuse) ----
            uint32_t ph[8][2], pl[8][2];
            #pragma unroll
            for (int nt = 0; nt < 8; nt++) {
                float p0 = sacc[nt][0], p1 = sacc[nt][1];
                float p2 = sacc[nt][2], p3 = sacc[nt][3];
                __nv_bfloat16 h0 = __float2bfloat16(p0), h1 = __float2bfloat16(p1);
                __nv_bfloat16 h2 = __float2bfloat16(p2), h3 = __float2bfloat16(p3);
                ph[nt][0] = pack_bf16(__bfloat162float(h0), __bfloat162float(h1));
                ph[nt][1] = pack_bf16(__bfloat162float(h2), __bfloat162float(h3));
                pl[nt][0] = pack_bf16(p0 - __bfloat162float(h0), p1 - __bfloat162float(h1));
                pl[nt][1] = pack_bf16(p2 - __bfloat162float(h2), p3 - __bfloat162float(h3));
            }

            // ---- O += P V (3-term), V via ldmatrix.trans ----
            #pragma unroll
            for (int kk = 0; kk < 4; kk++) {
                uint32_t aPh[4] = {ph[2*kk][0], ph[2*kk][1], ph[2*kk+1][0], ph[2*kk+1][1]};
                uint32_t aPl[4] = {pl[2*kk][0], pl[2*kk][1], pl[2*kk+1][0], pl[2*kk+1][1]};
                uint32_t vh4[4][4], vl4[4][4];
                #pragma unroll
                for (int dd = 0; dd < 4; dd++) {
                    ldsm_x4_t(vh4[dd], sw_addr(sb + KV_VH, kk * 16 + vrow, dd * 32 + vcb));
                    ldsm_x4_t(vl4[dd], sw_addr(sb + KV_VL, kk * 16 + vrow, dd * 32 + vcb));
                }
                #pragma unroll
                for (int dd = 0; dd < 4; dd++) {
                    mma16816(oacc[2*dd],   aPh, &vh4[dd][0]);
                    mma16816(oacc[2*dd+1], aPh, &vh4[dd][2]);
                }
                #pragma unroll
                for (int dd = 0; dd < 4; dd++) {
                    mma16816(oacc[2*dd],   aPh, &vl4[dd][0]);
                    mma16816(oacc[2*dd+1], aPh, &vl4[dd][2]);
                }
                #pragma unroll
                for (int dd = 0; dd < 4; dd++) {
                    mma16816(oacc[2*dd],   aPl, &vh4[dd][0]);
                    mma16816(oacc[2*dd+1], aPl, &vh4[dd][2]);
                }
            }
        }
        __syncthreads();

        if (c + 2 < n) {
            uint32_t sb2 = sbase + A_KV0 + (c & 1) * KV_STAGE;
            const char* gK  = (const char*)(qh + (size_t)(b * TT + (c + 2) * AT_BK) * C3 + CC + h * DD);
            const char* gKl = (const char*)(ql + (size_t)(b * TT + (c + 2) * AT_BK) * C3 + CC + h * DD);
            load_rows64(sb2 + KV_KH, gK, tid);
            load_rows64(sb2 + KV_KL, gKl, tid);
            load_rows64(sb2 + KV_VH, gK + 2048, tid);
            load_rows64(sb2 + KV_VL, gKl + 2048, tid);
            cp_commit();
        }
    }

    // ---- epilogue: normalize, split hi/lo, store y ----
    const float inv0 = 1.f / l0, inv1 = 1.f / l1;
    const size_t row0 = (size_t)(b * TT + q0 + w * 16 + g_);
    const int col0 = h * DD + 2 * t_;
    #pragma unroll
    for (int nt = 0; nt < 8; nt++) {
        float v0 = oacc[nt][0] * inv0, v1 = oacc[nt][1] * inv0;
        float v2 = oacc[nt][2] * inv1, v3 = oacc[nt][3] * inv1;
        __nv_bfloat16 h0 = __float2bfloat16(v0), h1 = __float2bfloat16(v1);
        __nv_bfloat16 h2 = __float2bfloat16(v2), h3 = __float2bfloat16(v3);
        size_t i0 = row0 * CC + col0 + nt * 8;
        size_t i1 = (row0 + 8) * CC + col0 + nt * 8;
        *(__nv_bfloat162*)(yh + i0) = __nv_bfloat162(h0, h1);
        *(__nv_bfloat162*)(yh + i1) = __nv_bfloat162(h2, h3);
        *(__nv_bfloat162*)(yl + i0) = __nv_bfloat162(
            __float2bfloat16(v0 - __bfloat162float(h0)),
            __float2bfloat16(v1 - __bfloat162float(h1)));
        *(__nv_bfloat162*)(yl + i1) = __nv_bfloat162(
            __float2bfloat16(v2 - __bfloat162float(h2)),
            __float2bfloat16(v3 - __bfloat162float(h3)));
    }
}

// ---------------------------------------------------------------------------
extern "C" void kernel_launch(void* const* d_in, const int* in_sizes, int n_in,
                              void* d_out, int out_size)
{
    const float* x      = (const float*)d_in[0];
    const float* W_attn = (const float*)d_in[1];
    const float* b_attn = (const float*)d_in[2];
    const float* W_proj = (const float*)d_in[3];
    const float* b_proj = (const float*)d_in[4];
    float* out = (float*)d_out;

    __nv_bfloat16 *qkvh, *qkvl, *xhi, *xlo, *yhi, *ylo, *wahi, *walo, *wphi, *wplo;
    cudaGetSymbolAddress((void**)&qkvh, g_qkvh);
    cudaGetSymbolAddress((void**)&qkvl, g_qkvl);
    cudaGetSymbolAddress((void**)&xhi,  g_xhi);
    cudaGetSymbolAddress((void**)&xlo,  g_xlo);
    cudaGetSymbolAddress((void**)&yhi,  g_yhi);
    cudaGetSymbolAddress((void**)&ylo,  g_ylo);
    cudaGetSymbolAddress((void**)&wahi, g_Wahi);
    cudaGetSymbolAddress((void**)&walo, g_Walo);
    cudaGetSymbolAddress((void**)&wphi, g_Wphi);
    cudaGetSymbolAddress((void**)&wplo, g_Wplo);

    static bool attr_done = false;
    if (!attr_done) {
        cudaFuncSetAttribute(hmma_gemm_kernel<true>,
                             cudaFuncAttributeMaxDynamicSharedMemorySize, GEMM_SMEM);
        cudaFuncSetAttribute(hmma_gemm_kernel<false>,
                             cudaFuncAttributeMaxDynamicSharedMemorySize, GEMM_SMEM);
        cudaFuncSetAttribute(attn_mma_kernel,
                             cudaFuncAttributeMaxDynamicSharedMemorySize, ATTN_SMEM);
        attr_done = true;
    }

    // 1) split x -> bf16 hi/lo
    {
        int n4 = BT * CC / 4;
        split_kernel<<<(n4 + 255) / 256, 256>>>(x, xhi, xlo, n4);
    }
    // 2) transpose+split weights
    transpose_split_kernel<<<dim3(C3 / 32, CC / 32), dim3(32, 8)>>>(W_attn, wahi, walo, CC, C3);
    transpose_split_kernel<<<dim3(CC / 32, CC / 32), dim3(32, 8)>>>(W_proj, wphi, wplo, CC, CC);

    // 3) QKV GEMM -> qkv hi/lo bf16 (fused split epilogue)
    hmma_gemm_kernel<true><<<dim3(C3 / GT_N, BT / GT_M), 256, GEMM_SMEM>>>(
        xhi, xlo, wahi, walo, b_attn, nullptr, qkvh, qkvl, C3);

    // 4) tensor-core flash attention -> y hi/lo bf16
    attn_mma_kernel<<<dim3(TT / AT_BQ, HH, BB), 256, ATTN_SMEM>>>(qkvh, qkvl, yhi, ylo);

    // 5) proj GEMM -> out fp32
    hmma_gemm_kernel<false><<<dim3(CC / GT_N, BT / GT_M), 256, GEMM_SMEM>>>(
        yhi, ylo, wphi, wplo, b_proj, out, nullptr, nullptr, CC);
}

// round 7
// speedup vs baseline: 3.1504x; 1.0402x over previous
#include <cuda_runtime.h>
#include <cuda_bf16.h>
#include <cstdint>

// Problem constants: B=4, T=2048, C=1024, H=16, D=64
#define BB   4
#define TT   2048
#define CC   1024
#define C3   3072
#define HH   16
#define DD   64
#define BT   (BB * TT)          // 8192 rows
#define KK   1024               // GEMM K (both GEMMs)

// ---------------------------------------------------------------------------
// Scratch (__device__ globals; no allocation allowed)
// ---------------------------------------------------------------------------
__device__ __align__(1024) __nv_bfloat16  g_qkvh[(size_t)BT * C3];   // qkv hi
__device__ __align__(1024) __nv_bfloat16  g_qkvl[(size_t)BT * C3];   // qkv lo
__device__ __align__(1024) __nv_bfloat16  g_xhi[(size_t)BT * CC];
__device__ __align__(1024) __nv_bfloat16  g_xlo[(size_t)BT * CC];
__device__ __align__(1024) __nv_bfloat16  g_yhi[(size_t)BT * CC];
__device__ __align__(1024) __nv_bfloat16  g_ylo[(size_t)BT * CC];
__device__ __align__(1024) __nv_bfloat16  g_Wahi[(size_t)C3 * CC];   // W_attn^T [N,K]
__device__ __align__(1024) __nv_bfloat16  g_Walo[(size_t)C3 * CC];
__device__ __align__(1024) __nv_bfloat16  g_Wphi[(size_t)CC * CC];   // W_proj^T [N,K]
__device__ __align__(1024) __nv_bfloat16  g_Wplo[(size_t)CC * CC];

// ---------------------------------------------------------------------------
// PTX helpers — baseline PTX only (compute_103 has no tcgen05/TMA-tensor!)
// ---------------------------------------------------------------------------
__device__ __forceinline__ uint32_t smem_u32(const void* p) {
    uint32_t a;
    asm("{ .reg .u64 t; cvta.to.shared.u64 t, %1; cvt.u32.u64 %0, t; }" : "=r"(a) : "l"(p));
    return a;
}
__device__ __forceinline__ void cp16(uint32_t saddr, const void* g) {
    asm volatile("cp.async.cg.shared.global [%0], [%1], 16;\n" :: "r"(saddr), "l"(g));
}
__device__ __forceinline__ void cp_commit() {
    asm volatile("cp.async.commit_group;\n" ::: "memory");
}
template<int N> __device__ __forceinline__ void cp_wait() {
    asm volatile("cp.async.wait_group %0;\n" :: "n"(N) : "memory");
}
__device__ __forceinline__ void ldsm_x4(uint32_t* r, uint32_t addr) {
    asm volatile("ldmatrix.sync.aligned.m8n8.x4.shared.b16 {%0,%1,%2,%3}, [%4];"
        : "=r"(r[0]), "=r"(r[1]), "=r"(r[2]), "=r"(r[3]) : "r"(addr));
}
__device__ __forceinline__ void ldsm_x4_t(uint32_t* r, uint32_t addr) {
    asm volatile("ldmatrix.sync.aligned.m8n8.x4.trans.shared.b16 {%0,%1,%2,%3}, [%4];"
        : "=r"(r[0]), "=r"(r[1]), "=r"(r[2]), "=r"(r[3]) : "r"(addr));
}
__device__ __forceinline__ void mma16816(float* d, const uint32_t* a, const uint32_t* b) {
    asm volatile("mma.sync.aligned.m16n8k16.row.col.f32.bf16.bf16.f32 "
        "{%0,%1,%2,%3}, {%4,%5,%6,%7}, {%8,%9}, {%0,%1,%2,%3};"
        : "+f"(d[0]), "+f"(d[1]), "+f"(d[2]), "+f"(d[3])
        : "r"(a[0]), "r"(a[1]), "r"(a[2]), "r"(a[3]), "r"(b[0]), "r"(b[1]));
}
// swizzled address inside a [rows][128B] tile (SW128: 16B chunks permuted)
__device__ __forceinline__ uint32_t sw_addr(uint32_t base, int row, int kb) {
    uint32_t off = ((uint32_t)row << 7) + (uint32_t)kb;
    return base + (off ^ ((off >> 3) & 0x70));
}
__device__ __forceinline__ uint32_t pack_bf16(float a, float b) {
    __nv_bfloat162 h = __floats2bfloat162_rn(a, b);
    return *(uint32_t*)&h;
}

// ---------------------------------------------------------------------------
// Split fp32 -> bf16 hi/lo (for input x)
// ---------------------------------------------------------------------------
__global__ void split_kernel(const float* __restrict__ src,
                             __nv_bfloat16* __restrict__ hi,
                             __nv_bfloat16* __restrict__ lo, int n4) {
    int i = blockIdx.x * blockDim.x + threadIdx.x;
    if (i >= n4) return;
    float4 v = ((const float4*)src)[i];
    __nv_bfloat16 h0 = __float2bfloat16(v.x), h1 = __float2bfloat16(v.y);
    __nv_bfloat16 h2 = __float2bfloat16(v.z), h3 = __float2bfloat16(v.w);
    __nv_bfloat16 l0 = __float2bfloat16(v.x - __bfloat162float(h0));
    __nv_bfloat16 l1 = __float2bfloat16(v.y - __bfloat162float(h1));
    __nv_bfloat16 l2 = __float2bfloat16(v.z - __bfloat162float(h2));
    __nv_bfloat16 l3 = __float2bfloat16(v.w - __bfloat162float(h3));
    ((__nv_bfloat162*)hi)[2*i]   = __nv_bfloat162(h0, h1);
    ((__nv_bfloat162*)hi)[2*i+1] = __nv_bfloat162(h2, h3);
    ((__nv_bfloat162*)lo)[2*i]   = __nv_bfloat162(l0, l1);
    ((__nv_bfloat162*)lo)[2*i+1] = __nv_bfloat162(l2, l3);
}

// Transpose W[K,N] -> Wt[N,K] with hi/lo split
__global__ void transpose_split_kernel(const float* __restrict__ W,
                                       __nv_bfloat16* __restrict__ Th,
                                       __nv_bfloat16* __restrict__ Tl,
                                       int K, int N) {
    __shared__ float t[32][33];
    int tx = threadIdx.x, ty = threadIdx.y;
    int n0 = blockIdx.x * 32, k0 = blockIdx.y * 32;
    #pragma unroll
    for (int j = 0; j < 4; j++)
        t[ty + 8*j][tx] = W[(size_t)(k0 + ty + 8*j) * N + n0 + tx];
    __syncthreads();
    #pragma unroll
    for (int j = 0; j < 4; j++) {
        float v = t[tx][ty + 8*j];
        __nv_bfloat16 h = __float2bfloat16(v);
        __nv_bfloat16 l = __float2bfloat16(v - __bfloat162float(h));
        size_t idx = (size_t)(n0 + ty + 8*j) * K + k0 + tx;
        Th[idx] = h;
        Tl[idx] = l;
    }
}

// ---------------------------------------------------------------------------
// mma.sync split-bf16 GEMM: C = Ahi·Bhi^T + Ahi·Blo^T + Alo·Bhi^T + bias
// SPLIT=true: write bf16 hi/lo outputs; SPLIT=false: write fp32.
// CTA 128x128, BK=64 (128B rows, SW128), 8 warps (2m x 4n).
// 3-stage cp.async ring, ONE __syncthreads per chunk.
// ---------------------------------------------------------------------------
#define GT_M   128
#define GT_N   128
#define GT_K   64
#define NKCH   (KK / GT_K)                // 16
#define TILE_B (128 * 128)                // 16384 bytes per [128][64bf16] tile
#define OFF_AH 0
#define OFF_AL (TILE_B)
#define OFF_BH (2 * TILE_B)
#define OFF_BL (3 * TILE_B)
#define STAGE  (4 * TILE_B)               // 65536
#define GEMM_SMEM (3 * STAGE)             // 196608

__device__ __forceinline__ void load_buf(uint32_t sdst, const char* g,
                                         int kbytes, int tid) {
    #pragma unroll
    for (int it = 0; it < 4; it++) {
        int c = tid + it * 256;           // 1024 chunks of 16B
        int r = c >> 3;
        int cb = (c & 7) << 4;
        uint32_t off = ((uint32_t)r << 7) | (uint32_t)cb;
        uint32_t sw = off ^ ((off >> 3) & 0x70);
        cp16(sdst + sw, g + (size_t)r * 2048 + kbytes + cb);
    }
}

template<bool SPLIT>
__global__ __launch_bounds__(256)
void hmma_gemm_kernel(const __nv_bfloat16* __restrict__ Ahi,
                      const __nv_bfloat16* __restrict__ Alo,
                      const __nv_bfloat16* __restrict__ Bhi,
                      const __nv_bfloat16* __restrict__ Blo,
                      const float* __restrict__ bias,
                      float* __restrict__ C,
                      __nv_bfloat16* __restrict__ Ch,
                      __nv_bfloat16* __restrict__ Cl, int N) {
    extern __shared__ char smem[];
    const uint32_t sbase = smem_u32(smem);
    const int tid  = threadIdx.x;
    const int lane = tid & 31;
    const int wid  = tid >> 5;
    const int wm   = wid >> 2;
    const int wn   = wid & 3;
    const int bx   = blockIdx.x;
    const int by   = blockIdx.y;

    const char* gAh = (const char*)Ahi + (size_t)by * GT_M * 2048;
    const char* gAl = (const char*)Alo + (size_t)by * GT_M * 2048;
    const char* gBh = (const char*)Bhi + (size_t)bx * GT_N * 2048;
    const char* gBl = (const char*)Blo + (size_t)bx * GT_N * 2048;

    // prologue: chunks 0,1 -> stages 0,1
    #pragma unroll
    for (int st = 0; st < 2; st++) {
        uint32_t sb = sbase + st * STAGE;
        int kb = st * 128;
        load_buf(sb + OFF_AH, gAh, kb, tid);
        load_buf(sb + OFF_AL, gAl, kb, tid);
        load_buf(sb + OFF_BH, gBh, kb, tid);
        load_buf(sb + OFF_BL, gBl, kb, tid);
        cp_commit();
    }

    float acc[4][4][4];
    #pragma unroll
    for (int mt = 0; mt < 4; mt++)
        #pragma unroll
        for (int nt = 0; nt < 4; nt++)
            #pragma unroll
            for (int r = 0; r < 4; r++) acc[mt][nt][r] = 0.f;

    const int arow = wm * 64 + (lane & 15);
    const int akb  = (lane >> 4) << 4;
    const int brow = wn * 32 + (lane & 7) + ((lane >> 4) << 3);
    const int bkb  = ((lane >> 3) & 1) << 4;

    for (int i = 0; i < NKCH; i++) {
        const uint32_t sb = sbase + (uint32_t)(i % 3) * STAGE;

        // chunk i fully arrived (own groups), then barrier -> visible to all,
        // and all warps are past compute of chunk i-1 (stage (i-1)%3 is free).
        if (i + 1 < NKCH) cp_wait<1>(); else cp_wait<0>();
        __syncthreads();

        // refill stage (i+2)%3 == (i-1)%3 BEFORE compute: overlap load w/ MMA
        if (i + 2 < NKCH) {
            uint32_t sb2 = sbase + (uint32_t)((i + 2) % 3) * STAGE;
            int kb = (i + 2) * 128;
            load_buf(sb2 + OFF_AH, gAh, kb, tid);
            load_buf(sb2 + OFF_AL, gAl, kb, tid);
            load_buf(sb2 + OFF_BH, gBh, kb, tid);
            load_buf(sb2 + OFF_BL, gBl, kb, tid);
            cp_commit();
        }

        #pragma unroll
        for (int ks = 0; ks < 4; ks++) {
            const int ksb = ks * 32;
            uint32_t ah[4][4], al[4][4], bh[2][4], bl[2][4];
            #pragma unroll
            for (int mt = 0; mt < 4; mt++) {
                ldsm_x4(ah[mt], sw_addr(sb + OFF_AH, arow + mt * 16, ksb + akb));
                ldsm_x4(al[mt], sw_addr(sb + OFF_AL, arow + mt * 16, ksb + akb));
            }
            #pragma unroll
            for (int p = 0; p < 2; p++) {
                ldsm_x4(bh[p], sw_addr(sb + OFF_BH, brow + p * 16, ksb + bkb));
                ldsm_x4(bl[p], sw_addr(sb + OFF_BL, brow + p * 16, ksb + bkb));
            }
            #pragma unroll
            for (int mt = 0; mt < 4; mt++)
                #pragma unroll
                for (int nt = 0; nt < 4; nt++)
                    mma16816(acc[mt][nt], ah[mt], &bh[nt >> 1][(nt & 1) * 2]);
            #pragma unroll
            for (int mt = 0; mt < 4; mt++)
                #pragma unroll
                for (int nt = 0; nt < 4; nt++)
                    mma16816(acc[mt][nt], ah[mt], &bl[nt >> 1][(nt & 1) * 2]);
            #pragma unroll
            for (int mt = 0; mt < 4; mt++)
                #pragma unroll
                for (int nt = 0; nt < 4; nt++)
                    mma16816(acc[mt][nt], al[mt], &bh[nt >> 1][(nt & 1) * 2]);
        }
    }

    // Epilogue
    const int g = lane >> 2, t = lane & 3;
    const int row_base = by * GT_M + wm * 64 + g;
    const int col_base = bx * GT_N + wn * 32 + t * 2;
    #pragma unroll
    for (int mt = 0; mt < 4; mt++) {
        const int r0 = row_base + mt * 16;
        #pragma unroll
        for (int nt = 0; nt < 4; nt++) {
            const int c = col_base + nt * 8;
            float b0 = bias[c], b1 = bias[c + 1];
            float v0 = acc[mt][nt][0] + b0, v1 = acc[mt][nt][1] + b1;
            float v2 = acc[mt][nt][2] + b0, v3 = acc[mt][nt][3] + b1;
            if (SPLIT) {
                __nv_bfloat16 h0 = __float2bfloat16(v0), h1 = __float2bfloat16(v1);
                __nv_bfloat16 h2 = __float2bfloat16(v2), h3 = __float2bfloat16(v3);
                *(__nv_bfloat162*)(Ch + (size_t)r0 * N + c)       = __nv_bfloat162(h0, h1);
                *(__nv_bfloat162*)(Ch + (size_t)(r0 + 8) * N + c) = __nv_bfloat162(h2, h3);
                *(__nv_bfloat162*)(Cl + (size_t)r0 * N + c)       = __nv_bfloat162(
                    __float2bfloat16(v0 - __bfloat162float(h0)),
                    __float2bfloat16(v1 - __bfloat162float(h1)));
                *(__nv_bfloat162*)(Cl + (size_t)(r0 + 8) * N + c) = __nv_bfloat162(
                    __float2bfloat16(v2 - __bfloat162float(h2)),
                    __float2bfloat16(v3 - __bfloat162float(h3)));
            } else {
                *(float2*)(C + (size_t)r0 * N + c)       = make_float2(v0, v1);
                *(float2*)(C + (size_t)(r0 + 8) * N + c) = make_float2(v2, v3);
            }
        }
    }
}

// ---------------------------------------------------------------------------
// mma.sync flash attention (causal, split-bf16 3-term everywhere).
// CTA: 128 q rows (8 warps x 16 rows), BK=64 kv chunks.
// 3-stage KV ring, ONE __syncthreads per chunk.
// ---------------------------------------------------------------------------
#define AT_BQ 128
#define AT_BK 64
#define A_QH  0
#define A_QL  16384
#define A_KV0 32768
#define KV_KH 0
#define KV_KL 8192
#define KV_VH 16384
#define KV_VL 24576
#define KV_STAGE 32768
#define ATTN_SMEM (A_KV0 + 3 * KV_STAGE)   // 131072

// rows=64 tile load, gmem pitch 6144 B (C3 bf16)
__device__ __forceinline__ void load_rows64(uint32_t sdst, const char* g, int tid) {
    #pragma unroll
    for (int it = 0; it < 2; it++) {
        int c = tid + it * 256;
        int r = c >> 3;
        int cb = (c & 7) << 4;
        uint32_t off = ((uint32_t)r << 7) | (uint32_t)cb;
        cp16(sdst + (off ^ ((off >> 3) & 0x70)), g + (size_t)r * 6144 + cb);
    }
}
__device__ __forceinline__ void load_rows128(uint32_t sdst, const char* g, int tid) {
    #pragma unroll
    for (int it = 0; it < 4; it++) {
        int c = tid + it * 256;
        int r = c >> 3;
        int cb = (c & 7) << 4;
        uint32_t off = ((uint32_t)r << 7) | (uint32_t)cb;
        cp16(sdst + (off ^ ((off >> 3) & 0x70)), g + (size_t)r * 6144 + cb);
    }
}
__device__ __forceinline__ void load_kv_chunk(uint32_t sb,
                                              const __nv_bfloat16* qh,
                                              const __nv_bfloat16* ql,
                                              int b, int h, int chunk, int tid) {
    const char* gK  = (const char*)(qh + (size_t)(b * TT + chunk * AT_BK) * C3 + CC + h * DD);
    const char* gKl = (const char*)(ql + (size_t)(b * TT + chunk * AT_BK) * C3 + CC + h * DD);
    load_rows64(sb + KV_KH, gK, tid);
    load_rows64(sb + KV_KL, gKl, tid);
    load_rows64(sb + KV_VH, gK + 2048, tid);     // V = +CC bf16 = +2048 B
    load_rows64(sb + KV_VL, gKl + 2048, tid);
    cp_commit();
}

__global__ __launch_bounds__(256)
void attn_mma_kernel(const __nv_bfloat16* __restrict__ qh,
                     const __nv_bfloat16* __restrict__ ql,
                     __nv_bfloat16* __restrict__ yh,
                     __nv_bfloat16* __restrict__ yl)
{
    extern __shared__ char smem[];
    const uint32_t sbase = smem_u32(smem);
    const int tid  = threadIdx.x;
    const int lane = tid & 31;
    const int w    = tid >> 5;            // warp 0..7, owns q rows w*16..+15
    const int qt = blockIdx.x, h = blockIdx.y, b = blockIdx.z;
    const int q0 = qt * AT_BQ;
    const int n  = 2 * qt + 2;            // kv chunks (n >= 2)

    const char* gQh = (const char*)(qh + (size_t)(b * TT + q0) * C3 + h * DD);
    const char* gQl = (const char*)(ql + (size_t)(b * TT + q0) * C3 + h * DD);

    // prologue: Q (group 0), KV0 (group 1), KV1 (group 2)
    load_rows128(sbase + A_QH, gQh, tid);
    load_rows128(sbase + A_QL, gQl, tid);
    cp_commit();
    load_kv_chunk(sbase + A_KV0, qh, ql, b, h, 0, tid);
    load_kv_chunk(sbase + A_KV0 + KV_STAGE, qh, ql, b, h, 1, tid);

    // Q ready (2 KV groups may still be pending)
    cp_wait<2>();
    __syncthreads();

    // Q fragments (loop-invariant): 4 ksteps x 4 regs, hi+lo
    const int arow = w * 16 + (lane & 15);
    const int akb  = (lane >> 4) << 4;
    uint32_t qfh[4][4], qfl[4][4];
    #pragma unroll
    for (int ks = 0; ks < 4; ks++) {
        ldsm_x4(qfh[ks], sw_addr(sbase + A_QH, arow, ks * 32 + akb));
        ldsm_x4(qfl[ks], sw_addr(sbase + A_QL, arow, ks * 32 + akb));
    }

    float oacc[8][4];
    #pragma unroll
    for (int nt = 0; nt < 8; nt++)
        #pragma unroll
        for (int r = 0; r < 4; r++) oacc[nt][r] = 0.f;
    float m0 = -1e30f, m1 = -1e30f, l0 = 0.f, l1 = 0.f;

    const int g_ = lane >> 2, t_ = lane & 3;
    const int brow = (lane & 7) + ((lane >> 4) << 3);
    const int bkb  = ((lane >> 3) & 1) << 4;
    const int vrow = ((lane >> 3) & 1) * 8 + (lane & 7);
    const int vcb  = (lane >> 4) << 4;

    for (int c = 0; c < n; c++) {
        // KV chunk c arrived; barrier frees stage (c-1)%3 for everyone
        if (c + 1 < n) cp_wait<1>(); else cp_wait<0>();
        __syncthreads();

        // refill BEFORE compute (stage (c+2)%3 == (c-1)%3, provably free)
        if (c + 2 < n)
            load_kv_chunk(sbase + A_KV0 + (uint32_t)((c + 2) % 3) * KV_STAGE,
                          qh, ql, b, h, c + 2, tid);

        const uint32_t sb = sbase + A_KV0 + (uint32_t)(c % 3) * KV_STAGE;
        const int kv0 = c * AT_BK;
        const bool active = (kv0 <= q0 + w * 16 + 15);
        const bool need_mask = (kv0 + 63 > q0 + w * 16);

        if (active) {
            // ---- S = Q K^T (3-term) ----
            float sacc[8][4];
            #pragma unroll
            for (int nt = 0; nt < 8; nt++)
                #pragma unroll
                for (int r = 0; r < 4; r++) sacc[nt][r] = 0.f;

            #pragma unroll
            for (int ks = 0; ks < 4; ks++) {
                const int ksb = ks * 32;
                uint32_t kh4[4][4], kl4[4][4];
                #pragma unroll
                for (int p = 0; p < 4; p++) {
                    ldsm_x4(kh4[p], sw_addr(sb + KV_KH, p * 16 + brow, ksb + bkb));
                    ldsm_x4(kl4[p], sw_addr(sb + KV_KL, p * 16 + brow, ksb + bkb));
                }
                #pragma unroll
                for (int p = 0; p < 4; p++) {
                    mma16816(sacc[2*p],   qfh[ks], &kh4[p][0]);
                    mma16816(sacc[2*p+1], qfh[ks], &kh4[p][2]);
                }
                #pragma unroll
                for (int p = 0; p < 4; p++) {
                    mma16816(sacc[2*p],   qfh[ks], &kl4[p][0]);
                    mma16816(sacc[2*p+1], qfh[ks], &kl4[p][2]);
                }
                #pragma unroll
                for (int p = 0; p < 4; p++) {
                    mma16816(sacc[2*p],   qfl[ks], &kh4[p][0]);
                    mma16816(sacc[2*p+1], qfl[ks], &kh4[p][2]);
                }
            }

            // scale + causal mask
            const int row0 = q0 + w * 16 + g_;
            #pragma unroll
            for (int nt = 0; nt < 8; nt++)
                #pragma unroll
                for (int r = 0; r < 4; r++) sacc[nt][r] *= 0.125f;
            if (need_mask) {
                #pragma unroll
                for (int nt = 0; nt < 8; nt++) {
                    int col = kv0 + nt * 8 + 2 * t_;
                    if (col     > row0)     sacc[nt][0] = -1e30f;
                    if (col + 1 > row0)     sacc[nt][1] = -1e30f;
                    if (col     > row0 + 8) sacc[nt][2] = -1e30f;
                    if (col + 1 > row0 + 8) sacc[nt][3] = -1e30f;
                }
            }

            // ---- online softmax (rows g_, g_+8) ----
            float mx0 = -1e30f, mx1 = -1e30f;
            #pragma unroll
            for (int nt = 0; nt < 8; nt++) {
                mx0 = fmaxf(mx0, fmaxf(sacc[nt][0], sacc[nt][1]));
                mx1 = fmaxf(mx1, fmaxf(sacc[nt][2], sacc[nt][3]));
            }
            mx0 = fmaxf(mx0, __shfl_xor_sync(0xffffffffu, mx0, 1));
            mx0 = fmaxf(mx0, __shfl_xor_sync(0xffffffffu, mx0, 2));
            mx1 = fmaxf(mx1, __shfl_xor_sync(0xffffffffu, mx1, 1));
            mx1 = fmaxf(mx1, __shfl_xor_sync(0xffffffffu, mx1, 2));
            mx0 = fmaxf(mx0, m0);
            mx1 = fmaxf(mx1, m1);

            float rs0 = 0.f, rs1 = 0.f;
            #pragma unroll
            for (int nt = 0; nt < 8; nt++) {
                sacc[nt][0] = __expf(sacc[nt][0] - mx0);
                sacc[nt][1] = __expf(sacc[nt][1] - mx0);
                sacc[nt][2] = __expf(sacc[nt][2] - mx1);
                sacc[nt][3] = __expf(sacc[nt][3] - mx1);
                rs0 += sacc[nt][0] + sacc[nt][1];
                rs1 += sacc[nt][2] + sacc[nt][3];
            }
            rs0 += __shfl_xor_sync(0xffffffffu, rs0, 1);
            rs0 += __shfl_xor_sync(0xffffffffu, rs0, 2);
            rs1 += __shfl_xor_sync(0xffffffffu, rs1, 1);
            rs1 += __shfl_xor_sync(0xffffffffu, rs1, 2);

            float a0 = __expf(m0 - mx0);
            float a1 = __expf(m1 - mx1);
            m0 = mx0; m1 = mx1;
            l0 = l0 * a0 + rs0;
            l1 = l1 * a1 + rs1;
            #pragma unroll
            for (int nt = 0; nt < 8; nt++) {
                oacc[nt][0] *= a0; oacc[nt][1] *= a0;
                oacc[nt][2] *= a1; oacc[nt][3] *= a1;
            }

            // ---- pack P hi/lo (accumulator -> A fragment register reuse) ----
            uint32_t ph[8][2], pl[8][2];
            #pragma unroll
            for (int nt = 0; nt < 8; nt++) {
                float p0 = sacc[nt][0], p1 = sacc[nt][1];
                float p2 = sacc[nt][2], p3 = sacc[nt][3];
                __nv_bfloat16 h0 = __float2bfloat16(p0), h1 = __float2bfloat16(p1);
                __nv_bfloat16 h2 = __float2bfloat16(p2), h3 = __float2bfloat16(p3);
                ph[nt][0] = pack_bf16(__bfloat162float(h0), __bfloat162float(h1));
                ph[nt][1] = pack_bf16(__bfloat162float(h2), __bfloat162float(h3));
                pl[nt][0] = pack_bf16(p0 - __bfloat162float(h0), p1 - __bfloat162float(h1));
                pl[nt][1] = pack_bf16(p2 - __bfloat162float(h2), p3 - __bfloat162float(h3));
            }

            // ---- O += P V (3-term), V via ldmatrix.trans ----
            #pragma unroll
            for (int kk = 0; kk < 4; kk++) {
                uint32_t aPh[4] = {ph[2*kk][0], ph[2*kk][1], ph[2*kk+1][0], ph[2*kk+1][1]};
                uint32_t aPl[4] = {pl[2*kk][0], pl[2*kk][1], pl[2*kk+1][0], pl[2*kk+1][1]};
                uint32_t vh4[4][4], vl4[4][4];
                #pragma unroll
                for (int dd = 0; dd < 4; dd++) {
                    ldsm_x4_t(vh4[dd], sw_addr(sb + KV_VH, kk * 16 + vrow, dd * 32 + vcb));
                    ldsm_x4_t(vl4[dd], sw_addr(sb + KV_VL, kk * 16 + vrow, dd * 32 + vcb));
                }
                #pragma unroll
                for (int dd = 0; dd < 4; dd++) {
                    mma16816(oacc[2*dd],   aPh, &vh4[dd][0]);
                    mma16816(oacc[2*dd+1], aPh, &vh4[dd][2]);
                }
                #pragma unroll
                for (int dd = 0; dd < 4; dd++) {
                    mma16816(oacc[2*dd],   aPh, &vl4[dd][0]);
                    mma16816(oacc[2*dd+1], aPh, &vl4[dd][2]);
                }
                #pragma unroll
                for (int dd = 0; dd < 4; dd++) {
                    mma16816(oacc[2*dd],   aPl, &vh4[dd][0]);
                    mma16816(oacc[2*dd+1], aPl, &vh4[dd][2]);
                }
            }
        }
    }

    // ---- epilogue: normalize, split hi/lo, store y ----
    const float inv0 = 1.f / l0, inv1 = 1.f / l1;
    const size_t row0 = (size_t)(b * TT + q0 + w * 16 + g_);
    const int col0 = h * DD + 2 * t_;
    #pragma unroll
    for (int nt = 0; nt < 8; nt++) {
        float v0 = oacc[nt][0] * inv0, v1 = oacc[nt][1] * inv0;
        float v2 = oacc[nt][2] * inv1, v3 = oacc[nt][3] * inv1;
        __nv_bfloat16 h0 = __float2bfloat16(v0), h1 = __float2bfloat16(v1);
        __nv_bfloat16 h2 = __float2bfloat16(v2), h3 = __float2bfloat16(v3);
        size_t i0 = row0 * CC + col0 + nt * 8;
        size_t i1 = (row0 + 8) * CC + col0 + nt * 8;
        *(__nv_bfloat162*)(yh + i0) = __nv_bfloat162(h0, h1);
        *(__nv_bfloat162*)(yh + i1) = __nv_bfloat162(h2, h3);
        *(__nv_bfloat162*)(yl + i0) = __nv_bfloat162(
            __float2bfloat16(v0 - __bfloat162float(h0)),
            __float2bfloat16(v1 - __bfloat162float(h1)));
        *(__nv_bfloat162*)(yl + i1) = __nv_bfloat162(
            __float2bfloat16(v2 - __bfloat162float(h2)),
            __float2bfloat16(v3 - __bfloat162float(h3)));
    }
}

// ---------------------------------------------------------------------------
extern "C" void kernel_launch(void* const* d_in, const int* in_sizes, int n_in,
                              void* d_out, int out_size)
{
    const float* x      = (const float*)d_in[0];
    const float* W_attn = (const float*)d_in[1];
    const float* b_attn = (const float*)d_in[2];
    const float* W_proj = (const float*)d_in[3];
    const float* b_proj = (const float*)d_in[4];
    float* out = (float*)d_out;

    __nv_bfloat16 *qkvh, *qkvl, *xhi, *xlo, *yhi, *ylo, *wahi, *walo, *wphi, *wplo;
    cudaGetSymbolAddress((void**)&qkvh, g_qkvh);
    cudaGetSymbolAddress((void**)&qkvl, g_qkvl);
    cudaGetSymbolAddress((void**)&xhi,  g_xhi);
    cudaGetSymbolAddress((void**)&xlo,  g_xlo);
    cudaGetSymbolAddress((void**)&yhi,  g_yhi);
    cudaGetSymbolAddress((void**)&ylo,  g_ylo);
    cudaGetSymbolAddress((void**)&wahi, g_Wahi);
    cudaGetSymbolAddress((void**)&walo, g_Walo);
    cudaGetSymbolAddress((void**)&wphi, g_Wphi);
    cudaGetSymbolAddress((void**)&wplo, g_Wplo);

    static bool attr_done = false;
    if (!attr_done) {
        cudaFuncSetAttribute(hmma_gemm_kernel<true>,
                             cudaFuncAttributeMaxDynamicSharedMemorySize, GEMM_SMEM);
        cudaFuncSetAttribute(hmma_gemm_kernel<false>,
                             cudaFuncAttributeMaxDynamicSharedMemorySize, GEMM_SMEM);
        cudaFuncSetAttribute(attn_mma_kernel,
                             cudaFuncAttributeMaxDynamicSharedMemorySize, ATTN_SMEM);
        attr_done = true;
    }

    // 1) split x -> bf16 hi/lo
    {
        int n4 = BT * CC / 4;
        split_kernel<<<(n4 + 255) / 256, 256>>>(x, xhi, xlo, n4);
    }
    // 2) transpose+split weights
    transpose_split_kernel<<<dim3(C3 / 32, CC / 32), dim3(32, 8)>>>(W_attn, wahi, walo, CC, C3);
    transpose_split_kernel<<<dim3(CC / 32, CC / 32), dim3(32, 8)>>>(W_proj, wphi, wplo, CC, CC);

    // 3) QKV GEMM -> qkv hi/lo bf16 (fused split epilogue)
    hmma_gemm_kernel<true><<<dim3(C3 / GT_N, BT / GT_M), 256, GEMM_SMEM>>>(
        xhi, xlo, wahi, walo, b_attn, nullptr, qkvh, qkvl, C3);

    // 4) tensor-core flash attention -> y hi/lo bf16
    attn_mma_kernel<<<dim3(TT / AT_BQ, HH, BB), 256, ATTN_SMEM>>>(qkvh, qkvl, yhi, ylo);

    // 5) proj GEMM -> out fp32
    hmma_gemm_kernel<false><<<dim3(CC / GT_N, BT / GT_M), 256, GEMM_SMEM>>>(
        yhi, ylo, wphi, wplo, b_proj, out, nullptr, nullptr, CC);
}

// round 8
// speedup vs baseline: 4.1543x; 1.3187x over previous
#include <cuda_runtime.h>
#include <cuda_fp16.h>
#include <cstdint>

// Problem constants: B=4, T=2048, C=1024, H=16, D=64
#define BB   4
#define TT   2048
#define CC   1024
#define C3   3072
#define HH   16
#define DD   64
#define BT   (BB * TT)          // 8192 rows
#define KK   1024               // GEMM K (both GEMMs)

// ---------------------------------------------------------------------------
// Scratch (__device__ globals; no allocation allowed)
// fp16 2-term scheme: activations split hi/lo, weights/K/V single fp16.
// ---------------------------------------------------------------------------
__device__ __align__(1024) __half  g_qkvh[(size_t)BT * C3];   // qkv hi
__device__ __align__(1024) __half  g_qkvl[(size_t)BT * C3];   // qkv lo (Q part used)
__device__ __align__(1024) __half  g_xhi[(size_t)BT * CC];
__device__ __align__(1024) __half  g_xlo[(size_t)BT * CC];
__device__ __align__(1024) __half  g_yhi[(size_t)BT * CC];
__device__ __align__(1024) __half  g_ylo[(size_t)BT * CC];
__device__ __align__(1024) __half  g_Wah[(size_t)C3 * CC];    // W_attn^T [N,K]
__device__ __align__(1024) __half  g_Wph[(size_t)CC * CC];    // W_proj^T [N,K]

// ---------------------------------------------------------------------------
// PTX helpers — baseline PTX only (compute_103 has no tcgen05/TMA-tensor!)
// ---------------------------------------------------------------------------
__device__ __forceinline__ uint32_t smem_u32(const void* p) {
    uint32_t a;
    asm("{ .reg .u64 t; cvta.to.shared.u64 t, %1; cvt.u32.u64 %0, t; }" : "=r"(a) : "l"(p));
    return a;
}
__device__ __forceinline__ void cp16(uint32_t saddr, const void* g) {
    asm volatile("cp.async.cg.shared.global [%0], [%1], 16;\n" :: "r"(saddr), "l"(g));
}
__device__ __forceinline__ void cp_commit() {
    asm volatile("cp.async.commit_group;\n" ::: "memory");
}
template<int N> __device__ __forceinline__ void cp_wait() {
    asm volatile("cp.async.wait_group %0;\n" :: "n"(N) : "memory");
}
__device__ __forceinline__ void ldsm_x4(uint32_t* r, uint32_t addr) {
    asm volatile("ldmatrix.sync.aligned.m8n8.x4.shared.b16 {%0,%1,%2,%3}, [%4];"
        : "=r"(r[0]), "=r"(r[1]), "=r"(r[2]), "=r"(r[3]) : "r"(addr));
}
__device__ __forceinline__ void ldsm_x4_t(uint32_t* r, uint32_t addr) {
    asm volatile("ldmatrix.sync.aligned.m8n8.x4.trans.shared.b16 {%0,%1,%2,%3}, [%4];"
        : "=r"(r[0]), "=r"(r[1]), "=r"(r[2]), "=r"(r[3]) : "r"(addr));
}
__device__ __forceinline__ void mma16816(float* d, const uint32_t* a, const uint32_t* b) {
    asm volatile("mma.sync.aligned.m16n8k16.row.col.f32.f16.f16.f32 "
        "{%0,%1,%2,%3}, {%4,%5,%6,%7}, {%8,%9}, {%0,%1,%2,%3};"
        : "+f"(d[0]), "+f"(d[1]), "+f"(d[2]), "+f"(d[3])
        : "r"(a[0]), "r"(a[1]), "r"(a[2]), "r"(a[3]), "r"(b[0]), "r"(b[1]));
}
// swizzled address inside a [rows][128B] tile (SW128: 16B chunks permuted)
__device__ __forceinline__ uint32_t sw_addr(uint32_t base, int row, int kb) {
    uint32_t off = ((uint32_t)row << 7) + (uint32_t)kb;
    return base + (off ^ ((off >> 3) & 0x70));
}
__device__ __forceinline__ uint32_t pack_f16(float a, float b) {
    __half2 h = __floats2half2_rn(a, b);
    return *(uint32_t*)&h;
}

// ---------------------------------------------------------------------------
// Split fp32 -> fp16 hi/lo (activations)
// ---------------------------------------------------------------------------
__global__ void split_kernel(const float* __restrict__ src,
                             __half* __restrict__ hi,
                             __half* __restrict__ lo, int n4) {
    int i = blockIdx.x * blockDim.x + threadIdx.x;
    if (i >= n4) return;
    float4 v = ((const float4*)src)[i];
    __half h0 = __float2half_rn(v.x), h1 = __float2half_rn(v.y);
    __half h2 = __float2half_rn(v.z), h3 = __float2half_rn(v.w);
    ((__half2*)hi)[2*i]   = __half2(h0, h1);
    ((__half2*)hi)[2*i+1] = __half2(h2, h3);
    ((__half2*)lo)[2*i]   = __half2(__float2half_rn(v.x - __half2float(h0)),
                                    __float2half_rn(v.y - __half2float(h1)));
    ((__half2*)lo)[2*i+1] = __half2(__float2half_rn(v.z - __half2float(h2)),
                                    __float2half_rn(v.w - __half2float(h3)));
}

// Transpose W[K,N] -> Wt[N,K], fp16 (weights stay single precision term)
__global__ void transpose_h_kernel(const float* __restrict__ W,
                                   __half* __restrict__ Th, int K, int N) {
    __shared__ float t[32][33];
    int tx = threadIdx.x, ty = threadIdx.y;
    int n0 = blockIdx.x * 32, k0 = blockIdx.y * 32;
    #pragma unroll
    for (int j = 0; j < 4; j++)
        t[ty + 8*j][tx] = W[(size_t)(k0 + ty + 8*j) * N + n0 + tx];
    __syncthreads();
    #pragma unroll
    for (int j = 0; j < 4; j++)
        Th[(size_t)(n0 + ty + 8*j) * K + k0 + tx] = __float2half_rn(t[tx][ty + 8*j]);
}

// ---------------------------------------------------------------------------
// mma.sync fp16 2-term GEMM: C = (Ahi+Alo)·Bh^T + bias
// A: [M,K] fp16 hi/lo, B: [N,K] fp16, C fp32 or fp16 hi/lo.
// CTA 128x128, BK=64 (128B rows, SW128), 16 warps (4m x 4n, 32x32 each).
// 3-stage cp.async ring, ONE __syncthreads per chunk. 512 threads.
// ---------------------------------------------------------------------------
#define GT_M   128
#define GT_N   128
#define GT_K   64
#define NKCH   (KK / GT_K)                // 16
#define TILE_B (128 * 128)                // 16384 bytes per [128][64 fp16] tile
#define OFF_AH 0
#define OFF_AL (TILE_B)
#define OFF_BH (2 * TILE_B)
#define STAGE  (3 * TILE_B)               // 49152
#define GEMM_SMEM (3 * STAGE)             // 147456

// load a [128 rows][64 fp16] tile; gmem pitch 2048 B (K=1024 fp16). 512 thr.
__device__ __forceinline__ void load_buf(uint32_t sdst, const char* g,
                                         int kbytes, int tid) {
    #pragma unroll
    for (int it = 0; it < 2; it++) {
        int c = tid + it * 512;           // 1024 chunks of 16B
        int r = c >> 3;
        int cb = (c & 7) << 4;
        uint32_t off = ((uint32_t)r << 7) | (uint32_t)cb;
        uint32_t sw = off ^ ((off >> 3) & 0x70);
        cp16(sdst + sw, g + (size_t)r * 2048 + kbytes + cb);
    }
}

template<bool SPLIT>
__global__ __launch_bounds__(512)
void hmma_gemm_kernel(const __half* __restrict__ Ahi,
                      const __half* __restrict__ Alo,
                      const __half* __restrict__ Bh,
                      const float* __restrict__ bias,
                      float* __restrict__ C,
                      __half* __restrict__ Ch,
                      __half* __restrict__ Cl, int N) {
    extern __shared__ char smem[];
    const uint32_t sbase = smem_u32(smem);
    const int tid  = threadIdx.x;
    const int lane = tid & 31;
    const int wid  = tid >> 5;            // 0..15
    const int wm   = wid >> 2;            // 0..3 -> 32 rows
    const int wn   = wid & 3;             // 0..3 -> 32 cols
    const int bx   = blockIdx.x;
    const int by   = blockIdx.y;

    const char* gAh = (const char*)Ahi + (size_t)by * GT_M * 2048;
    const char* gAl = (const char*)Alo + (size_t)by * GT_M * 2048;
    const char* gBh = (const char*)Bh  + (size_t)bx * GT_N * 2048;

    // prologue: chunks 0,1 -> stages 0,1
    #pragma unroll
    for (int st = 0; st < 2; st++) {
        uint32_t sb = sbase + st * STAGE;
        int kb = st * 128;
        load_buf(sb + OFF_AH, gAh, kb, tid);
        load_buf(sb + OFF_AL, gAl, kb, tid);
        load_buf(sb + OFF_BH, gBh, kb, tid);
        cp_commit();
    }

    float acc[2][4][4];
    #pragma unroll
    for (int mt = 0; mt < 2; mt++)
        #pragma unroll
        for (int nt = 0; nt < 4; nt++)
            #pragma unroll
            for (int r = 0; r < 4; r++) acc[mt][nt][r] = 0.f;

    const int arow = wm * 32 + (lane & 15);
    const int akb  = (lane >> 4) << 4;
    const int brow = wn * 32 + (lane & 7) + ((lane >> 4) << 3);
    const int bkb  = ((lane >> 3) & 1) << 4;

    for (int i = 0; i < NKCH; i++) {
        const uint32_t sb = sbase + (uint32_t)(i % 3) * STAGE;

        if (i + 1 < NKCH) cp_wait<1>(); else cp_wait<0>();
        __syncthreads();

        // refill stage (i+2)%3 == (i-1)%3 BEFORE compute
        if (i + 2 < NKCH) {
            uint32_t sb2 = sbase + (uint32_t)((i + 2) % 3) * STAGE;
            int kb = (i + 2) * 128;
            load_buf(sb2 + OFF_AH, gAh, kb, tid);
            load_buf(sb2 + OFF_AL, gAl, kb, tid);
            load_buf(sb2 + OFF_BH, gBh, kb, tid);
            cp_commit();
        }

        #pragma unroll
        for (int ks = 0; ks < 4; ks++) {
            const int ksb = ks * 32;
            uint32_t ah[2][4], al[2][4], bh[2][4];
            #pragma unroll
            for (int mt = 0; mt < 2; mt++) {
                ldsm_x4(ah[mt], sw_addr(sb + OFF_AH, arow + mt * 16, ksb + akb));
                ldsm_x4(al[mt], sw_addr(sb + OFF_AL, arow + mt * 16, ksb + akb));
            }
            #pragma unroll
            for (int p = 0; p < 2; p++)
                ldsm_x4(bh[p], sw_addr(sb + OFF_BH, brow + p * 16, ksb + bkb));
            #pragma unroll
            for (int mt = 0; mt < 2; mt++)
                #pragma unroll
                for (int nt = 0; nt < 4; nt++)
                    mma16816(acc[mt][nt], ah[mt], &bh[nt >> 1][(nt & 1) * 2]);
            #pragma unroll
            for (int mt = 0; mt < 2; mt++)
                #pragma unroll
                for (int nt = 0; nt < 4; nt++)
                    mma16816(acc[mt][nt], al[mt], &bh[nt >> 1][(nt & 1) * 2]);
        }
    }

    // Epilogue
    const int g = lane >> 2, t = lane & 3;
    const int row_base = by * GT_M + wm * 32 + g;
    const int col_base = bx * GT_N + wn * 32 + t * 2;
    #pragma unroll
    for (int mt = 0; mt < 2; mt++) {
        const int r0 = row_base + mt * 16;
        #pragma unroll
        for (int nt = 0; nt < 4; nt++) {
            const int c = col_base + nt * 8;
            float b0 = bias[c], b1 = bias[c + 1];
            float v0 = acc[mt][nt][0] + b0, v1 = acc[mt][nt][1] + b1;
            float v2 = acc[mt][nt][2] + b0, v3 = acc[mt][nt][3] + b1;
            if (SPLIT) {
                __half h0 = __float2half_rn(v0), h1 = __float2half_rn(v1);
                __half h2 = __float2half_rn(v2), h3 = __float2half_rn(v3);
                *(__half2*)(Ch + (size_t)r0 * N + c)       = __half2(h0, h1);
                *(__half2*)(Ch + (size_t)(r0 + 8) * N + c) = __half2(h2, h3);
                *(__half2*)(Cl + (size_t)r0 * N + c)       = __half2(
                    __float2half_rn(v0 - __half2float(h0)),
                    __float2half_rn(v1 - __half2float(h1)));
                *(__half2*)(Cl + (size_t)(r0 + 8) * N + c) = __half2(
                    __float2half_rn(v2 - __half2float(h2)),
                    __float2half_rn(v3 - __half2float(h3)));
            } else {
                *(float2*)(C + (size_t)r0 * N + c)       = make_float2(v0, v1);
                *(float2*)(C + (size_t)(r0 + 8) * N + c) = make_float2(v2, v3);
            }
        }
    }
}

// ---------------------------------------------------------------------------
// mma.sync flash attention (causal, fp16 2-term: Q/P split, K/V single).
// CTA: 128 q rows (8 warps x 16 rows), BK=64 kv chunks.
// 3-stage KV ring (kh+vh = 16KB/stage), ONE __syncthreads per chunk.
// ---------------------------------------------------------------------------
#define AT_BQ 128
#define AT_BK 64
#define A_QH  0
#define A_QL  16384
#define A_KV0 32768
#define KV_KH 0
#define KV_VH 8192
#define KV_STAGE 16384
#define ATTN_SMEM (A_KV0 + 3 * KV_STAGE)   // 81920

// rows=64 tile load, gmem pitch 6144 B (C3 fp16)
__device__ __forceinline__ void load_rows64(uint32_t sdst, const char* g, int tid) {
    #pragma unroll
    for (int it = 0; it < 2; it++) {
        int c = tid + it * 256;
        int r = c >> 3;
        int cb = (c & 7) << 4;
        uint32_t off = ((uint32_t)r << 7) | (uint32_t)cb;
        cp16(sdst + (off ^ ((off >> 3) & 0x70)), g + (size_t)r * 6144 + cb);
    }
}
__device__ __forceinline__ void load_rows128(uint32_t sdst, const char* g, int tid) {
    #pragma unroll
    for (int it = 0; it < 4; it++) {
        int c = tid + it * 256;
        int r = c >> 3;
        int cb = (c & 7) << 4;
        uint32_t off = ((uint32_t)r << 7) | (uint32_t)cb;
        cp16(sdst + (off ^ ((off >> 3) & 0x70)), g + (size_t)r * 6144 + cb);
    }
}
__device__ __forceinline__ void load_kv_chunk(uint32_t sb, const __half* qh,
                                              int b, int h, int chunk, int tid) {
    const char* gK = (const char*)(qh + (size_t)(b * TT + chunk * AT_BK) * C3 + CC + h * DD);
    load_rows64(sb + KV_KH, gK, tid);
    load_rows64(sb + KV_VH, gK + 2048, tid);     // V = +CC fp16 = +2048 B
    cp_commit();
}

__global__ __launch_bounds__(256)
void attn_mma_kernel(const __half* __restrict__ qh,
                     const __half* __restrict__ ql,
                     __half* __restrict__ yh,
                     __half* __restrict__ yl)
{
    extern __shared__ char smem[];
    const uint32_t sbase = smem_u32(smem);
    const int tid  = threadIdx.x;
    const int lane = tid & 31;
    const int w    = tid >> 5;            // warp 0..7, owns q rows w*16..+15
    const int qt = blockIdx.x, h = blockIdx.y, b = blockIdx.z;
    const int q0 = qt * AT_BQ;
    const int n  = 2 * qt + 2;            // kv chunks (n >= 2)

    const char* gQh = (const char*)(qh + (size_t)(b * TT + q0) * C3 + h * DD);
    const char* gQl = (const char*)(ql + (size_t)(b * TT + q0) * C3 + h * DD);

    // prologue: Q (group 0), KV0 (group 1), KV1 (group 2)
    load_rows128(sbase + A_QH, gQh, tid);
    load_rows128(sbase + A_QL, gQl, tid);
    cp_commit();
    load_kv_chunk(sbase + A_KV0, qh, b, h, 0, tid);
    load_kv_chunk(sbase + A_KV0 + KV_STAGE, qh, b, h, 1, tid);

    cp_wait<2>();
    __syncthreads();

    // Q fragments (loop-invariant): 4 ksteps x 4 regs, hi+lo
    const int arow = w * 16 + (lane & 15);
    const int akb  = (lane >> 4) << 4;
    uint32_t qfh[4][4], qfl[4][4];
    #pragma unroll
    for (int ks = 0; ks < 4; ks++) {
        ldsm_x4(qfh[ks], sw_addr(sbase + A_QH, arow, ks * 32 + akb));
        ldsm_x4(qfl[ks], sw_addr(sbase + A_QL, arow, ks * 32 + akb));
    }

    float oacc[8][4];
    #pragma unroll
    for (int nt = 0; nt < 8; nt++)
        #pragma unroll
        for (int r = 0; r < 4; r++) oacc[nt][r] = 0.f;
    float m0 = -1e30f, m1 = -1e30f, l0 = 0.f, l1 = 0.f;

    const int g_ = lane >> 2, t_ = lane & 3;
    const int brow = (lane & 7) + ((lane >> 4) << 3);
    const int bkb  = ((lane >> 3) & 1) << 4;
    const int vrow = ((lane >> 3) & 1) * 8 + (lane & 7);
    const int vcb  = (lane >> 4) << 4;

    for (int c = 0; c < n; c++) {
        if (c + 1 < n) cp_wait<1>(); else cp_wait<0>();
        __syncthreads();

        if (c + 2 < n)
            load_kv_chunk(sbase + A_KV0 + (uint32_t)((c + 2) % 3) * KV_STAGE,
                          qh, b, h, c + 2, tid);

        const uint32_t sb = sbase + A_KV0 + (uint32_t)(c % 3) * KV_STAGE;
        const int kv0 = c * AT_BK;
        const bool active = (kv0 <= q0 + w * 16 + 15);
        const bool need_mask = (kv0 + 63 > q0 + w * 16);

        if (active) {
            // ---- S = Q K^T (2-term: qh·kh + ql·kh) ----
            float sacc[8][4];
            #pragma unroll
            for (int nt = 0; nt < 8; nt++)
                #pragma unroll
                for (int r = 0; r < 4; r++) sacc[nt][r] = 0.f;

            #pragma unroll
            for (int ks = 0; ks < 4; ks++) {
                const int ksb = ks * 32;
                uint32_t kh4[4][4];
                #pragma unroll
                for (int p = 0; p < 4; p++)
                    ldsm_x4(kh4[p], sw_addr(sb + KV_KH, p * 16 + brow, ksb + bkb));
                #pragma unroll
                for (int p = 0; p < 4; p++) {
                    mma16816(sacc[2*p],   qfh[ks], &kh4[p][0]);
                    mma16816(sacc[2*p+1], qfh[ks], &kh4[p][2]);
                }
                #pragma unroll
                for (int p = 0; p < 4; p++) {
                    mma16816(sacc[2*p],   qfl[ks], &kh4[p][0]);
                    mma16816(sacc[2*p+1], qfl[ks], &kh4[p][2]);
                }
            }

            // scale + causal mask
            const int row0 = q0 + w * 16 + g_;
            #pragma unroll
            for (int nt = 0; nt < 8; nt++)
                #pragma unroll
                for (int r = 0; r < 4; r++) sacc[nt][r] *= 0.125f;
            if (need_mask) {
                #pragma unroll
                for (int nt = 0; nt < 8; nt++) {
                    int col = kv0 + nt * 8 + 2 * t_;
                    if (col     > row0)     sacc[nt][0] = -1e30f;
                    if (col + 1 > row0)     sacc[nt][1] = -1e30f;
                    if (col     > row0 + 8) sacc[nt][2] = -1e30f;
                    if (col + 1 > row0 + 8) sacc[nt][3] = -1e30f;
                }
            }

            // ---- online softmax (rows g_, g_+8) ----
            float mx0 = -1e30f, mx1 = -1e30f;
            #pragma unroll
            for (int nt = 0; nt < 8; nt++) {
                mx0 = fmaxf(mx0, fmaxf(sacc[nt][0], sacc[nt][1]));
                mx1 = fmaxf(mx1, fmaxf(sacc[nt][2], sacc[nt][3]));
            }
            mx0 = fmaxf(mx0, __shfl_xor_sync(0xffffffffu, mx0, 1));
            mx0 = fmaxf(mx0, __shfl_xor_sync(0xffffffffu, mx0, 2));
            mx1 = fmaxf(mx1, __shfl_xor_sync(0xffffffffu, mx1, 1));
            mx1 = fmaxf(mx1, __shfl_xor_sync(0xffffffffu, mx1, 2));
            mx0 = fmaxf(mx0, m0);
            mx1 = fmaxf(mx1, m1);

            float rs0 = 0.f, rs1 = 0.f;
            #pragma unroll
            for (int nt = 0; nt < 8; nt++) {
                sacc[nt][0] = __expf(sacc[nt][0] - mx0);
                sacc[nt][1] = __expf(sacc[nt][1] - mx0);
                sacc[nt][2] = __expf(sacc[nt][2] - mx1);
                sacc[nt][3] = __expf(sacc[nt][3] - mx1);
                rs0 += sacc[nt][0] + sacc[nt][1];
                rs1 += sacc[nt][2] + sacc[nt][3];
            }
            rs0 += __shfl_xor_sync(0xffffffffu, rs0, 1);
            rs0 += __shfl_xor_sync(0xffffffffu, rs0, 2);
            rs1 += __shfl_xor_sync(0xffffffffu, rs1, 1);
            rs1 += __shfl_xor_sync(0xffffffffu, rs1, 2);

            float a0 = __expf(m0 - mx0);
            float a1 = __expf(m1 - mx1);
            m0 = mx0; m1 = mx1;
            l0 = l0 * a0 + rs0;
            l1 = l1 * a1 + rs1;
            #pragma unroll
            for (int nt = 0; nt < 8; nt++) {
                oacc[nt][0] *= a0; oacc[nt][1] *= a0;
                oacc[nt][2] *= a1; oacc[nt][3] *= a1;
            }

            // ---- pack P hi/lo fp16 (accumulator -> A fragment reuse) ----
            uint32_t ph[8][2], pl[8][2];
            #pragma unroll
            for (int nt = 0; nt < 8; nt++) {
                float p0 = sacc[nt][0], p1 = sacc[nt][1];
                float p2 = sacc[nt][2], p3 = sacc[nt][3];
                __half h0 = __float2half_rn(p0), h1 = __float2half_rn(p1);
                __half h2 = __float2half_rn(p2), h3 = __float2half_rn(p3);
                ph[nt][0] = pack_f16(__half2float(h0), __half2float(h1));
                ph[nt][1] = pack_f16(__half2float(h2), __half2float(h3));
                pl[nt][0] = pack_f16(p0 - __half2float(h0), p1 - __half2float(h1));
                pl[nt][1] = pack_f16(p2 - __half2float(h2), p3 - __half2float(h3));
            }

            // ---- O += P V (2-term: Ph·vh + Pl·vh), V via ldmatrix.trans ----
            #pragma unroll
            for (int kk = 0; kk < 4; kk++) {
                uint32_t aPh[4] = {ph[2*kk][0], ph[2*kk][1], ph[2*kk+1][0], ph[2*kk+1][1]};
                uint32_t aPl[4] = {pl[2*kk][0], pl[2*kk][1], pl[2*kk+1][0], pl[2*kk+1][1]};
                uint32_t vh4[4][4];
                #pragma unroll
                for (int dd = 0; dd < 4; dd++)
                    ldsm_x4_t(vh4[dd], sw_addr(sb + KV_VH, kk * 16 + vrow, dd * 32 + vcb));
                #pragma unroll
                for (int dd = 0; dd < 4; dd++) {
                    mma16816(oacc[2*dd],   aPh, &vh4[dd][0]);
                    mma16816(oacc[2*dd+1], aPh, &vh4[dd][2]);
                }
                #pragma unroll
                for (int dd = 0; dd < 4; dd++) {
                    mma16816(oacc[2*dd],   aPl, &vh4[dd][0]);
                    mma16816(oacc[2*dd+1], aPl, &vh4[dd][2]);
                }
            }
        }
    }

    // ---- epilogue: normalize, split hi/lo, store y ----
    const float inv0 = 1.f / l0, inv1 = 1.f / l1;
    const size_t row0 = (size_t)(b * TT + q0 + w * 16 + g_);
    const int col0 = h * DD + 2 * t_;
    #pragma unroll
    for (int nt = 0; nt < 8; nt++) {
        float v0 = oacc[nt][0] * inv0, v1 = oacc[nt][1] * inv0;
        float v2 = oacc[nt][2] * inv1, v3 = oacc[nt][3] * inv1;
        __half h0 = __float2half_rn(v0), h1 = __float2half_rn(v1);
        __half h2 = __float2half_rn(v2), h3 = __float2half_rn(v3);
        size_t i0 = row0 * CC + col0 + nt * 8;
        size_t i1 = (row0 + 8) * CC + col0 + nt * 8;
        *(__half2*)(yh + i0) = __half2(h0, h1);
        *(__half2*)(yh + i1) = __half2(h2, h3);
        *(__half2*)(yl + i0) = __half2(__float2half_rn(v0 - __half2float(h0)),
                                       __float2half_rn(v1 - __half2float(h1)));
        *(__half2*)(yl + i1) = __half2(__float2half_rn(v2 - __half2float(h2)),
                                       __float2half_rn(v3 - __half2float(h3)));
    }
}

// ---------------------------------------------------------------------------
extern "C" void kernel_launch(void* const* d_in, const int* in_sizes, int n_in,
                              void* d_out, int out_size)
{
    const float* x      = (const float*)d_in[0];
    const float* W_attn = (const float*)d_in[1];
    const float* b_attn = (const float*)d_in[2];
    const float* W_proj = (const float*)d_in[3];
    const float* b_proj = (const float*)d_in[4];
    float* out = (float*)d_out;

    __half *qkvh, *qkvl, *xhi, *xlo, *yhi, *ylo, *wah, *wph;
    cudaGetSymbolAddress((void**)&qkvh, g_qkvh);
    cudaGetSymbolAddress((void**)&qkvl, g_qkvl);
    cudaGetSymbolAddress((void**)&xhi,  g_xhi);
    cudaGetSymbolAddress((void**)&xlo,  g_xlo);
    cudaGetSymbolAddress((void**)&yhi,  g_yhi);
    cudaGetSymbolAddress((void**)&ylo,  g_ylo);
    cudaGetSymbolAddress((void**)&wah,  g_Wah);
    cudaGetSymbolAddress((void**)&wph,  g_Wph);

    static bool attr_done = false;
    if (!attr_done) {
        cudaFuncSetAttribute(hmma_gemm_kernel<true>,
                             cudaFuncAttributeMaxDynamicSharedMemorySize, GEMM_SMEM);
        cudaFuncSetAttribute(hmma_gemm_kernel<false>,
                             cudaFuncAttributeMaxDynamicSharedMemorySize, GEMM_SMEM);
        cudaFuncSetAttribute(attn_mma_kernel,
                             cudaFuncAttributeMaxDynamicSharedMemorySize, ATTN_SMEM);
        attr_done = true;
    }

    // 1) split x -> fp16 hi/lo
    {
        int n4 = BT * CC / 4;
        split_kernel<<<(n4 + 255) / 256, 256>>>(x, xhi, xlo, n4);
    }
    // 2) transpose weights (single fp16)
    transpose_h_kernel<<<dim3(C3 / 32, CC / 32), dim3(32, 8)>>>(W_attn, wah, CC, C3);
    transpose_h_kernel<<<dim3(CC / 32, CC / 32), dim3(32, 8)>>>(W_proj, wph, CC, CC);

    // 3) QKV GEMM -> qkv hi/lo fp16 (fused split epilogue)
    hmma_gemm_kernel<true><<<dim3(C3 / GT_N, BT / GT_M), 512, GEMM_SMEM>>>(
        xhi, xlo, wah, b_attn, nullptr, qkvh, qkvl, C3);

    // 4) tensor-core flash attention -> y hi/lo fp16
    attn_mma_kernel<<<dim3(TT / AT_BQ, HH, BB), 256, ATTN_SMEM>>>(qkvh, qkvl, yhi, ylo);

    // 5) proj GEMM -> out fp32
    hmma_gemm_kernel<false><<<dim3(CC / GT_N, BT / GT_M), 512, GEMM_SMEM>>>(
        yhi, ylo, wph, b_proj, out, nullptr, nullptr, CC);
}

// round 11
// speedup vs baseline: 4.7032x; 1.1321x over previous
#include <cuda_runtime.h>
#include <cuda_fp16.h>
#include <cstdint>

// Problem constants: B=4, T=2048, C=1024, H=16, D=64
#define BB   4
#define TT   2048
#define CC   1024
#define C3   3072
#define HH   16
#define DD   64
#define BT   (BB * TT)          // 8192 rows
#define KK   1024               // GEMM K (both GEMMs)

// ---------------------------------------------------------------------------
// Scratch (__device__ globals; no allocation allowed)
// fp16 2-term scheme: activations split hi/lo, weights/K/V single fp16.
// Q part of qkv is pre-scaled by 0.125 (fused in GEMM epilogue).
// ---------------------------------------------------------------------------
__device__ __align__(1024) __half  g_qkvh[(size_t)BT * C3];   // qkv hi
__device__ __align__(1024) __half  g_qkvl[(size_t)BT * C3];   // qkv lo (Q cols only)
__device__ __align__(1024) __half  g_xhi[(size_t)BT * CC];
__device__ __align__(1024) __half  g_xlo[(size_t)BT * CC];
__device__ __align__(1024) __half  g_yhi[(size_t)BT * CC];
__device__ __align__(1024) __half  g_ylo[(size_t)BT * CC];
__device__ __align__(1024) __half  g_Wah[(size_t)C3 * CC];    // W_attn^T [N,K]
__device__ __align__(1024) __half  g_Wph[(size_t)CC * CC];    // W_proj^T [N,K]

// ---------------------------------------------------------------------------
// PTX helpers — baseline PTX only (compute_103 has no tcgen05/TMA-tensor!)
// ---------------------------------------------------------------------------
__device__ __forceinline__ uint32_t smem_u32(const void* p) {
    uint32_t a;
    asm("{ .reg .u64 t; cvta.to.shared.u64 t, %1; cvt.u32.u64 %0, t; }" : "=r"(a) : "l"(p));
    return a;
}
__device__ __forceinline__ void cp16(uint32_t saddr, const void* g) {
    asm volatile("cp.async.cg.shared.global [%0], [%1], 16;\n" :: "r"(saddr), "l"(g));
}
__device__ __forceinline__ void cp_commit() {
    asm volatile("cp.async.commit_group;\n" ::: "memory");
}
template<int N> __device__ __forceinline__ void cp_wait() {
    asm volatile("cp.async.wait_group %0;\n" :: "n"(N) : "memory");
}
__device__ __forceinline__ void ldsm_x4(uint32_t* r, uint32_t addr) {
    asm volatile("ldmatrix.sync.aligned.m8n8.x4.shared.b16 {%0,%1,%2,%3}, [%4];"
        : "=r"(r[0]), "=r"(r[1]), "=r"(r[2]), "=r"(r[3]) : "r"(addr));
}
__device__ __forceinline__ void ldsm_x4_t(uint32_t* r, uint32_t addr) {
    asm volatile("ldmatrix.sync.aligned.m8n8.x4.trans.shared.b16 {%0,%1,%2,%3}, [%4];"
        : "=r"(r[0]), "=r"(r[1]), "=r"(r[2]), "=r"(r[3]) : "r"(addr));
}
__device__ __forceinline__ void mma16816(float* d, const uint32_t* a, const uint32_t* b) {
    asm volatile("mma.sync.aligned.m16n8k16.row.col.f32.f16.f16.f32 "
        "{%0,%1,%2,%3}, {%4,%5,%6,%7}, {%8,%9}, {%0,%1,%2,%3};"
        : "+f"(d[0]), "+f"(d[1]), "+f"(d[2]), "+f"(d[3])
        : "r"(a[0]), "r"(a[1]), "r"(a[2]), "r"(a[3]), "r"(b[0]), "r"(b[1]));
}
// swizzled address inside a [rows][128B] tile (SW128: 16B chunks permuted)
__device__ __forceinline__ uint32_t sw_addr(uint32_t base, int row, int kb) {
    uint32_t off = ((uint32_t)row << 7) + (uint32_t)kb;
    return base + (off ^ ((off >> 3) & 0x70));
}
__device__ __forceinline__ uint32_t pack_f16(float a, float b) {
    __half2 h = __floats2half2_rn(a, b);
    return *(uint32_t*)&h;
}

// ---------------------------------------------------------------------------
// Split fp32 -> fp16 hi/lo (activations)
// ---------------------------------------------------------------------------
__global__ void split_kernel(const float* __restrict__ src,
                             __half* __restrict__ hi,
                             __half* __restrict__ lo, int n4) {
    int i = blockIdx.x * blockDim.x + threadIdx.x;
    if (i >= n4) return;
    float4 v = ((const float4*)src)[i];
    __half h0 = __float2half_rn(v.x), h1 = __float2half_rn(v.y);
    __half h2 = __float2half_rn(v.z), h3 = __float2half_rn(v.w);
    ((__half2*)hi)[2*i]   = __half2(h0, h1);
    ((__half2*)hi)[2*i+1] = __half2(h2, h3);
    ((__half2*)lo)[2*i]   = __half2(__float2half_rn(v.x - __half2float(h0)),
                                    __float2half_rn(v.y - __half2float(h1)));
    ((__half2*)lo)[2*i+1] = __half2(__float2half_rn(v.z - __half2float(h2)),
                                    __float2half_rn(v.w - __half2float(h3)));
}

// Transpose W[K,N] -> Wt[N,K], fp16
__global__ void transpose_h_kernel(const float* __restrict__ W,
                                   __half* __restrict__ Th, int K, int N) {
    __shared__ float t[32][33];
    int tx = threadIdx.x, ty = threadIdx.y;
    int n0 = blockIdx.x * 32, k0 = blockIdx.y * 32;
    #pragma unroll
    for (int j = 0; j < 4; j++)
        t[ty + 8*j][tx] = W[(size_t)(k0 + ty + 8*j) * N + n0 + tx];
    __syncthreads();
    #pragma unroll
    for (int j = 0; j < 4; j++)
        Th[(size_t)(n0 + ty + 8*j) * K + k0 + tx] = __float2half_rn(t[tx][ty + 8*j]);
}

// ---------------------------------------------------------------------------
// mma.sync fp16 2-term GEMM: C = (Ahi+Alo)·Bh^T + bias  [optionally *0.125]
// CTA 128x256, BK=64 (128B rows, SW128), 16 warps (4m x 4n, 32x64 each).
// 3-stage cp.async ring, ONE __syncthreads per chunk. 512 threads.
// SPLIT: write fp16 hi (+ lo only where col < lo_below); else fp32.
// scale_below: cols < scale_below get *0.125 after bias (Q pre-scale).
// ---------------------------------------------------------------------------
#define GT_M   128
#define GT_N   256
#define GT_K   64
#define NKCH   (KK / GT_K)                // 16
#define TILE_A (128 * 128)                // 16384 B
#define TILE_BB (256 * 128)               // 32768 B
#define OFF_AH 0
#define OFF_AL (TILE_A)
#define OFF_BH (2 * TILE_A)
#define STAGE  (2 * TILE_A + TILE_BB)     // 65536
#define GEMM_SMEM (3 * STAGE)             // 196608

// gmem pitch 2048 B (K=1024 fp16), 512 threads
__device__ __forceinline__ void load_tileA(uint32_t sdst, const char* g,
                                           int kbytes, int tid) {
    #pragma unroll
    for (int it = 0; it < 2; it++) {
        int c = tid + it * 512;           // 1024 chunks of 16B
        int r = c >> 3;
        int cb = (c & 7) << 4;
        uint32_t off = ((uint32_t)r << 7) | (uint32_t)cb;
        cp16(sdst + (off ^ ((off >> 3) & 0x70)), g + (size_t)r * 2048 + kbytes + cb);
    }
}
__device__ __forceinline__ void load_tileB(uint32_t sdst, const char* g,
                                           int kbytes, int tid) {
    #pragma unroll
    for (int it = 0; it < 4; it++) {
        int c = tid + it * 512;           // 2048 chunks of 16B
        int r = c >> 3;
        int cb = (c & 7) << 4;
        uint32_t off = ((uint32_t)r << 7) | (uint32_t)cb;
        cp16(sdst + (off ^ ((off >> 3) & 0x70)), g + (size_t)r * 2048 + kbytes + cb);
    }
}

template<bool SPLIT>
__global__ __launch_bounds__(512)
void hmma_gemm_kernel(const __half* __restrict__ Ahi,
                      const __half* __restrict__ Alo,
                      const __half* __restrict__ Bh,
                      const float* __restrict__ bias,
                      float* __restrict__ C,
                      __half* __restrict__ Ch,
                      __half* __restrict__ Cl,
                      int N, int scale_below, int lo_below) {
    extern __shared__ char smem[];
    const uint32_t sbase = smem_u32(smem);
    const int tid  = threadIdx.x;
    const int lane = tid & 31;
    const int wid  = tid >> 5;            // 0..15
    const int wm   = wid >> 2;            // 0..3 -> 32 rows
    const int wn   = wid & 3;             // 0..3 -> 64 cols
    const int bx   = blockIdx.x;
    const int by   = blockIdx.y;

    const char* gAh = (const char*)Ahi + (size_t)by * GT_M * 2048;
    const char* gAl = (const char*)Alo + (size_t)by * GT_M * 2048;
    const char* gBh = (const char*)Bh  + (size_t)bx * GT_N * 2048;

    // prologue: chunks 0,1 -> stages 0,1
    #pragma unroll
    for (int st = 0; st < 2; st++) {
        uint32_t sb = sbase + st * STAGE;
        int kb = st * 128;
        load_tileA(sb + OFF_AH, gAh, kb, tid);
        load_tileA(sb + OFF_AL, gAl, kb, tid);
        load_tileB(sb + OFF_BH, gBh, kb, tid);
        cp_commit();
    }

    float acc[2][8][4];
    #pragma unroll
    for (int mt = 0; mt < 2; mt++)
        #pragma unroll
        for (int nt = 0; nt < 8; nt++)
            #pragma unroll
            for (int r = 0; r < 4; r++) acc[mt][nt][r] = 0.f;

    const int arow = wm * 32 + (lane & 15);
    const int akb  = (lane >> 4) << 4;
    const int brow = wn * 64 + (lane & 7) + ((lane >> 4) << 3);
    const int bkb  = ((lane >> 3) & 1) << 4;

    for (int i = 0; i < NKCH; i++) {
        const uint32_t sb = sbase + (uint32_t)(i % 3) * STAGE;

        if (i + 1 < NKCH) cp_wait<1>(); else cp_wait<0>();
        __syncthreads();

        // refill stage (i+2)%3 == (i-1)%3 BEFORE compute
        if (i + 2 < NKCH) {
            uint32_t sb2 = sbase + (uint32_t)((i + 2) % 3) * STAGE;
            int kb = (i + 2) * 128;
            load_tileA(sb2 + OFF_AH, gAh, kb, tid);
            load_tileA(sb2 + OFF_AL, gAl, kb, tid);
            load_tileB(sb2 + OFF_BH, gBh, kb, tid);
            cp_commit();
        }

        #pragma unroll
        for (int ks = 0; ks < 4; ks++) {
            const int ksb = ks * 32;
            uint32_t ah[2][4], al[2][4], bh[4][4];
            #pragma unroll
            for (int mt = 0; mt < 2; mt++) {
                ldsm_x4(ah[mt], sw_addr(sb + OFF_AH, arow + mt * 16, ksb + akb));
                ldsm_x4(al[mt], sw_addr(sb + OFF_AL, arow + mt * 16, ksb + akb));
            }
            #pragma unroll
            for (int p = 0; p < 4; p++)
                ldsm_x4(bh[p], sw_addr(sb + OFF_BH, brow + p * 16, ksb + bkb));
            #pragma unroll
            for (int mt = 0; mt < 2; mt++)
                #pragma unroll
                for (int nt = 0; nt < 8; nt++)
                    mma16816(acc[mt][nt], ah[mt], &bh[nt >> 1][(nt & 1) * 2]);
            #pragma unroll
            for (int mt = 0; mt < 2; mt++)
                #pragma unroll
                for (int nt = 0; nt < 8; nt++)
                    mma16816(acc[mt][nt], al[mt], &bh[nt >> 1][(nt & 1) * 2]);
        }
    }

    // Epilogue
    const int g = lane >> 2, t = lane & 3;
    const int row_base = by * GT_M + wm * 32 + g;
    const int col_base = bx * GT_N + wn * 64 + t * 2;
    const float sc = (col_base < scale_below) ? 0.125f : 1.0f;   // uniform per warp
    const bool store_lo = SPLIT && (col_base < lo_below);
    #pragma unroll
    for (int mt = 0; mt < 2; mt++) {
        const int r0 = row_base + mt * 16;
        #pragma unroll
        for (int nt = 0; nt < 8; nt++) {
            const int c = col_base + nt * 8;
            float b0 = bias[c], b1 = bias[c + 1];
            float v0 = (acc[mt][nt][0] + b0) * sc, v1 = (acc[mt][nt][1] + b1) * sc;
            float v2 = (acc[mt][nt][2] + b0) * sc, v3 = (acc[mt][nt][3] + b1) * sc;
            if (SPLIT) {
                __half h0 = __float2half_rn(v0), h1 = __float2half_rn(v1);
                __half h2 = __float2half_rn(v2), h3 = __float2half_rn(v3);
                *(__half2*)(Ch + (size_t)r0 * N + c)       = __half2(h0, h1);
                *(__half2*)(Ch + (size_t)(r0 + 8) * N + c) = __half2(h2, h3);
                if (store_lo) {
                    *(__half2*)(Cl + (size_t)r0 * N + c) = __half2(
                        __float2half_rn(v0 - __half2float(h0)),
                        __float2half_rn(v1 - __half2float(h1)));
                    *(__half2*)(Cl + (size_t)(r0 + 8) * N + c) = __half2(
                        __float2half_rn(v2 - __half2float(h2)),
                        __float2half_rn(v3 - __half2float(h3)));
                }
            } else {
                *(float2*)(C + (size_t)r0 * N + c)       = make_float2(v0, v1);
                *(float2*)(C + (size_t)(r0 + 8) * N + c) = make_float2(v2, v3);
            }
        }
    }
}

// ---------------------------------------------------------------------------
// mma.sync flash attention (causal). Q 2-term (pre-scaled by 0.125), K/V/P
// single fp16. CTA: 128 q rows (8 warps x 16), BK=64, 3-stage KV ring.
// ---------------------------------------------------------------------------
#define AT_BQ 128
#define AT_BK 64
#define A_QH  0
#define A_QL  16384
#define A_KV0 32768
#define KV_KH 0
#define KV_VH 8192
#define KV_STAGE 16384
#define ATTN_SMEM (A_KV0 + 3 * KV_STAGE)   // 81920

// rows=64 tile load, gmem pitch 6144 B (C3 fp16)
__device__ __forceinline__ void load_rows64(uint32_t sdst, const char* g, int tid) {
    #pragma unroll
    for (int it = 0; it < 2; it++) {
        int c = tid + it * 256;
        int r = c >> 3;
        int cb = (c & 7) << 4;
        uint32_t off = ((uint32_t)r << 7) | (uint32_t)cb;
        cp16(sdst + (off ^ ((off >> 3) & 0x70)), g + (size_t)r * 6144 + cb);
    }
}
__device__ __forceinline__ void load_rows128(uint32_t sdst, const char* g, int tid) {
    #pragma unroll
    for (int it = 0; it < 4; it++) {
        int c = tid + it * 256;
        int r = c >> 3;
        int cb = (c & 7) << 4;
        uint32_t off = ((uint32_t)r << 7) | (uint32_t)cb;
        cp16(sdst + (off ^ ((off >> 3) & 0x70)), g + (size_t)r * 6144 + cb);
    }
}
__device__ __forceinline__ void load_kv_chunk(uint32_t sb, const __half* qh,
                                              int b, int h, int chunk, int tid) {
    const char* gK = (const char*)(qh + (size_t)(b * TT + chunk * AT_BK) * C3 + CC + h * DD);
    load_rows64(sb + KV_KH, gK, tid);
    load_rows64(sb + KV_VH, gK + 2048, tid);     // V = +CC fp16 = +2048 B
    cp_commit();
}

__global__ __launch_bounds__(256)
void attn_mma_kernel(const __half* __restrict__ qh,
                     const __half* __restrict__ ql,
                     __half* __restrict__ yh,
                     __half* __restrict__ yl)
{
    extern __shared__ char smem[];
    const uint32_t sbase = smem_u32(smem);
    const int tid  = threadIdx.x;
    const int lane = tid & 31;
    const int w    = tid >> 5;            // warp 0..7, owns q rows w*16..+15
    const int qt = blockIdx.x, h = blockIdx.y, b = blockIdx.z;
    const int q0 = qt * AT_BQ;
    const int n  = 2 * qt + 2;            // kv chunks (n >= 2)

    const char* gQh = (const char*)(qh + (size_t)(b * TT + q0) * C3 + h * DD);
    const char* gQl = (const char*)(ql + (size_t)(b * TT + q0) * C3 + h * DD);

    // prologue: Q (group 0), KV0 (group 1), KV1 (group 2)
    load_rows128(sbase + A_QH, gQh, tid);
    load_rows128(sbase + A_QL, gQl, tid);
    cp_commit();
    load_kv_chunk(sbase + A_KV0, qh, b, h, 0, tid);
    load_kv_chunk(sbase + A_KV0 + KV_STAGE, qh, b, h, 1, tid);

    cp_wait<2>();
    __syncthreads();

    // Q fragments (loop-invariant): 4 ksteps x 4 regs, hi+lo
    const int arow = w * 16 + (lane & 15);
    const int akb  = (lane >> 4) << 4;
    uint32_t qfh[4][4], qfl[4][4];
    #pragma unroll
    for (int ks = 0; ks < 4; ks++) {
        ldsm_x4(qfh[ks], sw_addr(sbase + A_QH, arow, ks * 32 + akb));
        ldsm_x4(qfl[ks], sw_addr(sbase + A_QL, arow, ks * 32 + akb));
    }

    float oacc[8][4];
    #pragma unroll
    for (int nt = 0; nt < 8; nt++)
        #pragma unroll
        for (int r = 0; r < 4; r++) oacc[nt][r] = 0.f;
    float m0 = -1e30f, m1 = -1e30f, l0 = 0.f, l1 = 0.f;

    const int g_ = lane >> 2, t_ = lane & 3;
    const int brow = (lane & 7) + ((lane >> 4) << 3);
    const int bkb  = ((lane >> 3) & 1) << 4;
    const int vrow = ((lane >> 3) & 1) * 8 + (lane & 7);
    const int vcb  = (lane >> 4) << 4;

    for (int c = 0; c < n; c++) {
        if (c + 1 < n) cp_wait<1>(); else cp_wait<0>();
        __syncthreads();

        if (c + 2 < n)
            load_kv_chunk(sbase + A_KV0 + (uint32_t)((c + 2) % 3) * KV_STAGE,
                          qh, b, h, c + 2, tid);

        const uint32_t sb = sbase + A_KV0 + (uint32_t)(c % 3) * KV_STAGE;
        const int kv0 = c * AT_BK;
        const bool active = (kv0 <= q0 + w * 16 + 15);
        const bool need_mask = (kv0 + 63 > q0 + w * 16);

        if (active) {
            // ---- S = Q K^T (2-term: qh·kh + ql·kh); Q pre-scaled by 0.125 ----
            float sacc[8][4];
            #pragma unroll
            for (int nt = 0; nt < 8; nt++)
                #pragma unroll
                for (int r = 0; r < 4; r++) sacc[nt][r] = 0.f;

            #pragma unroll
            for (int ks = 0; ks < 4; ks++) {
                const int ksb = ks * 32;
                uint32_t kh4[4][4];
                #pragma unroll
                for (int p = 0; p < 4; p++)
                    ldsm_x4(kh4[p], sw_addr(sb + KV_KH, p * 16 + brow, ksb + bkb));
                #pragma unroll
                for (int p = 0; p < 4; p++) {
                    mma16816(sacc[2*p],   qfh[ks], &kh4[p][0]);
                    mma16816(sacc[2*p+1], qfh[ks], &kh4[p][2]);
                }
                #pragma unroll
                for (int p = 0; p < 4; p++) {
                    mma16816(sacc[2*p],   qfl[ks], &kh4[p][0]);
                    mma16816(sacc[2*p+1], qfl[ks], &kh4[p][2]);
                }
            }

            // causal mask (no scale needed — folded into Q)
            const int row0 = q0 + w * 16 + g_;
            if (need_mask) {
                #pragma unroll
                for (int nt = 0; nt < 8; nt++) {
                    int col = kv0 + nt * 8 + 2 * t_;
                    if (col     > row0)     sacc[nt][0] = -1e30f;
                    if (col + 1 > row0)     sacc[nt][1] = -1e30f;
                    if (col     > row0 + 8) sacc[nt][2] = -1e30f;
                    if (col + 1 > row0 + 8) sacc[nt][3] = -1e30f;
                }
            }

            // ---- online softmax (rows g_, g_+8) ----
            float mx0 = -1e30f, mx1 = -1e30f;
            #pragma unroll
            for (int nt = 0; nt < 8; nt++) {
                mx0 = fmaxf(mx0, fmaxf(sacc[nt][0], sacc[nt][1]));
                mx1 = fmaxf(mx1, fmaxf(sacc[nt][2], sacc[nt][3]));
            }
            mx0 = fmaxf(mx0, __shfl_xor_sync(0xffffffffu, mx0, 1));
            mx0 = fmaxf(mx0, __shfl_xor_sync(0xffffffffu, mx0, 2));
            mx1 = fmaxf(mx1, __shfl_xor_sync(0xffffffffu, mx1, 1));
            mx1 = fmaxf(mx1, __shfl_xor_sync(0xffffffffu, mx1, 2));
            mx0 = fmaxf(mx0, m0);
            mx1 = fmaxf(mx1, m1);

            float rs0 = 0.f, rs1 = 0.f;
            #pragma unroll
            for (int nt = 0; nt < 8; nt++) {
                sacc[nt][0] = __expf(sacc[nt][0] - mx0);
                sacc[nt][1] = __expf(sacc[nt][1] - mx0);
                sacc[nt][2] = __expf(sacc[nt][2] - mx1);
                sacc[nt][3] = __expf(sacc[nt][3] - mx1);
                rs0 += sacc[nt][0] + sacc[nt][1];
                rs1 += sacc[nt][2] + sacc[nt][3];
            }
            rs0 += __shfl_xor_sync(0xffffffffu, rs0, 1);
            rs0 += __shfl_xor_sync(0xffffffffu, rs0, 2);
            rs1 += __shfl_xor_sync(0xffffffffu, rs1, 1);
            rs1 += __shfl_xor_sync(0xffffffffu, rs1, 2);

            float a0 = __expf(m0 - mx0);
            float a1 = __expf(m1 - mx1);
            m0 = mx0; m1 = mx1;
            l0 = l0 * a0 + rs0;
            l1 = l1 * a1 + rs1;
            #pragma unroll
            for (int nt = 0; nt < 8; nt++) {
                oacc[nt][0] *= a0; oacc[nt][1] *= a0;
                oacc[nt][2] *= a1; oacc[nt][3] *= a1;
            }

            // ---- pack P single fp16 (P-lo dropped: same error class as
            //      the already-single V term, empirically ~3e-4 total) ----
            uint32_t ph[8][2];
            #pragma unroll
            for (int nt = 0; nt < 8; nt++) {
                ph[nt][0] = pack_f16(sacc[nt][0], sacc[nt][1]);
                ph[nt][1] = pack_f16(sacc[nt][2], sacc[nt][3]);
            }

            // ---- O += P V (1-term), V via ldmatrix.trans ----
            #pragma unroll
            for (int kk = 0; kk < 4; kk++) {
                uint32_t aPh[4] = {ph[2*kk][0], ph[2*kk][1], ph[2*kk+1][0], ph[2*kk+1][1]};
                uint32_t vh4[4][4];
                #pragma unroll
                for (int dd = 0; dd < 4; dd++)
                    ldsm_x4_t(vh4[dd], sw_addr(sb + KV_VH, kk * 16 + vrow, dd * 32 + vcb));
                #pragma unroll
                for (int dd = 0; dd < 4; dd++) {
                    mma16816(oacc[2*dd],   aPh, &vh4[dd][0]);
                    mma16816(oacc[2*dd+1], aPh, &vh4[dd][2]);
                }
            }
        }
    }

    // ---- epilogue: normalize, split hi/lo, store y ----
    const float inv0 = 1.f / l0, inv1 = 1.f / l1;
    const size_t row0 = (size_t)(b * TT + q0 + w * 16 + g_);
    const int col0 = h * DD + 2 * t_;
    #pragma unroll
    for (int nt = 0; nt < 8; nt++) {
        float v0 = oacc[nt][0] * inv0, v1 = oacc[nt][1] * inv0;
        float v2 = oacc[nt][2] * inv1, v3 = oacc[nt][3] * inv1;
        __half h0 = __float2half_rn(v0), h1 = __float2half_rn(v1);
        __half h2 = __float2half_rn(v2), h3 = __float2half_rn(v3);
        size_t i0 = row0 * CC + col0 + nt * 8;
        size_t i1 = (row0 + 8) * CC + col0 + nt * 8;
        *(__half2*)(yh + i0) = __half2(h0, h1);
        *(__half2*)(yh + i1) = __half2(h2, h3);
        *(__half2*)(yl + i0) = __half2(__float2half_rn(v0 - __half2float(h0)),
                                       __float2half_rn(v1 - __half2float(h1)));
        *(__half2*)(yl + i1) = __half2(__float2half_rn(v2 - __half2float(h2)),
                                       __float2half_rn(v3 - __half2float(h3)));
    }
}

// ---------------------------------------------------------------------------
extern "C" void kernel_launch(void* const* d_in, const int* in_sizes, int n_in,
                              void* d_out, int out_size)
{
    const float* x      = (const float*)d_in[0];
    const float* W_attn = (const float*)d_in[1];
    const float* b_attn = (const float*)d_in[2];
    const float* W_proj = (const float*)d_in[3];
    const float* b_proj = (const float*)d_in[4];
    float* out = (float*)d_out;

    __half *qkvh, *qkvl, *xhi, *xlo, *yhi, *ylo, *wah, *wph;
    cudaGetSymbolAddress((void**)&qkvh, g_qkvh);
    cudaGetSymbolAddress((void**)&qkvl, g_qkvl);
    cudaGetSymbolAddress((void**)&xhi,  g_xhi);
    cudaGetSymbolAddress((void**)&xlo,  g_xlo);
    cudaGetSymbolAddress((void**)&yhi,  g_yhi);
    cudaGetSymbolAddress((void**)&ylo,  g_ylo);
    cudaGetSymbolAddress((void**)&wah,  g_Wah);
    cudaGetSymbolAddress((void**)&wph,  g_Wph);

    static bool attr_done = false;
    if (!attr_done) {
        cudaFuncSetAttribute(hmma_gemm_kernel<true>,
                             cudaFuncAttributeMaxDynamicSharedMemorySize, GEMM_SMEM);
        cudaFuncSetAttribute(hmma_gemm_kernel<false>,
                             cudaFuncAttributeMaxDynamicSharedMemorySize, GEMM_SMEM);
        cudaFuncSetAttribute(attn_mma_kernel,
                             cudaFuncAttributeMaxDynamicSharedMemorySize, ATTN_SMEM);
        attr_done = true;
    }

    // 1) split x -> fp16 hi/lo
    {
        int n4 = BT * CC / 4;
        split_kernel<<<(n4 + 255) / 256, 256>>>(x, xhi, xlo, n4);
    }
    // 2) transpose weights (single fp16)
    transpose_h_kernel<<<dim3(C3 / 32, CC / 32), dim3(32, 8)>>>(W_attn, wah, CC, C3);
    transpose_h_kernel<<<dim3(CC / 32, CC / 32), dim3(32, 8)>>>(W_proj, wph, CC, CC);

    // 3) QKV GEMM -> qkv hi (+ lo for Q cols), Q cols pre-scaled by 0.125
    hmma_gemm_kernel<true><<<dim3(C3 / GT_N, BT / GT_M), 512, GEMM_SMEM>>>(
        xhi, xlo, wah, b_attn, nullptr, qkvh, qkvl, C3,
        /*scale_below=*/CC, /*lo_below=*/CC);

    // 4) tensor-core flash attention -> y hi/lo fp16
    attn_mma_kernel<<<dim3(TT / AT_BQ, HH, BB), 256, ATTN_SMEM>>>(qkvh, qkvl, yhi, ylo);

    // 5) proj GEMM -> out fp32
    hmma_gemm_kernel<false><<<dim3(CC / GT_N, BT / GT_M), 512, GEMM_SMEM>>>(
        yhi, ylo, wph, b_proj, out, nullptr, nullptr, CC,
        /*scale_below=*/0, /*lo_below=*/0);
}

// round 13
// speedup vs baseline: 4.9178x; 1.0456x over previous
#include <cuda_runtime.h>
#include <cuda_fp16.h>
#include <cstdint>

// Problem constants: B=4, T=2048, C=1024, H=16, D=64
#define BB   4
#define TT   2048
#define CC   1024
#define C3   3072
#define HH   16
#define DD   64
#define BT   (BB * TT)          // 8192 rows
#define KK   1024               // GEMM K (both GEMMs)

// ---------------------------------------------------------------------------
// Scratch (__device__ globals; no allocation allowed)
// fp16 2-term scheme: activations split hi/lo, weights/K/V single fp16.
// Q part of qkv is pre-scaled by 0.125 (fused in GEMM epilogue).
// K/V columns of the QKV GEMM are computed 1-term (they are stored as
// single fp16 anyway; adds ~2.8e-4 RMS, same class as their quantization).
// ---------------------------------------------------------------------------
__device__ __align__(1024) __half  g_qkvh[(size_t)BT * C3];   // qkv hi
__device__ __align__(1024) __half  g_qkvl[(size_t)BT * C3];   // qkv lo (Q cols only)
__device__ __align__(1024) __half  g_xhi[(size_t)BT * CC];
__device__ __align__(1024) __half  g_xlo[(size_t)BT * CC];
__device__ __align__(1024) __half  g_yhi[(size_t)BT * CC];
__device__ __align__(1024) __half  g_ylo[(size_t)BT * CC];
__device__ __align__(1024) __half  g_Wah[(size_t)C3 * CC];    // W_attn^T [N,K]
__device__ __align__(1024) __half  g_Wph[(size_t)CC * CC];    // W_proj^T [N,K]

// ---------------------------------------------------------------------------
// PTX helpers — baseline PTX only (compute_103 has no tcgen05/TMA-tensor!)
// ---------------------------------------------------------------------------
__device__ __forceinline__ uint32_t smem_u32(const void* p) {
    uint32_t a;
    asm("{ .reg .u64 t; cvta.to.shared.u64 t, %1; cvt.u32.u64 %0, t; }" : "=r"(a) : "l"(p));
    return a;
}
__device__ __forceinline__ void cp16(uint32_t saddr, const void* g) {
    asm volatile("cp.async.cg.shared.global [%0], [%1], 16;\n" :: "r"(saddr), "l"(g));
}
__device__ __forceinline__ void cp_commit() {
    asm volatile("cp.async.commit_group;\n" ::: "memory");
}
template<int N> __device__ __forceinline__ void cp_wait() {
    asm volatile("cp.async.wait_group %0;\n" :: "n"(N) : "memory");
}
__device__ __forceinline__ void ldsm_x4(uint32_t* r, uint32_t addr) {
    asm volatile("ldmatrix.sync.aligned.m8n8.x4.shared.b16 {%0,%1,%2,%3}, [%4];"
        : "=r"(r[0]), "=r"(r[1]), "=r"(r[2]), "=r"(r[3]) : "r"(addr));
}
__device__ __forceinline__ void ldsm_x4_t(uint32_t* r, uint32_t addr) {
    asm volatile("ldmatrix.sync.aligned.m8n8.x4.trans.shared.b16 {%0,%1,%2,%3}, [%4];"
        : "=r"(r[0]), "=r"(r[1]), "=r"(r[2]), "=r"(r[3]) : "r"(addr));
}
__device__ __forceinline__ void mma16816(float* d, const uint32_t* a, const uint32_t* b) {
    asm volatile("mma.sync.aligned.m16n8k16.row.col.f32.f16.f16.f32 "
        "{%0,%1,%2,%3}, {%4,%5,%6,%7}, {%8,%9}, {%0,%1,%2,%3};"
        : "+f"(d[0]), "+f"(d[1]), "+f"(d[2]), "+f"(d[3])
        : "r"(a[0]), "r"(a[1]), "r"(a[2]), "r"(a[3]), "r"(b[0]), "r"(b[1]));
}
// swizzled address inside a [rows][128B] tile (SW128: 16B chunks permuted)
__device__ __forceinline__ uint32_t sw_addr(uint32_t base, int row, int kb) {
    uint32_t off = ((uint32_t)row << 7) + (uint32_t)kb;
    return base + (off ^ ((off >> 3) & 0x70));
}
__device__ __forceinline__ uint32_t pack_f16(float a, float b) {
    __half2 h = __floats2half2_rn(a, b);
    return *(uint32_t*)&h;
}

// ---------------------------------------------------------------------------
// Split fp32 -> fp16 hi/lo (activations)
// ---------------------------------------------------------------------------
__global__ void split_kernel(const float* __restrict__ src,
                             __half* __restrict__ hi,
                             __half* __restrict__ lo, int n4) {
    int i = blockIdx.x * blockDim.x + threadIdx.x;
    if (i >= n4) return;
    float4 v = ((const float4*)src)[i];
    __half h0 = __float2half_rn(v.x), h1 = __float2half_rn(v.y);
    __half h2 = __float2half_rn(v.z), h3 = __float2half_rn(v.w);
    ((__half2*)hi)[2*i]   = __half2(h0, h1);
    ((__half2*)hi)[2*i+1] = __half2(h2, h3);
    ((__half2*)lo)[2*i]   = __half2(__float2half_rn(v.x - __half2float(h0)),
                                    __float2half_rn(v.y - __half2float(h1)));
    ((__half2*)lo)[2*i+1] = __half2(__float2half_rn(v.z - __half2float(h2)),
                                    __float2half_rn(v.w - __half2float(h3)));
}

// Transpose W[K,N] -> Wt[N,K], fp16
__global__ void transpose_h_kernel(const float* __restrict__ W,
                                   __half* __restrict__ Th, int K, int N) {
    __shared__ float t[32][33];
    int tx = threadIdx.x, ty = threadIdx.y;
    int n0 = blockIdx.x * 32, k0 = blockIdx.y * 32;
    #pragma unroll
    for (int j = 0; j < 4; j++)
        t[ty + 8*j][tx] = W[(size_t)(k0 + ty + 8*j) * N + n0 + tx];
    __syncthreads();
    #pragma unroll
    for (int j = 0; j < 4; j++)
        Th[(size_t)(n0 + ty + 8*j) * K + k0 + tx] = __float2half_rn(t[tx][ty + 8*j]);
}

// ---------------------------------------------------------------------------
// mma.sync fp16 GEMM: C = (Ahi[+Alo])·Bh^T + bias  [optionally *0.125]
// CTA 128x256, BK=64 (128B rows, SW128), 16 warps (4m x 4n, 32x64 each).
// 3-stage cp.async ring, ONE __syncthreads per chunk. 512 threads.
// A-lo term applied only for output cols < aterm2_below (uniform per CTA).
// Per-warp ks rotation decorrelates ldmatrix bursts across an SMSP.
// ---------------------------------------------------------------------------
#define GT_M   128
#define GT_N   256
#define GT_K   64
#define NKCH   (KK / GT_K)                // 16
#define TILE_A (128 * 128)                // 16384 B
#define TILE_BB (256 * 128)               // 32768 B
#define OFF_AH 0
#define OFF_AL (TILE_A)
#define OFF_BH (2 * TILE_A)
#define STAGE  (2 * TILE_A + TILE_BB)     // 65536
#define GEMM_SMEM (3 * STAGE)             // 196608

// gmem pitch 2048 B (K=1024 fp16), 512 threads
__device__ __forceinline__ void load_tileA(uint32_t sdst, const char* g,
                                           int kbytes, int tid) {
    #pragma unroll
    for (int it = 0; it < 2; it++) {
        int c = tid + it * 512;           // 1024 chunks of 16B
        int r = c >> 3;
        int cb = (c & 7) << 4;
        uint32_t off = ((uint32_t)r << 7) | (uint32_t)cb;
        cp16(sdst + (off ^ ((off >> 3) & 0x70)), g + (size_t)r * 2048 + kbytes + cb);
    }
}
__device__ __forceinline__ void load_tileB(uint32_t sdst, const char* g,
                                           int kbytes, int tid) {
    #pragma unroll
    for (int it = 0; it < 4; it++) {
        int c = tid + it * 512;           // 2048 chunks of 16B
        int r = c >> 3;
        int cb = (c & 7) << 4;
        uint32_t off = ((uint32_t)r << 7) | (uint32_t)cb;
        cp16(sdst + (off ^ ((off >> 3) & 0x70)), g + (size_t)r * 2048 + kbytes + cb);
    }
}

template<bool SPLIT>
__global__ __launch_bounds__(512)
void hmma_gemm_kernel(const __half* __restrict__ Ahi,
                      const __half* __restrict__ Alo,
                      const __half* __restrict__ Bh,
                      const float* __restrict__ bias,
                      float* __restrict__ C,
                      __half* __restrict__ Ch,
                      __half* __restrict__ Cl,
                      int N, int scale_below, int lo_below, int aterm2_below) {
    extern __shared__ char smem[];
    const uint32_t sbase = smem_u32(smem);
    const int tid  = threadIdx.x;
    const int lane = tid & 31;
    const int wid  = tid >> 5;            // 0..15
    const int wm   = wid >> 2;            // 0..3 -> 32 rows
    const int wn   = wid & 3;             // 0..3 -> 64 cols
    const int bx   = blockIdx.x;
    const int by   = blockIdx.y;
    const bool two_term = (bx * GT_N) < aterm2_below;   // uniform per CTA

    const char* gAh = (const char*)Ahi + (size_t)by * GT_M * 2048;
    const char* gAl = (const char*)Alo + (size_t)by * GT_M * 2048;
    const char* gBh = (const char*)Bh  + (size_t)bx * GT_N * 2048;

    // prologue: chunks 0,1 -> stages 0,1
    #pragma unroll
    for (int st = 0; st < 2; st++) {
        uint32_t sb = sbase + st * STAGE;
        int kb = st * 128;
        load_tileA(sb + OFF_AH, gAh, kb, tid);
        if (two_term) load_tileA(sb + OFF_AL, gAl, kb, tid);
        load_tileB(sb + OFF_BH, gBh, kb, tid);
        cp_commit();
    }

    float acc[2][8][4];
    #pragma unroll
    for (int mt = 0; mt < 2; mt++)
        #pragma unroll
        for (int nt = 0; nt < 8; nt++)
            #pragma unroll
            for (int r = 0; r < 4; r++) acc[mt][nt][r] = 0.f;

    const int arow = wm * 32 + (lane & 15);
    const int akb  = (lane >> 4) << 4;
    const int brow = wn * 64 + (lane & 7) + ((lane >> 4) << 3);
    const int bkb  = ((lane >> 3) & 1) << 4;

    for (int i = 0; i < NKCH; i++) {
        const uint32_t sb = sbase + (uint32_t)(i % 3) * STAGE;

        if (i + 1 < NKCH) cp_wait<1>(); else cp_wait<0>();
        __syncthreads();

        // refill stage (i+2)%3 == (i-1)%3 BEFORE compute
        if (i + 2 < NKCH) {
            uint32_t sb2 = sbase + (uint32_t)((i + 2) % 3) * STAGE;
            int kb = (i + 2) * 128;
            load_tileA(sb2 + OFF_AH, gAh, kb, tid);
            if (two_term) load_tileA(sb2 + OFF_AL, gAl, kb, tid);
            load_tileB(sb2 + OFF_BH, gBh, kb, tid);
            cp_commit();
        }

        #pragma unroll
        for (int kss = 0; kss < 4; kss++) {
            // per-warp rotation: decorrelate ldsm bursts across the SMSP
            const int ks = (kss + wid) & 3;
            const int ksb = ks * 32;
            uint32_t ah[2][4], al[2][4], bh[4][4];
            #pragma unroll
            for (int mt = 0; mt < 2; mt++)
                ldsm_x4(ah[mt], sw_addr(sb + OFF_AH, arow + mt * 16, ksb + akb));
            if (two_term)
                #pragma unroll
                for (int mt = 0; mt < 2; mt++)
                    ldsm_x4(al[mt], sw_addr(sb + OFF_AL, arow + mt * 16, ksb + akb));
            #pragma unroll
            for (int p = 0; p < 4; p++)
                ldsm_x4(bh[p], sw_addr(sb + OFF_BH, brow + p * 16, ksb + bkb));
            #pragma unroll
            for (int mt = 0; mt < 2; mt++)
                #pragma unroll
                for (int nt = 0; nt < 8; nt++)
                    mma16816(acc[mt][nt], ah[mt], &bh[nt >> 1][(nt & 1) * 2]);
            if (two_term)
                #pragma unroll
                for (int mt = 0; mt < 2; mt++)
                    #pragma unroll
                    for (int nt = 0; nt < 8; nt++)
                        mma16816(acc[mt][nt], al[mt], &bh[nt >> 1][(nt & 1) * 2]);
        }
    }

    // Epilogue
    const int g = lane >> 2, t = lane & 3;
    const int row_base = by * GT_M + wm * 32 + g;
    const int col_base = bx * GT_N + wn * 64 + t * 2;
    const float sc = (col_base < scale_below) ? 0.125f : 1.0f;   // uniform per warp
    const bool store_lo = SPLIT && (col_base < lo_below);
    #pragma unroll
    for (int mt = 0; mt < 2; mt++) {
        const int r0 = row_base + mt * 16;
        #pragma unroll
        for (int nt = 0; nt < 8; nt++) {
            const int c = col_base + nt * 8;
            float b0 = bias[c], b1 = bias[c + 1];
            float v0 = (acc[mt][nt][0] + b0) * sc, v1 = (acc[mt][nt][1] + b1) * sc;
            float v2 = (acc[mt][nt][2] + b0) * sc, v3 = (acc[mt][nt][3] + b1) * sc;
            if (SPLIT) {
                __half h0 = __float2half_rn(v0), h1 = __float2half_rn(v1);
                __half h2 = __float2half_rn(v2), h3 = __float2half_rn(v3);
                *(__half2*)(Ch + (size_t)r0 * N + c)       = __half2(h0, h1);
                *(__half2*)(Ch + (size_t)(r0 + 8) * N + c) = __half2(h2, h3);
                if (store_lo) {
                    *(__half2*)(Cl + (size_t)r0 * N + c) = __half2(
                        __float2half_rn(v0 - __half2float(h0)),
                        __float2half_rn(v1 - __half2float(h1)));
                    *(__half2*)(Cl + (size_t)(r0 + 8) * N + c) = __half2(
                        __float2half_rn(v2 - __half2float(h2)),
                        __float2half_rn(v3 - __half2float(h3)));
                }
            } else {
                *(float2*)(C + (size_t)r0 * N + c)       = make_float2(v0, v1);
                *(float2*)(C + (size_t)(r0 + 8) * N + c) = make_float2(v2, v3);
            }
        }
    }
}

// ---------------------------------------------------------------------------
// mma.sync flash attention (causal). Q 2-term (pre-scaled by 0.125), K/V/P
// single fp16. CTA: 128 q rows (8 warps x 16), BK=64, 3-stage KV ring.
// Per-warp ks/kk rotation decorrelates ldmatrix bursts.
// ---------------------------------------------------------------------------
#define AT_BQ 128
#define AT_BK 64
#define A_QH  0
#define A_QL  16384
#define A_KV0 32768
#define KV_KH 0
#define KV_VH 8192
#define KV_STAGE 16384
#define ATTN_SMEM (A_KV0 + 3 * KV_STAGE)   // 81920

// rows=64 tile load, gmem pitch 6144 B (C3 fp16)
__device__ __forceinline__ void load_rows64(uint32_t sdst, const char* g, int tid) {
    #pragma unroll
    for (int it = 0; it < 2; it++) {
        int c = tid + it * 256;
        int r = c >> 3;
        int cb = (c & 7) << 4;
        uint32_t off = ((uint32_t)r << 7) | (uint32_t)cb;
        cp16(sdst + (off ^ ((off >> 3) & 0x70)), g + (size_t)r * 6144 + cb);
    }
}
__device__ __forceinline__ void load_rows128(uint32_t sdst, const char* g, int tid) {
    #pragma unroll
    for (int it = 0; it < 4; it++) {
        int c = tid + it * 256;
        int r = c >> 3;
        int cb = (c & 7) << 4;
        uint32_t off = ((uint32_t)r << 7) | (uint32_t)cb;
        cp16(sdst + (off ^ ((off >> 3) & 0x70)), g + (size_t)r * 6144 + cb);
    }
}
__device__ __forceinline__ void load_kv_chunk(uint32_t sb, const __half* qh,
                                              int b, int h, int chunk, int tid) {
    const char* gK = (const char*)(qh + (size_t)(b * TT + chunk * AT_BK) * C3 + CC + h * DD);
    load_rows64(sb + KV_KH, gK, tid);
    load_rows64(sb + KV_VH, gK + 2048, tid);     // V = +CC fp16 = +2048 B
    cp_commit();
}

__global__ __launch_bounds__(256)
void attn_mma_kernel(const __half* __restrict__ qh,
                     const __half* __restrict__ ql,
                     __half* __restrict__ yh,
                     __half* __restrict__ yl)
{
    extern __shared__ char smem[];
    const uint32_t sbase = smem_u32(smem);
    const int tid  = threadIdx.x;
    const int lane = tid & 31;
    const int w    = tid >> 5;            // warp 0..7, owns q rows w*16..+15
    const int qt = blockIdx.x, h = blockIdx.y, b = blockIdx.z;
    const int q0 = qt * AT_BQ;
    const int n  = 2 * qt + 2;            // kv chunks (n >= 2)

    const char* gQh = (const char*)(qh + (size_t)(b * TT + q0) * C3 + h * DD);
    const char* gQl = (const char*)(ql + (size_t)(b * TT + q0) * C3 + h * DD);

    // prologue: Q (group 0), KV0 (group 1), KV1 (group 2)
    load_rows128(sbase + A_QH, gQh, tid);
    load_rows128(sbase + A_QL, gQl, tid);
    cp_commit();
    load_kv_chunk(sbase + A_KV0, qh, b, h, 0, tid);
    load_kv_chunk(sbase + A_KV0 + KV_STAGE, qh, b, h, 1, tid);

    cp_wait<2>();
    __syncthreads();

    // Q fragments (loop-invariant): 4 ksteps x 4 regs, hi+lo
    const int arow = w * 16 + (lane & 15);
    const int akb  = (lane >> 4) << 4;
    uint32_t qfh[4][4], qfl[4][4];
    #pragma unroll
    for (int ks = 0; ks < 4; ks++) {
        ldsm_x4(qfh[ks], sw_addr(sbase + A_QH, arow, ks * 32 + akb));
        ldsm_x4(qfl[ks], sw_addr(sbase + A_QL, arow, ks * 32 + akb));
    }

    float oacc[8][4];
    #pragma unroll
    for (int nt = 0; nt < 8; nt++)
        #pragma unroll
        for (int r = 0; r < 4; r++) oacc[nt][r] = 0.f;
    float m0 = -1e30f, m1 = -1e30f, l0 = 0.f, l1 = 0.f;

    const int g_ = lane >> 2, t_ = lane & 3;
    const int brow = (lane & 7) + ((lane >> 4) << 3);
    const int bkb  = ((lane >> 3) & 1) << 4;
    const int vrow = ((lane >> 3) & 1) * 8 + (lane & 7);
    const int vcb  = (lane >> 4) << 4;

    for (int c = 0; c < n; c++) {
        if (c + 1 < n) cp_wait<1>(); else cp_wait<0>();
        __syncthreads();

        if (c + 2 < n)
            load_kv_chunk(sbase + A_KV0 + (uint32_t)((c + 2) % 3) * KV_STAGE,
                          qh, b, h, c + 2, tid);

        const uint32_t sb = sbase + A_KV0 + (uint32_t)(c % 3) * KV_STAGE;
        const int kv0 = c * AT_BK;
        const bool active = (kv0 <= q0 + w * 16 + 15);
        const bool need_mask = (kv0 + 63 > q0 + w * 16);

        if (active) {
            // ---- S = Q K^T (2-term: qh·kh + ql·kh); Q pre-scaled by 0.125 ----
            float sacc[8][4];
            #pragma unroll
            for (int nt = 0; nt < 8; nt++)
                #pragma unroll
                for (int r = 0; r < 4; r++) sacc[nt][r] = 0.f;

            #pragma unroll
            for (int kss = 0; kss < 4; kss++) {
                const int ks = (kss + w) & 3;       // per-warp rotation
                const int ksb = ks * 32;
                uint32_t kh4[4][4];
                #pragma unroll
                for (int p = 0; p < 4; p++)
                    ldsm_x4(kh4[p], sw_addr(sb + KV_KH, p * 16 + brow, ksb + bkb));
                #pragma unroll
                for (int p = 0; p < 4; p++) {
                    mma16816(sacc[2*p],   qfh[ks], &kh4[p][0]);
                    mma16816(sacc[2*p+1], qfh[ks], &kh4[p][2]);
                }
                #pragma unroll
                for (int p = 0; p < 4; p++) {
                    mma16816(sacc[2*p],   qfl[ks], &kh4[p][0]);
                    mma16816(sacc[2*p+1], qfl[ks], &kh4[p][2]);
                }
            }

            // causal mask (no scale needed — folded into Q)
            const int row0 = q0 + w * 16 + g_;
            if (need_mask) {
                #pragma unroll
                for (int nt = 0; nt < 8; nt++) {
                    int col = kv0 + nt * 8 + 2 * t_;
                    if (col     > row0)     sacc[nt][0] = -1e30f;
                    if (col + 1 > row0)     sacc[nt][1] = -1e30f;
                    if (col     > row0 + 8) sacc[nt][2] = -1e30f;
                    if (col + 1 > row0 + 8) sacc[nt][3] = -1e30f;
                }
            }

            // ---- online softmax (rows g_, g_+8) ----
            float mx0 = -1e30f, mx1 = -1e30f;
            #pragma unroll
            for (int nt = 0; nt < 8; nt++) {
                mx0 = fmaxf(mx0, fmaxf(sacc[nt][0], sacc[nt][1]));
                mx1 = fmaxf(mx1, fmaxf(sacc[nt][2], sacc[nt][3]));
            }
            mx0 = fmaxf(mx0, __shfl_xor_sync(0xffffffffu, mx0, 1));
            mx0 = fmaxf(mx0, __shfl_xor_sync(0xffffffffu, mx0, 2));
            mx1 = fmaxf(mx1, __shfl_xor_sync(0xffffffffu, mx1, 1));
            mx1 = fmaxf(mx1, __shfl_xor_sync(0xffffffffu, mx1, 2));
            mx0 = fmaxf(mx0, m0);
            mx1 = fmaxf(mx1, m1);

            float rs0 = 0.f, rs1 = 0.f;
            #pragma unroll
            for (int nt = 0; nt < 8; nt++) {
                sacc[nt][0] = __expf(sacc[nt][0] - mx0);
                sacc[nt][1] = __expf(sacc[nt][1] - mx0);
                sacc[nt][2] = __expf(sacc[nt][2] - mx1);
                sacc[nt][3] = __expf(sacc[nt][3] - mx1);
                rs0 += sacc[nt][0] + sacc[nt][1];
                rs1 += sacc[nt][2] + sacc[nt][3];
            }
            rs0 += __shfl_xor_sync(0xffffffffu, rs0, 1);
            rs0 += __shfl_xor_sync(0xffffffffu, rs0, 2);
            rs1 += __shfl_xor_sync(0xffffffffu, rs1, 1);
            rs1 += __shfl_xor_sync(0xffffffffu, rs1, 2);

            float a0 = __expf(m0 - mx0);
            float a1 = __expf(m1 - mx1);
            m0 = mx0; m1 = mx1;
            l0 = l0 * a0 + rs0;
            l1 = l1 * a1 + rs1;
            #pragma unroll
            for (int nt = 0; nt < 8; nt++) {
                oacc[nt][0] *= a0; oacc[nt][1] *= a0;
                oacc[nt][2] *= a1; oacc[nt][3] *= a1;
            }

            // ---- pack P single fp16 ----
            uint32_t ph[8][2];
            #pragma unroll
            for (int nt = 0; nt < 8; nt++) {
                ph[nt][0] = pack_f16(sacc[nt][0], sacc[nt][1]);
                ph[nt][1] = pack_f16(sacc[nt][2], sacc[nt][3]);
            }

            // ---- O += P V (1-term), V via ldmatrix.trans ----
            #pragma unroll
            for (int kks = 0; kks < 4; kks++) {
                const int kk = (kks + w) & 3;       // per-warp rotation
                uint32_t aPh[4] = {ph[2*kk][0], ph[2*kk][1], ph[2*kk+1][0], ph[2*kk+1][1]};
                uint32_t vh4[4][4];
                #pragma unroll
                for (int dd = 0; dd < 4; dd++)
                    ldsm_x4_t(vh4[dd], sw_addr(sb + KV_VH, kk * 16 + vrow, dd * 32 + vcb));
                #pragma unroll
                for (int dd = 0; dd < 4; dd++) {
                    mma16816(oacc[2*dd],   aPh, &vh4[dd][0]);
                    mma16816(oacc[2*dd+1], aPh, &vh4[dd][2]);
                }
            }
        }
    }

    // ---- epilogue: normalize, split hi/lo, store y ----
    const float inv0 = 1.f / l0, inv1 = 1.f / l1;
    const size_t row0 = (size_t)(b * TT + q0 + w * 16 + g_);
    const int col0 = h * DD + 2 * t_;
    #pragma unroll
    for (int nt = 0; nt < 8; nt++) {
        float v0 = oacc[nt][0] * inv0, v1 = oacc[nt][1] * inv0;
        float v2 = oacc[nt][2] * inv1, v3 = oacc[nt][3] * inv1;
        __half h0 = __float2half_rn(v0), h1 = __float2half_rn(v1);
        __half h2 = __float2half_rn(v2), h3 = __float2half_rn(v3);
        size_t i0 = row0 * CC + col0 + nt * 8;
        size_t i1 = (row0 + 8) * CC + col0 + nt * 8;
        *(__half2*)(yh + i0) = __half2(h0, h1);
        *(__half2*)(yh + i1) = __half2(h2, h3);
        *(__half2*)(yl + i0) = __half2(__float2half_rn(v0 - __half2float(h0)),
                                       __float2half_rn(v1 - __half2float(h1)));
        *(__half2*)(yl + i1) = __half2(__float2half_rn(v2 - __half2float(h2)),
                                       __float2half_rn(v3 - __half2float(h3)));
    }
}

// ---------------------------------------------------------------------------
extern "C" void kernel_launch(void* const* d_in, const int* in_sizes, int n_in,
                              void* d_out, int out_size)
{
    const float* x      = (const float*)d_in[0];
    const float* W_attn = (const float*)d_in[1];
    const float* b_attn = (const float*)d_in[2];
    const float* W_proj = (const float*)d_in[3];
    const float* b_proj = (const float*)d_in[4];
    float* out = (float*)d_out;

    __half *qkvh, *qkvl, *xhi, *xlo, *yhi, *ylo, *wah, *wph;
    cudaGetSymbolAddress((void**)&qkvh, g_qkvh);
    cudaGetSymbolAddress((void**)&qkvl, g_qkvl);
    cudaGetSymbolAddress((void**)&xhi,  g_xhi);
    cudaGetSymbolAddress((void**)&xlo,  g_xlo);
    cudaGetSymbolAddress((void**)&yhi,  g_yhi);
    cudaGetSymbolAddress((void**)&ylo,  g_ylo);
    cudaGetSymbolAddress((void**)&wah,  g_Wah);
    cudaGetSymbolAddress((void**)&wph,  g_Wph);

    static bool attr_done = false;
    if (!attr_done) {
        cudaFuncSetAttribute(hmma_gemm_kernel<true>,
                             cudaFuncAttributeMaxDynamicSharedMemorySize, GEMM_SMEM);
        cudaFuncSetAttribute(hmma_gemm_kernel<false>,
                             cudaFuncAttributeMaxDynamicSharedMemorySize, GEMM_SMEM);
        cudaFuncSetAttribute(attn_mma_kernel,
                             cudaFuncAttributeMaxDynamicSharedMemorySize, ATTN_SMEM);
        attr_done = true;
    }

    // 1) split x -> fp16 hi/lo
    {
        int n4 = BT * CC / 4;
        split_kernel<<<(n4 + 255) / 256, 256>>>(x, xhi, xlo, n4);
    }
    // 2) transpose weights (single fp16)
    transpose_h_kernel<<<dim3(C3 / 32, CC / 32), dim3(32, 8)>>>(W_attn, wah, CC, C3);
    transpose_h_kernel<<<dim3(CC / 32, CC / 32), dim3(32, 8)>>>(W_proj, wph, CC, CC);

    // 3) QKV GEMM: Q cols 2-term + pre-scaled 0.125 + hi/lo; K/V cols 1-term hi only
    hmma_gemm_kernel<true><<<dim3(C3 / GT_N, BT / GT_M), 512, GEMM_SMEM>>>(
        xhi, xlo, wah, b_attn, nullptr, qkvh, qkvl, C3,
        /*scale_below=*/CC, /*lo_below=*/CC, /*aterm2_below=*/CC);

    // 4) tensor-core flash attention -> y hi/lo fp16
    attn_mma_kernel<<<dim3(TT / AT_BQ, HH, BB), 256, ATTN_SMEM>>>(qkvh, qkvl, yhi, ylo);

    // 5) proj GEMM -> out fp32 (full 2-term)
    hmma_gemm_kernel<false><<<dim3(CC / GT_N, BT / GT_M), 512, GEMM_SMEM>>>(
        yhi, ylo, wph, b_proj, out, nullptr, nullptr, CC,
        /*scale_below=*/0, /*lo_below=*/0, /*aterm2_below=*/CC);
}

// round 17
// speedup vs baseline: 6.6106x; 1.3442x over previous
#include <cuda_runtime.h>
#include <cuda_fp16.h>
#include <cstdint>

// Problem constants: B=4, T=2048, C=1024, H=16, D=64
#define BB   4
#define TT   2048
#define CC   1024
#define C3   3072
#define HH   16
#define DD   64
#define BT   (BB * TT)          // 8192 rows
#define KK   1024               // GEMM K (both GEMMs)

// ---------------------------------------------------------------------------
// Scratch (__device__ globals; no allocation allowed)
// Precision plan (measured-creep-calibrated):
//   x -> fp16 (1 term)            -> QKV GEMM 1-term -> qkv fp16
//   attention: Q/K/V/P all single fp16, fp32 accum; Q pre-scaled 0.125
//   y -> fp16 hi/lo (2 terms)     -> proj GEMM 2-term -> fp32 out
// ---------------------------------------------------------------------------
__device__ __align__(1024) __half  g_qkvh[(size_t)BT * C3];   // qkv fp16
__device__ __align__(1024) __half  g_xhi[(size_t)BT * CC];
__device__ __align__(1024) __half  g_yhi[(size_t)BT * CC];
__device__ __align__(1024) __half  g_ylo[(size_t)BT * CC];
__device__ __align__(1024) __half  g_Wah[(size_t)C3 * CC];    // W_attn^T [N,K]
__device__ __align__(1024) __half  g_Wph[(size_t)CC * CC];    // W_proj^T [N,K]

// ---------------------------------------------------------------------------
// PTX helpers — baseline PTX only (compute_103 has no tcgen05/TMA-tensor!)
// ---------------------------------------------------------------------------
__device__ __forceinline__ uint32_t smem_u32(const void* p) {
    uint32_t a;
    asm("{ .reg .u64 t; cvta.to.shared.u64 t, %1; cvt.u32.u64 %0, t; }" : "=r"(a) : "l"(p));
    return a;
}
__device__ __forceinline__ void cp16(uint32_t saddr, const void* g) {
    asm volatile("cp.async.cg.shared.global [%0], [%1], 16;\n" :: "r"(saddr), "l"(g));
}
__device__ __forceinline__ void cp_commit() {
    asm volatile("cp.async.commit_group;\n" ::: "memory");
}
template<int N> __device__ __forceinline__ void cp_wait() {
    asm volatile("cp.async.wait_group %0;\n" :: "n"(N) : "memory");
}
__device__ __forceinline__ void ldsm_x4(uint32_t* r, uint32_t addr) {
    asm volatile("ldmatrix.sync.aligned.m8n8.x4.shared.b16 {%0,%1,%2,%3}, [%4];"
        : "=r"(r[0]), "=r"(r[1]), "=r"(r[2]), "=r"(r[3]) : "r"(addr));
}
__device__ __forceinline__ void ldsm_x4_t(uint32_t* r, uint32_t addr) {
    asm volatile("ldmatrix.sync.aligned.m8n8.x4.trans.shared.b16 {%0,%1,%2,%3}, [%4];"
        : "=r"(r[0]), "=r"(r[1]), "=r"(r[2]), "=r"(r[3]) : "r"(addr));
}
__device__ __forceinline__ void mma16816(float* d, const uint32_t* a, const uint32_t* b) {
    asm volatile("mma.sync.aligned.m16n8k16.row.col.f32.f16.f16.f32 "
        "{%0,%1,%2,%3}, {%4,%5,%6,%7}, {%8,%9}, {%0,%1,%2,%3};"
        : "+f"(d[0]), "+f"(d[1]), "+f"(d[2]), "+f"(d[3])
        : "r"(a[0]), "r"(a[1]), "r"(a[2]), "r"(a[3]), "r"(b[0]), "r"(b[1]));
}
// swizzled address inside a [rows][128B] tile (SW128: 16B chunks permuted)
__device__ __forceinline__ uint32_t sw_addr(uint32_t base, int row, int kb) {
    uint32_t off = ((uint32_t)row << 7) + (uint32_t)kb;
    return base + (off ^ ((off >> 3) & 0x70));
}
__device__ __forceinline__ uint32_t pack_f16(float a, float b) {
    __half2 h = __floats2half2_rn(a, b);
    return *(uint32_t*)&h;
}

// ---------------------------------------------------------------------------
// Convert fp32 -> fp16 (x; single term)
// ---------------------------------------------------------------------------
__global__ void convert_h_kernel(const float* __restrict__ src,
                                 __half* __restrict__ dst, int n4) {
    int i = blockIdx.x * blockDim.x + threadIdx.x;
    if (i >= n4) return;
    float4 v = ((const float4*)src)[i];
    ((__half2*)dst)[2*i]   = __floats2half2_rn(v.x, v.y);
    ((__half2*)dst)[2*i+1] = __floats2half2_rn(v.z, v.w);
}

// Transpose W[K,N] -> Wt[N,K], fp16
__global__ void transpose_h_kernel(const float* __restrict__ W,
                                   __half* __restrict__ Th, int K, int N) {
    __shared__ float t[32][33];
    int tx = threadIdx.x, ty = threadIdx.y;
    int n0 = blockIdx.x * 32, k0 = blockIdx.y * 32;
    #pragma unroll
    for (int j = 0; j < 4; j++)
        t[ty + 8*j][tx] = W[(size_t)(k0 + ty + 8*j) * N + n0 + tx];
    __syncthreads();
    #pragma unroll
    for (int j = 0; j < 4; j++)
        Th[(size_t)(n0 + ty + 8*j) * K + k0 + tx] = __float2half_rn(t[tx][ty + 8*j]);
}

// ---------------------------------------------------------------------------
// mma.sync fp16 GEMM: C = (Ahi[+Alo])·Bh^T + bias  [cols<scale_below: *0.125]
// CTA 128x256, BK=64 (128B rows, SW128), 16 warps (4m x 4n, 32x64 each).
// 3-stage cp.async ring, ONE __syncthreads per chunk. 512 threads.
// TWO_TERM=false: QKV (fp16 out). TWO_TERM=true: proj (fp32 out).
// ---------------------------------------------------------------------------
#define GT_M   128
#define GT_N   256
#define GT_K   64
#define NKCH   (KK / GT_K)                // 16
#define TILE_A (128 * 128)                // 16384 B
#define TILE_BB (256 * 128)               // 32768 B
#define OFF_AH 0
#define OFF_AL (TILE_A)
#define OFF_BH (2 * TILE_A)
#define STAGE  (2 * TILE_A + TILE_BB)     // 65536
#define GEMM_SMEM (3 * STAGE)             // 196608

// gmem pitch 2048 B (K=1024 fp16), 512 threads
__device__ __forceinline__ void load_tileA(uint32_t sdst, const char* g,
                                           int kbytes, int tid) {
    #pragma unroll
    for (int it = 0; it < 2; it++) {
        int c = tid + it * 512;           // 1024 chunks of 16B
        int r = c >> 3;
        int cb = (c & 7) << 4;
        uint32_t off = ((uint32_t)r << 7) | (uint32_t)cb;
        cp16(sdst + (off ^ ((off >> 3) & 0x70)), g + (size_t)r * 2048 + kbytes + cb);
    }
}
__device__ __forceinline__ void load_tileB(uint32_t sdst, const char* g,
                                           int kbytes, int tid) {
    #pragma unroll
    for (int it = 0; it < 4; it++) {
        int c = tid + it * 512;           // 2048 chunks of 16B
        int r = c >> 3;
        int cb = (c & 7) << 4;
        uint32_t off = ((uint32_t)r << 7) | (uint32_t)cb;
        cp16(sdst + (off ^ ((off >> 3) & 0x70)), g + (size_t)r * 2048 + kbytes + cb);
    }
}

template<bool TWO_TERM>
__global__ __launch_bounds__(512)
void hmma_gemm_kernel(const __half* __restrict__ Ahi,
                      const __half* __restrict__ Alo,
                      const __half* __restrict__ Bh,
                      const float* __restrict__ bias,
                      float* __restrict__ C,
                      __half* __restrict__ Ch,
                      int N, int scale_below) {
    extern __shared__ char smem[];
    const uint32_t sbase = smem_u32(smem);
    const int tid  = threadIdx.x;
    const int lane = tid & 31;
    const int wid  = tid >> 5;            // 0..15
    const int wm   = wid >> 2;            // 0..3 -> 32 rows
    const int wn   = wid & 3;             // 0..3 -> 64 cols
    const int bx   = blockIdx.x;
    const int by   = blockIdx.y;

    const char* gAh = (const char*)Ahi + (size_t)by * GT_M * 2048;
    const char* gAl = (const char*)Alo + (size_t)by * GT_M * 2048;
    const char* gBh = (const char*)Bh  + (size_t)bx * GT_N * 2048;

    // prologue: chunks 0,1 -> stages 0,1
    #pragma unroll
    for (int st = 0; st < 2; st++) {
        uint32_t sb = sbase + st * STAGE;
        int kb = st * 128;
        load_tileA(sb + OFF_AH, gAh, kb, tid);
        if (TWO_TERM) load_tileA(sb + OFF_AL, gAl, kb, tid);
        load_tileB(sb + OFF_BH, gBh, kb, tid);
        cp_commit();
    }

    float acc[2][8][4];
    #pragma unroll
    for (int mt = 0; mt < 2; mt++)
        #pragma unroll
        for (int nt = 0; nt < 8; nt++)
            #pragma unroll
            for (int r = 0; r < 4; r++) acc[mt][nt][r] = 0.f;

    const int arow = wm * 32 + (lane & 15);
    const int akb  = (lane >> 4) << 4;
    const int brow = wn * 64 + (lane & 7) + ((lane >> 4) << 3);
    const int bkb  = ((lane >> 3) & 1) << 4;

    for (int i = 0; i < NKCH; i++) {
        const uint32_t sb = sbase + (uint32_t)(i % 3) * STAGE;

        if (i + 1 < NKCH) cp_wait<1>(); else cp_wait<0>();
        __syncthreads();

        // refill stage (i+2)%3 == (i-1)%3 BEFORE compute
        if (i + 2 < NKCH) {
            uint32_t sb2 = sbase + (uint32_t)((i + 2) % 3) * STAGE;
            int kb = (i + 2) * 128;
            load_tileA(sb2 + OFF_AH, gAh, kb, tid);
            if (TWO_TERM) load_tileA(sb2 + OFF_AL, gAl, kb, tid);
            load_tileB(sb2 + OFF_BH, gBh, kb, tid);
            cp_commit();
        }

        #pragma unroll
        for (int ks = 0; ks < 4; ks++) {
            const int ksb = ks * 32;
            uint32_t ah[2][4], al[2][4], bh[4][4];
            #pragma unroll
            for (int mt = 0; mt < 2; mt++)
                ldsm_x4(ah[mt], sw_addr(sb + OFF_AH, arow + mt * 16, ksb + akb));
            if (TWO_TERM)
                #pragma unroll
                for (int mt = 0; mt < 2; mt++)
                    ldsm_x4(al[mt], sw_addr(sb + OFF_AL, arow + mt * 16, ksb + akb));
            #pragma unroll
            for (int p = 0; p < 4; p++)
                ldsm_x4(bh[p], sw_addr(sb + OFF_BH, brow + p * 16, ksb + bkb));
            #pragma unroll
            for (int mt = 0; mt < 2; mt++)
                #pragma unroll
                for (int nt = 0; nt < 8; nt++)
                    mma16816(acc[mt][nt], ah[mt], &bh[nt >> 1][(nt & 1) * 2]);
            if (TWO_TERM)
                #pragma unroll
                for (int mt = 0; mt < 2; mt++)
                    #pragma unroll
                    for (int nt = 0; nt < 8; nt++)
                        mma16816(acc[mt][nt], al[mt], &bh[nt >> 1][(nt & 1) * 2]);
        }
    }

    // Epilogue
    const int g = lane >> 2, t = lane & 3;
    const int row_base = by * GT_M + wm * 32 + g;
    const int col_base = bx * GT_N + wn * 64 + t * 2;
    const float sc = (col_base < scale_below) ? 0.125f : 1.0f;   // uniform per warp
    #pragma unroll
    for (int mt = 0; mt < 2; mt++) {
        const int r0 = row_base + mt * 16;
        #pragma unroll
        for (int nt = 0; nt < 8; nt++) {
            const int c = col_base + nt * 8;
            float b0 = bias[c], b1 = bias[c + 1];
            float v0 = (acc[mt][nt][0] + b0) * sc, v1 = (acc[mt][nt][1] + b1) * sc;
            float v2 = (acc[mt][nt][2] + b0) * sc, v3 = (acc[mt][nt][3] + b1) * sc;
            if (TWO_TERM) {
                *(float2*)(C + (size_t)r0 * N + c)       = make_float2(v0, v1);
                *(float2*)(C + (size_t)(r0 + 8) * N + c) = make_float2(v2, v3);
            } else {
                *(__half2*)(Ch + (size_t)r0 * N + c)       = __floats2half2_rn(v0, v1);
                *(__half2*)(Ch + (size_t)(r0 + 8) * N + c) = __floats2half2_rn(v2, v3);
            }
        }
    }
}

// ---------------------------------------------------------------------------
// mma.sync flash attention (causal). Q/K/V/P single fp16 (Q pre-scaled
// 0.125), fp32 accumulators. CTA: 128 q rows (8 warps x 16), BK=64,
// 3-stage KV ring, ONE __syncthreads per chunk. Writes y hi/lo fp16.
// ---------------------------------------------------------------------------
#define AT_BQ 128
#define AT_BK 64
#define A_QH  0
#define A_KV0 16384
#define KV_KH 0
#define KV_VH 8192
#define KV_STAGE 16384
#define ATTN_SMEM (A_KV0 + 3 * KV_STAGE)   // 65536

// rows=64 tile load, gmem pitch 6144 B (C3 fp16)
__device__ __forceinline__ void load_rows64(uint32_t sdst, const char* g, int tid) {
    #pragma unroll
    for (int it = 0; it < 2; it++) {
        int c = tid + it * 256;
        int r = c >> 3;
        int cb = (c & 7) << 4;
        uint32_t off = ((uint32_t)r << 7) | (uint32_t)cb;
        cp16(sdst + (off ^ ((off >> 3) & 0x70)), g + (size_t)r * 6144 + cb);
    }
}
__device__ __forceinline__ void load_rows128(uint32_t sdst, const char* g, int tid) {
    #pragma unroll
    for (int it = 0; it < 4; it++) {
        int c = tid + it * 256;
        int r = c >> 3;
        int cb = (c & 7) << 4;
        uint32_t off = ((uint32_t)r << 7) | (uint32_t)cb;
        cp16(sdst + (off ^ ((off >> 3) & 0x70)), g + (size_t)r * 6144 + cb);
    }
}
__device__ __forceinline__ void load_kv_chunk(uint32_t sb, const __half* qh,
                                              int b, int h, int chunk, int tid) {
    const char* gK = (const char*)(qh + (size_t)(b * TT + chunk * AT_BK) * C3 + CC + h * DD);
    load_rows64(sb + KV_KH, gK, tid);
    load_rows64(sb + KV_VH, gK + 2048, tid);     // V = +CC fp16 = +2048 B
    cp_commit();
}

__global__ __launch_bounds__(256)
void attn_mma_kernel(const __half* __restrict__ qh,
                     __half* __restrict__ yh,
                     __half* __restrict__ yl)
{
    extern __shared__ char smem[];
    const uint32_t sbase = smem_u32(smem);
    const int tid  = threadIdx.x;
    const int lane = tid & 31;
    const int w    = tid >> 5;            // warp 0..7, owns q rows w*16..+15
    const int qt = blockIdx.x, h = blockIdx.y, b = blockIdx.z;
    const int q0 = qt * AT_BQ;
    const int n  = 2 * qt + 2;            // kv chunks (n >= 2)

    const char* gQh = (const char*)(qh + (size_t)(b * TT + q0) * C3 + h * DD);

    // prologue: Q (group 0), KV0 (group 1), KV1 (group 2)
    load_rows128(sbase + A_QH, gQh, tid);
    cp_commit();
    load_kv_chunk(sbase + A_KV0, qh, b, h, 0, tid);
    load_kv_chunk(sbase + A_KV0 + KV_STAGE, qh, b, h, 1, tid);

    cp_wait<2>();
    __syncthreads();

    // Q fragments (loop-invariant): 4 ksteps x 4 regs
    const int arow = w * 16 + (lane & 15);
    const int akb  = (lane >> 4) << 4;
    uint32_t qfh[4][4];
    #pragma unroll
    for (int ks = 0; ks < 4; ks++)
        ldsm_x4(qfh[ks], sw_addr(sbase + A_QH, arow, ks * 32 + akb));

    float oacc[8][4];
    #pragma unroll
    for (int nt = 0; nt < 8; nt++)
        #pragma unroll
        for (int r = 0; r < 4; r++) oacc[nt][r] = 0.f;
    float m0 = -1e30f, m1 = -1e30f, l0 = 0.f, l1 = 0.f;

    const int g_ = lane >> 2, t_ = lane & 3;
    const int brow = (lane & 7) + ((lane >> 4) << 3);
    const int bkb  = ((lane >> 3) & 1) << 4;
    const int vrow = ((lane >> 3) & 1) * 8 + (lane & 7);
    const int vcb  = (lane >> 4) << 4;

    for (int c = 0; c < n; c++) {
        if (c + 1 < n) cp_wait<1>(); else cp_wait<0>();
        __syncthreads();

        if (c + 2 < n)
            load_kv_chunk(sbase + A_KV0 + (uint32_t)((c + 2) % 3) * KV_STAGE,
                          qh, b, h, c + 2, tid);

        const uint32_t sb = sbase + A_KV0 + (uint32_t)(c % 3) * KV_STAGE;
        const int kv0 = c * AT_BK;
        const bool active = (kv0 <= q0 + w * 16 + 15);
        const bool need_mask = (kv0 + 63 > q0 + w * 16);

        if (active) {
            // ---- S = Q K^T (1-term fp16; Q pre-scaled by 0.125) ----
            float sacc[8][4];
            #pragma unroll
            for (int nt = 0; nt < 8; nt++)
                #pragma unroll
                for (int r = 0; r < 4; r++) sacc[nt][r] = 0.f;

            #pragma unroll
            for (int ks = 0; ks < 4; ks++) {
                const int ksb = ks * 32;
                uint32_t kh4[4][4];
                #pragma unroll
                for (int p = 0; p < 4; p++)
                    ldsm_x4(kh4[p], sw_addr(sb + KV_KH, p * 16 + brow, ksb + bkb));
                #pragma unroll
                for (int p = 0; p < 4; p++) {
                    mma16816(sacc[2*p],   qfh[ks], &kh4[p][0]);
                    mma16816(sacc[2*p+1], qfh[ks], &kh4[p][2]);
                }
            }

            // causal mask (scale folded into Q)
            const int row0 = q0 + w * 16 + g_;
            if (need_mask) {
                #pragma unroll
                for (int nt = 0; nt < 8; nt++) {
                    int col = kv0 + nt * 8 + 2 * t_;
                    if (col     > row0)     sacc[nt][0] = -1e30f;
                    if (col + 1 > row0)     sacc[nt][1] = -1e30f;
                    if (col     > row0 + 8) sacc[nt][2] = -1e30f;
                    if (col + 1 > row0 + 8) sacc[nt][3] = -1e30f;
                }
            }

            // ---- online softmax (rows g_, g_+8) ----
            float mx0 = -1e30f, mx1 = -1e30f;
            #pragma unroll
            for (int nt = 0; nt < 8; nt++) {
                mx0 = fmaxf(mx0, fmaxf(sacc[nt][0], sacc[nt][1]));
                mx1 = fmaxf(mx1, fmaxf(sacc[nt][2], sacc[nt][3]));
            }
            mx0 = fmaxf(mx0, __shfl_xor_sync(0xffffffffu, mx0, 1));
            mx0 = fmaxf(mx0, __shfl_xor_sync(0xffffffffu, mx0, 2));
            mx1 = fmaxf(mx1, __shfl_xor_sync(0xffffffffu, mx1, 1));
            mx1 = fmaxf(mx1, __shfl_xor_sync(0xffffffffu, mx1, 2));
            mx0 = fmaxf(mx0, m0);
            mx1 = fmaxf(mx1, m1);

            float rs0 = 0.f, rs1 = 0.f;
            #pragma unroll
            for (int nt = 0; nt < 8; nt++) {
                sacc[nt][0] = __expf(sacc[nt][0] - mx0);
                sacc[nt][1] = __expf(sacc[nt][1] - mx0);
                sacc[nt][2] = __expf(sacc[nt][2] - mx1);
                sacc[nt][3] = __expf(sacc[nt][3] - mx1);
                rs0 += sacc[nt][0] + sacc[nt][1];
                rs1 += sacc[nt][2] + sacc[nt][3];
            }
            rs0 += __shfl_xor_sync(0xffffffffu, rs0, 1);
            rs0 += __shfl_xor_sync(0xffffffffu, rs0, 2);
            rs1 += __shfl_xor_sync(0xffffffffu, rs1, 1);
            rs1 += __shfl_xor_sync(0xffffffffu, rs1, 2);

            float a0 = __expf(m0 - mx0);
            float a1 = __expf(m1 - mx1);
            m0 = mx0; m1 = mx1;
            l0 = l0 * a0 + rs0;
            l1 = l1 * a1 + rs1;
            #pragma unroll
            for (int nt = 0; nt < 8; nt++) {
                oacc[nt][0] *= a0; oacc[nt][1] *= a0;
                oacc[nt][2] *= a1; oacc[nt][3] *= a1;
            }

            // ---- pack P single fp16 ----
            uint32_t ph[8][2];
            #pragma unroll
            for (int nt = 0; nt < 8; nt++) {
                ph[nt][0] = pack_f16(sacc[nt][0], sacc[nt][1]);
                ph[nt][1] = pack_f16(sacc[nt][2], sacc[nt][3]);
            }

            // ---- O += P V (1-term), V via ldmatrix.trans ----
            #pragma unroll
            for (int kk = 0; kk < 4; kk++) {
                uint32_t aPh[4] = {ph[2*kk][0], ph[2*kk][1], ph[2*kk+1][0], ph[2*kk+1][1]};
                uint32_t vh4[4][4];
                #pragma unroll
                for (int dd = 0; dd < 4; dd++)
                    ldsm_x4_t(vh4[dd], sw_addr(sb + KV_VH, kk * 16 + vrow, dd * 32 + vcb));
                #pragma unroll
                for (int dd = 0; dd < 4; dd++) {
                    mma16816(oacc[2*dd],   aPh, &vh4[dd][0]);
                    mma16816(oacc[2*dd+1], aPh, &vh4[dd][2]);
                }
            }
        }
    }

    // ---- epilogue: normalize, split hi/lo, store y ----
    const float inv0 = 1.f / l0, inv1 = 1.f / l1;
    const size_t row0 = (size_t)(b * TT + q0 + w * 16 + g_);
    const int col0 = h * DD + 2 * t_;
    #pragma unroll
    for (int nt = 0; nt < 8; nt++) {
        float v0 = oacc[nt][0] * inv0, v1 = oacc[nt][1] * inv0;
        float v2 = oacc[nt][2] * inv1, v3 = oacc[nt][3] * inv1;
        __half h0 = __float2half_rn(v0), h1 = __float2half_rn(v1);
        __half h2 = __float2half_rn(v2), h3 = __float2half_rn(v3);
        size_t i0 = row0 * CC + col0 + nt * 8;
        size_t i1 = (row0 + 8) * CC + col0 + nt * 8;
        *(__half2*)(yh + i0) = __half2(h0, h1);
        *(__half2*)(yh + i1) = __half2(h2, h3);
        *(__half2*)(yl + i0) = __half2(__float2half_rn(v0 - __half2float(h0)),
                                       __float2half_rn(v1 - __half2float(h1)));
        *(__half2*)(yl + i1) = __half2(__float2half_rn(v2 - __half2float(h2)),
                                       __float2half_rn(v3 - __half2float(h3)));
    }
}

// ---------------------------------------------------------------------------
extern "C" void kernel_launch(void* const* d_in, const int* in_sizes, int n_in,
                              void* d_out, int out_size)
{
    const float* x      = (const float*)d_in[0];
    const float* W_attn = (const float*)d_in[1];
    const float* b_attn = (const float*)d_in[2];
    const float* W_proj = (const float*)d_in[3];
    const float* b_proj = (const float*)d_in[4];
    float* out = (float*)d_out;

    __half *qkvh, *xhi, *yhi, *ylo, *wah, *wph;
    cudaGetSymbolAddress((void**)&qkvh, g_qkvh);
    cudaGetSymbolAddress((void**)&xhi,  g_xhi);
    cudaGetSymbolAddress((void**)&yhi,  g_yhi);
    cudaGetSymbolAddress((void**)&ylo,  g_ylo);
    cudaGetSymbolAddress((void**)&wah,  g_Wah);
    cudaGetSymbolAddress((void**)&wph,  g_Wph);

    static bool attr_done = false;
    if (!attr_done) {
        cudaFuncSetAttribute(hmma_gemm_kernel<false>,
                             cudaFuncAttributeMaxDynamicSharedMemorySize, GEMM_SMEM);
        cudaFuncSetAttribute(hmma_gemm_kernel<true>,
                             cudaFuncAttributeMaxDynamicSharedMemorySize, GEMM_SMEM);
        cudaFuncSetAttribute(attn_mma_kernel,
                             cudaFuncAttributeMaxDynamicSharedMemorySize, ATTN_SMEM);
        attr_done = true;
    }

    // 1) convert x -> fp16
    {
        int n4 = BT * CC / 4;
        convert_h_kernel<<<(n4 + 255) / 256, 256>>>(x, xhi, n4);
    }
    // 2) transpose weights (fp16)
    transpose_h_kernel<<<dim3(C3 / 32, CC / 32), dim3(32, 8)>>>(W_attn, wah, CC, C3);
    transpose_h_kernel<<<dim3(CC / 32, CC / 32), dim3(32, 8)>>>(W_proj, wph, CC, CC);

    // 3) QKV GEMM (1-term) -> qkv fp16; Q cols pre-scaled by 0.125
    hmma_gemm_kernel<false><<<dim3(C3 / GT_N, BT / GT_M), 512, GEMM_SMEM>>>(
        xhi, nullptr, wah, b_attn, nullptr, qkvh, C3, /*scale_below=*/CC);

    // 4) tensor-core flash attention -> y hi/lo fp16
    attn_mma_kernel<<<dim3(TT / AT_BQ, HH, BB), 256, ATTN_SMEM>>>(qkvh, yhi, ylo);

    // 5) proj GEMM (2-term) -> out fp32
    hmma_gemm_kernel<true><<<dim3(CC / GT_N, BT / GT_M), 512, GEMM_SMEM>>>(
        yhi, ylo, wph, b_proj, out, nullptr, CC, /*scale_below=*/0);
}